// round 8
// baseline (speedup 1.0000x reference)
#include <cuda_runtime.h>
#include <cuda_bf16.h>
#include <math.h>
#include <stdint.h>

// Problem constants
#define BB 2
#define HH 256
#define WW 256
#define NN 65536          // H*W
#define CC 128
#define HEADS 8
#define DH 64             // dim_head
#define GG 64             // SLICE
#define INNER 512         // HEADS*DH
#define SPLITS 64         // split-K for token reduction
#define CHUNK 1024        // tokens per split (NN/SPLITS)
#define KTOT 1152         // 9 taps * 128 channels

// ---------------- device scratch (static, no allocs) ----------------
__device__ float g_fx[(size_t)BB * NN * INNER];      // fx_mid  [b][n][inner]
__device__ float g_tokp[(size_t)SPLITS * BB * HEADS * GG * DH];
__device__ float g_normp[(size_t)SPLITS * BB * HEADS * GG];
__device__ float g_tok [(size_t)BB * HEADS * GG * DH];
__device__ float g_norm[(size_t)BB * HEADS * GG];
__device__ float g_lbias[INNER];                     // (bx·Wslice + bslice)/temp

// slice weights as bf16 hi/lo pair  [bh][n][g]
__device__ __align__(16) __nv_bfloat16 g_swhi[(size_t)BB * HEADS * NN * GG];
__device__ __align__(16) __nv_bfloat16 g_swlo[(size_t)BB * HEADS * NN * GG];
// Mt = (out_slice · Wout^T) transposed: [b][o][h*64+g], bf16 hi/lo
__device__ __align__(16) __nv_bfloat16 g_Mthi[(size_t)BB * CC * INNER];
__device__ __align__(16) __nv_bfloat16 g_Mtlo[(size_t)BB * CC * INNER];

// bf16 3-split staging for conv
__device__ __align__(16) __nv_bfloat16 g_xhi[(size_t)BB * NN * CC];
__device__ __align__(16) __nv_bfloat16 g_xlo[(size_t)BB * NN * CC];
// rows 0..511: Wfx cols; rows 512..1023: combined logit weights (Wx·Wslice/temp)
__device__ __align__(16) __nv_bfloat16 g_whi[(size_t)1024 * KTOT];
__device__ __align__(16) __nv_bfloat16 g_wlo[(size_t)1024 * KTOT];

// ---------------- prep kernels ----------------
__global__ void split_x_kernel(const float* __restrict__ x,
                               __nv_bfloat16* __restrict__ xhi,
                               __nv_bfloat16* __restrict__ xlo) {
    size_t i = (size_t)blockIdx.x * 256 + threadIdx.x;
    float f = x[i];
    __nv_bfloat16 h = __float2bfloat16(f);
    float r = f - __bfloat162float(h);
    xhi[i] = h;
    xlo[i] = __float2bfloat16(r);
}

// Wfx (fx conv weights) -> rows 0..511 of g_whi/g_wlo, transposed [oc][k]
__global__ void split_w_kernel(const float* __restrict__ Wfx,
                               __nv_bfloat16* __restrict__ whi,
                               __nv_bfloat16* __restrict__ wlo) {
    int i = blockIdx.x * 256 + threadIdx.x;   // 512*1152 total
    int oc = i / KTOT;
    int k  = i - oc * KTOT;
    float f = Wfx[(size_t)k * 512 + oc];
    __nv_bfloat16 h = __float2bfloat16(f);
    float r = f - __bfloat162float(h);
    whi[i] = h;
    wlo[i] = __float2bfloat16(r);
}

// W~[k][h*64+g] = (sum_d Wx[k][h*64+d]*Wslice[g][d]) / temp_h -> rows 512..1023
__global__ void combine_w_kernel(const float* __restrict__ Wx,
                                 const float* __restrict__ Wsl,
                                 const float* __restrict__ temp,
                                 __nv_bfloat16* __restrict__ whi,
                                 __nv_bfloat16* __restrict__ wlo) {
    __shared__ float ws[64];
    const int col = blockIdx.x;          // 0..511
    const int h = col >> 6, g = col & 63;
    const int tid = threadIdx.x;         // 128
    if (tid < 64) ws[tid] = Wsl[g * 64 + tid];
    __syncthreads();
    float t = fminf(fmaxf(temp[h], 0.1f), 5.0f);
    float invt = 1.0f / t;
    int k = blockIdx.y * 128 + tid;      // 9 y-blocks -> 0..1151
    const float* wr = Wx + (size_t)k * 512 + h * 64;
    float s = 0.f;
    #pragma unroll 8
    for (int d = 0; d < 64; d++) s += wr[d] * ws[d];
    s *= invt;
    __nv_bfloat16 hv = __float2bfloat16(s);
    size_t o = (size_t)(512 + col) * KTOT + k;
    whi[o] = hv;
    wlo[o] = __float2bfloat16(s - __bfloat162float(hv));
}

// lbias[h*64+g] = (bx_h · Wslice_g + bslice_g) / temp_h   (one block per col)
__global__ void lbias_kernel(const float* __restrict__ bx,
                             const float* __restrict__ Wsl,
                             const float* __restrict__ bsl,
                             const float* __restrict__ temp,
                             float* __restrict__ lb) {
    int col = blockIdx.x;                // 0..511
    int h = col >> 6, g = col & 63;
    int lane = threadIdx.x;              // 32
    float s = bx[h * 64 + lane] * Wsl[g * 64 + lane]
            + bx[h * 64 + 32 + lane] * Wsl[g * 64 + 32 + lane];
    #pragma unroll
    for (int o = 16; o > 0; o >>= 1)
        s += __shfl_xor_sync(0xffffffffu, s, o);
    if (lane == 0) {
        float t = fminf(fmaxf(temp[h], 0.1f), 5.0f);
        lb[col] = (s + bsl[g]) / t;
    }
}

// ---------------- shared MMA plumbing ----------------
__device__ __forceinline__ void cp16(uint32_t saddr, const void* g, bool valid) {
    int sz = valid ? 16 : 0;
    asm volatile("cp.async.cg.shared.global [%0], [%1], 16, %2;\n"
                 :: "r"(saddr), "l"(g), "r"(sz));
}

// 16-word rows (final kernel, kc=32 layout)
__device__ __forceinline__ uint32_t lds_frag(const uint32_t* base, int row, int kw) {
    return base[row * 16 + ((((kw >> 2) ^ (row & 3)) << 2) | (kw & 3))];
}

__device__ __forceinline__ void mma_bf16(float c[4], uint32_t a0, uint32_t a1,
                                         uint32_t a2, uint32_t a3,
                                         uint32_t b0, uint32_t b1) {
    asm volatile(
        "mma.sync.aligned.m16n8k16.row.col.f32.bf16.bf16.f32 "
        "{%0,%1,%2,%3}, {%4,%5,%6,%7}, {%8,%9}, {%0,%1,%2,%3};"
        : "+f"(c[0]), "+f"(c[1]), "+f"(c[2]), "+f"(c[3])
        : "r"(a0), "r"(a1), "r"(a2), "r"(a3), "r"(b0), "r"(b1));
}

__device__ __forceinline__ void ldsm4(uint32_t r[4], uint32_t addr) {
    asm volatile("ldmatrix.sync.aligned.m8n8.x4.shared.b16 {%0,%1,%2,%3}, [%4];"
                 : "=r"(r[0]), "=r"(r[1]), "=r"(r[2]), "=r"(r[3]) : "r"(addr));
}

// ---------------- conv: implicit GEMM 128x256, kc=64, ldmatrix, 512 threads ----------------
// ocb 0..1: fx output (cols ocb*256..+255); ocb 2..3: slice-weight softmax (4 heads each).
// Stage (96KB): Ahi 16K | Alo 16K | Bhi 32K | Blo 32K.
// Rows are 128B (64 bf16), granule-swizzled: off = row*128 + ((gr ^ (row&7))<<4).
// 16 warps (4/SMSP): warp tile 32 rows x 64 cols.
#define CSTAGE 98304

__device__ __forceinline__ void conv_load(
    uint32_t st,
    const __nv_bfloat16* __restrict__ Xhi, const __nv_bfloat16* __restrict__ Xlo,
    const __nv_bfloat16* __restrict__ Whi, const __nv_bfloat16* __restrict__ Wlo,
    int it, int b, int hrow, int w0, int ocb, int tid)
{
    const int kg  = it * 64;
    const int tap = kg >> 7;
    const int dy = tap / 3 - 1, dx = tap % 3 - 1;
    const int c0 = kg & 127;            // 0 or 64
    const int hp = hrow + dy;
    const bool hok = (hp >= 0) && (hp < HH);
    const int hpc = hok ? hp : 0;

    // A: 2 arrays x 128 rows x 8 granules = 2048 lines (4 per thread)
    #pragma unroll
    for (int j = 0; j < 4; j++) {
        int id  = tid + j * 512;
        int arr = id >> 10;             // 0:Ahi 1:Alo
        int l   = id & 1023;
        int row = l >> 3;
        int gr  = l & 7;
        uint32_t saddr = st + arr * 16384 + row * 128 + ((gr ^ (row & 7)) << 4);
        int wp = w0 + row + dx;
        bool valid = hok && (wp >= 0) && (wp < WW);
        int wpc = valid ? wp : 0;
        const __nv_bfloat16* g = (arr == 0 ? Xhi : Xlo) +
            (((size_t)b * NN + (size_t)hpc * WW + wpc) * CC + c0 + gr * 8);
        cp16(saddr, g, valid);
    }
    // B: 2 arrays x 256 rows x 8 granules = 4096 lines (8 per thread)
    #pragma unroll
    for (int j = 0; j < 8; j++) {
        int id  = tid + j * 512;        // 0..4095
        int arr = id >> 11;             // 0:Bhi 1:Blo
        int l   = id & 2047;
        int row = l >> 3;
        int gr  = l & 7;
        uint32_t saddr = st + 32768 + arr * 32768 + row * 128 + ((gr ^ (row & 7)) << 4);
        const __nv_bfloat16* g = (arr == 0 ? Whi : Wlo) +
            ((size_t)(ocb * 256 + row) * KTOT + kg + gr * 8);
        cp16(saddr, g, true);
    }
}

__global__ __launch_bounds__(512, 1)
void conv_mma_kernel(const __nv_bfloat16* __restrict__ Xhi,
                     const __nv_bfloat16* __restrict__ Xlo,
                     const __nv_bfloat16* __restrict__ Whi,
                     const __nv_bfloat16* __restrict__ Wlo,
                     const float* __restrict__ bfx,
                     const float* __restrict__ lbias,
                     float* __restrict__ ofx,
                     __nv_bfloat16* __restrict__ swhi,
                     __nv_bfloat16* __restrict__ swlo)
{
    extern __shared__ char smem[];           // 2 stages x 96KB

    const int ocb = blockIdx.x;              // 0..3
    const int pt  = blockIdx.y;              // 0..511
    const int b   = blockIdx.z;
    const int n0  = pt * 128;
    const int hrow = n0 >> 8;
    const int w0   = n0 & 255;

    const int tid  = threadIdx.x;
    const int wid  = tid >> 5;               // 0..15
    const int lane = tid & 31;
    const int grp  = lane >> 2;
    const int tid4 = lane & 3;
    const int wm   = wid & 3;                // 4 row-groups of 32
    const int wn   = wid >> 2;               // 4 col-groups of 64

    // ldmatrix lane addressing precompute
    const int t8   = lane >> 3;              // tile index 0..3
    const int r8   = lane & 7;               // row within tile
    const int a_roff = ((t8 & 1) << 3) + r8; // A: +0/+8 rows, granule pair t8>>1
    const int a_gsel = t8 >> 1;
    const int b_roff = ((t8 >> 1) << 3) + r8;// B: +0/+8 rows, granule pair t8&1
    const int b_gsel = t8 & 1;

    float acc[2][8][4];
    #pragma unroll
    for (int i = 0; i < 2; i++)
        #pragma unroll
        for (int j = 0; j < 8; j++)
            #pragma unroll
            for (int r = 0; r < 4; r++) acc[i][j][r] = 0.f;

    uint32_t sbase = (uint32_t)__cvta_generic_to_shared(smem);

    conv_load(sbase, Xhi, Xlo, Whi, Wlo, 0, b, hrow, w0, ocb, tid);
    asm volatile("cp.async.commit_group;\n" ::: "memory");

    for (int it = 0; it < 18; ++it) {
        const int cur = it & 1;
        if (it + 1 < 18) {
            conv_load(sbase + (uint32_t)(1 - cur) * CSTAGE,
                      Xhi, Xlo, Whi, Wlo, it + 1, b, hrow, w0, ocb, tid);
            asm volatile("cp.async.commit_group;\n" ::: "memory");
            asm volatile("cp.async.wait_group 1;\n" ::: "memory");
        } else {
            asm volatile("cp.async.wait_group 0;\n" ::: "memory");
        }
        __syncthreads();

        const uint32_t stA = sbase + (uint32_t)cur * CSTAGE;
        const uint32_t stB = stA + 32768;

        #pragma unroll
        for (int s = 0; s < 4; s++) {
            // A fragments: 2 mi x (hi, lo)
            uint32_t ah[2][4], al[2][4];
            #pragma unroll
            for (int mi = 0; mi < 2; mi++) {
                int row = wm * 32 + mi * 16 + a_roff;
                int g = 2 * s + a_gsel;
                uint32_t addr = stA + row * 128 + ((g ^ (row & 7)) << 4);
                ldsm4(ah[mi], addr);
                ldsm4(al[mi], addr + 16384);
            }
            // B fragments per 16-col pair; term-major MMA order
            #pragma unroll
            for (int np = 0; np < 4; np++) {
                int row = wn * 64 + np * 16 + b_roff;
                int g = 2 * s + b_gsel;
                uint32_t addr = stB + row * 128 + ((g ^ (row & 7)) << 4);
                uint32_t bh[4], bl[4];
                ldsm4(bh, addr);
                ldsm4(bl, addr + 32768);
                #pragma unroll
                for (int mi = 0; mi < 2; mi++) {
                    mma_bf16(acc[mi][2 * np],     ah[mi][0], ah[mi][1], ah[mi][2], ah[mi][3], bh[0], bh[1]);
                    mma_bf16(acc[mi][2 * np + 1], ah[mi][0], ah[mi][1], ah[mi][2], ah[mi][3], bh[2], bh[3]);
                }
                #pragma unroll
                for (int mi = 0; mi < 2; mi++) {
                    mma_bf16(acc[mi][2 * np],     ah[mi][0], ah[mi][1], ah[mi][2], ah[mi][3], bl[0], bl[1]);
                    mma_bf16(acc[mi][2 * np + 1], ah[mi][0], ah[mi][1], ah[mi][2], ah[mi][3], bl[2], bl[3]);
                }
                #pragma unroll
                for (int mi = 0; mi < 2; mi++) {
                    mma_bf16(acc[mi][2 * np],     al[mi][0], al[mi][1], al[mi][2], al[mi][3], bh[0], bh[1]);
                    mma_bf16(acc[mi][2 * np + 1], al[mi][0], al[mi][1], al[mi][2], al[mi][3], bh[2], bh[3]);
                }
            }
        }
        __syncthreads();
    }

    if (ocb < 2) {
        // fx output: direct fp32 stores with bias
        const int ocbase = ocb * 256;
        #pragma unroll
        for (int mi = 0; mi < 2; mi++) {
            int row = wm * 32 + mi * 16 + grp;
            int n  = n0 + row;
            #pragma unroll
            for (int ni = 0; ni < 8; ni++) {
                int col = wn * 64 + ni * 8 + tid4 * 2;
                int oc  = ocbase + col;
                float b0v = bfx[oc], b1v = bfx[oc + 1];
                size_t base0 = ((size_t)b * NN + n) * INNER + oc;
                ofx[base0]     = acc[mi][ni][0] + b0v;
                ofx[base0 + 1] = acc[mi][ni][1] + b1v;
                size_t base1 = ((size_t)b * NN + n + 8) * INNER + oc;
                ofx[base1]     = acc[mi][ni][2] + b0v;
                ofx[base1 + 1] = acc[mi][ni][3] + b1v;
            }
        }
    } else {
        // logits: stage to smem, softmax per (pixel, head), emit bf16 hi/lo
        float* sred = (float*)smem;          // [128][260]
        #pragma unroll
        for (int mi = 0; mi < 2; mi++) {
            int row = wm * 32 + mi * 16 + grp;
            #pragma unroll
            for (int ni = 0; ni < 8; ni++) {
                int col = wn * 64 + ni * 8 + tid4 * 2;
                sred[row * 260 + col]           = acc[mi][ni][0];
                sred[row * 260 + col + 1]       = acc[mi][ni][1];
                sred[(row + 8) * 260 + col]     = acc[mi][ni][2];
                sred[(row + 8) * 260 + col + 1] = acc[mi][ni][3];
            }
        }
        __syncthreads();

        // 512 tasks = 512 threads: one (pixel,head) each
        int row  = tid >> 2;
        int hloc = tid & 3;
        int h = (ocb - 2) * 4 + hloc;
        int n = n0 + row;
        const float* lb = lbias + h * 64;
        float* sr = sred + row * 260 + hloc * 64;

        float mx = -1e30f;
        #pragma unroll 8
        for (int g = 0; g < 64; g++) mx = fmaxf(mx, sr[g] + lb[g]);
        float ssum = 0.f;
        #pragma unroll 8
        for (int g = 0; g < 64; g++) {
            float e = __expf(sr[g] + lb[g] - mx);
            ssum += e;
            sr[g] = e;
        }
        float inv = 1.0f / ssum;

        size_t base = ((size_t)(b * HEADS + h) * NN + n) * GG;
        #pragma unroll
        for (int c = 0; c < 8; c++) {
            union { __nv_bfloat16 hb[8]; uint4 u; } Uh, Ul;
            #pragma unroll
            for (int e = 0; e < 8; e++) {
                float v = sr[c * 8 + e] * inv;
                __nv_bfloat16 hv = __float2bfloat16(v);
                Uh.hb[e] = hv;
                Ul.hb[e] = __float2bfloat16(v - __bfloat162float(hv));
            }
            ((uint4*)(swhi + base))[c] = Uh.u;
            ((uint4*)(swlo + base))[c] = Ul.u;
        }
    }
}

// ---------------- K3: split-K reduction: slice_token partials ----------------
__global__ void token_reduce_kernel(const __nv_bfloat16* __restrict__ whi,
                                    const __nv_bfloat16* __restrict__ wlo,
                                    const float* __restrict__ fx,
                                    float* __restrict__ tokp,
                                    float* __restrict__ normp) {
    const int bh = blockIdx.y;
    const int b = bh >> 3, h = bh & 7;
    const int split = blockIdx.x;
    const int nbase = split * CHUNK;
    const int tx = threadIdx.x, ty = threadIdx.y;
    const int tid = ty * 16 + tx;

    __shared__ float wb[16][64];
    __shared__ float fb[16][64];

    float acc[4][4] = {};
    float nacc[4] = {};

    const int lt = tid >> 4;            // token row 0..15
    const int lq = (tid & 15) * 4;      // col group

    for (int t0 = 0; t0 < CHUNK; t0 += 16) {
        {
            int n = nbase + t0 + lt;
            size_t wi = ((size_t)bh * NN + n) * GG + lq;
            uint2 uh = *(const uint2*)(whi + wi);
            uint2 ul = *(const uint2*)(wlo + wi);
            const __nv_bfloat162* h2 = (const __nv_bfloat162*)&uh;
            const __nv_bfloat162* l2 = (const __nv_bfloat162*)&ul;
            float4 wv;
            wv.x = __bfloat162float(h2[0].x) + __bfloat162float(l2[0].x);
            wv.y = __bfloat162float(h2[0].y) + __bfloat162float(l2[0].y);
            wv.z = __bfloat162float(h2[1].x) + __bfloat162float(l2[1].x);
            wv.w = __bfloat162float(h2[1].y) + __bfloat162float(l2[1].y);
            *(float4*)&wb[lt][lq] = wv;
            *(float4*)&fb[lt][lq] =
                *(const float4*)(fx + ((size_t)b * NN + n) * INNER + h * DH + lq);
        }
        __syncthreads();
        #pragma unroll
        for (int t = 0; t < 16; t++) {
            float a[4], bv[4];
            #pragma unroll
            for (int i = 0; i < 4; i++) a[i] = wb[t][ty + 16 * i];
            #pragma unroll
            for (int j = 0; j < 4; j++) bv[j] = fb[t][tx + 16 * j];
            #pragma unroll
            for (int i = 0; i < 4; i++)
                #pragma unroll
                for (int j = 0; j < 4; j++)
                    acc[i][j] += a[i] * bv[j];
            if (tx == 0) {
                #pragma unroll
                for (int i = 0; i < 4; i++) nacc[i] += a[i];
            }
        }
        __syncthreads();
    }

    const size_t base = ((size_t)split * (BB * HEADS) + bh) * (GG * DH);
    #pragma unroll
    for (int i = 0; i < 4; i++)
        #pragma unroll
        for (int j = 0; j < 4; j++)
            tokp[base + (size_t)(ty + 16 * i) * DH + tx + 16 * j] = acc[i][j];
    if (tx == 0) {
        #pragma unroll
        for (int i = 0; i < 4; i++)
            normp[((size_t)split * (BB * HEADS) + bh) * GG + ty + 16 * i] = nacc[i];
    }
}

// ---------------- K3b: deterministic split reduction ----------------
__global__ void split_reduce_kernel(const float* __restrict__ tokp,
                                    const float* __restrict__ normp,
                                    float* __restrict__ tok,
                                    float* __restrict__ norm) {
    const int blk = blockIdx.x;
    const int tid = threadIdx.x;
    if (blk < 256) {
        int idx = blk * 256 + tid;
        float s = 0.f;
        #pragma unroll 8
        for (int sp = 0; sp < SPLITS; sp++)
            s += tokp[(size_t)sp * 65536 + idx];
        tok[idx] = s;
    } else {
        int idx = (blk - 256) * 256 + tid;
        float s = 0.f;
        #pragma unroll 8
        for (int sp = 0; sp < SPLITS; sp++)
            s += normp[(size_t)sp * 1024 + idx];
        norm[idx] = s;
    }
}

// ---------------- K4: tiny attention per (b,h), emits Mt bf16 hi/lo ----------------
__global__ void attn_kernel(const float* __restrict__ tok,
                            const float* __restrict__ norm,
                            const float* __restrict__ Wq,
                            const float* __restrict__ Wk,
                            const float* __restrict__ Wv,
                            const float* __restrict__ Wout,
                            __nv_bfloat16* __restrict__ Mthi,
                            __nv_bfloat16* __restrict__ Mtlo) {
    const int bh = blockIdx.x;
    const int b = bh >> 3, h = bh & 7;
    const int tx = threadIdx.x, ty = threadIdx.y;
    const int tid = ty * 16 + tx;

    __shared__ float A[64][65];
    __shared__ float Bm[64][65];
    __shared__ float Cm[64][65];

    #pragma unroll
    for (int e = 0; e < 16; e++) {
        int idx = tid + e * 256;
        int g = idx >> 6, d = idx & 63;
        A[g][d] = tok[(size_t)bh * 4096 + idx] / (norm[bh * 64 + g] + 1e-5f);
    }
    __syncthreads();

    {
        float aq[4][4] = {}, ak[4][4] = {};
        #pragma unroll
        for (int kk = 0; kk < 64; kk++) {
            float a[4];
            #pragma unroll
            for (int i = 0; i < 4; i++) a[i] = A[ty + 16 * i][kk];
            #pragma unroll
            for (int j = 0; j < 4; j++) {
                float wq = __ldg(&Wq[(tx + 16 * j) * 64 + kk]);
                float wk = __ldg(&Wk[(tx + 16 * j) * 64 + kk]);
                #pragma unroll
                for (int i = 0; i < 4; i++) {
                    aq[i][j] += a[i] * wq;
                    ak[i][j] += a[i] * wk;
                }
            }
        }
        #pragma unroll
        for (int i = 0; i < 4; i++)
            #pragma unroll
            for (int j = 0; j < 4; j++) {
                Bm[ty + 16 * i][tx + 16 * j] = aq[i][j];
                Cm[ty + 16 * i][tx + 16 * j] = ak[i][j];
            }
    }
    __syncthreads();

    {
        float L[4][4] = {};
        #pragma unroll
        for (int kk = 0; kk < 64; kk++) {
            float a[4], bv[4];
            #pragma unroll
            for (int i = 0; i < 4; i++) a[i] = Bm[ty + 16 * i][kk];
            #pragma unroll
            for (int j = 0; j < 4; j++) bv[j] = Cm[tx + 16 * j][kk];
            #pragma unroll
            for (int i = 0; i < 4; i++)
                #pragma unroll
                for (int j = 0; j < 4; j++)
                    L[i][j] += a[i] * bv[j];
        }
        #pragma unroll
        for (int i = 0; i < 4; i++) {
            #pragma unroll
            for (int j = 0; j < 4; j++) L[i][j] *= 0.125f;
            float mx = L[i][0];
            #pragma unroll
            for (int j = 1; j < 4; j++) mx = fmaxf(mx, L[i][j]);
            #pragma unroll
            for (int o = 1; o < 16; o <<= 1)
                mx = fmaxf(mx, __shfl_xor_sync(0xffffffffu, mx, o, 16));
            float s = 0.f;
            #pragma unroll
            for (int j = 0; j < 4; j++) { L[i][j] = __expf(L[i][j] - mx); s += L[i][j]; }
            #pragma unroll
            for (int o = 1; o < 16; o <<= 1)
                s += __shfl_xor_sync(0xffffffffu, s, o, 16);
            float inv = 1.0f / s;
            #pragma unroll
            for (int j = 0; j < 4; j++)
                A[ty + 16 * i][tx + 16 * j] = L[i][j] * inv;
        }
    }
    __syncthreads();

    #pragma unroll
    for (int e = 0; e < 16; e++) {
        int idx = tid + e * 256;
        int g = idx >> 6;
        Bm[g][idx & 63] = tok[(size_t)bh * 4096 + idx] / (norm[bh * 64 + g] + 1e-5f);
    }
    __syncthreads();

    {
        float av[4][4] = {};
        #pragma unroll
        for (int kk = 0; kk < 64; kk++) {
            float a[4];
            #pragma unroll
            for (int i = 0; i < 4; i++) a[i] = Bm[ty + 16 * i][kk];
            #pragma unroll
            for (int j = 0; j < 4; j++) {
                float wv = __ldg(&Wv[(tx + 16 * j) * 64 + kk]);
                #pragma unroll
                for (int i = 0; i < 4; i++) av[i][j] += a[i] * wv;
            }
        }
        __syncthreads();
        #pragma unroll
        for (int i = 0; i < 4; i++)
            #pragma unroll
            for (int j = 0; j < 4; j++)
                Cm[ty + 16 * i][tx + 16 * j] = av[i][j];
    }
    __syncthreads();

    {
        float ao[4][4] = {};
        #pragma unroll
        for (int kk = 0; kk < 64; kk++) {
            float a[4], bv[4];
            #pragma unroll
            for (int i = 0; i < 4; i++) a[i] = A[ty + 16 * i][kk];
            #pragma unroll
            for (int j = 0; j < 4; j++) bv[j] = Cm[kk][tx + 16 * j];
            #pragma unroll
            for (int i = 0; i < 4; i++)
                #pragma unroll
                for (int j = 0; j < 4; j++)
                    ao[i][j] += a[i] * bv[j];
        }
        __syncthreads();
        #pragma unroll
        for (int i = 0; i < 4; i++)
            #pragma unroll
            for (int j = 0; j < 4; j++)
                Bm[ty + 16 * i][tx + 16 * j] = ao[i][j];
    }
    __syncthreads();

    {
        float am[4][8] = {};
        #pragma unroll
        for (int kk = 0; kk < 64; kk++) {
            float a[4];
            #pragma unroll
            for (int i = 0; i < 4; i++) a[i] = Bm[ty + 16 * i][kk];
            #pragma unroll
            for (int j = 0; j < 8; j++) {
                float wv = __ldg(&Wout[(size_t)(tx + 16 * j) * INNER + h * DH + kk]);
                #pragma unroll
                for (int i = 0; i < 4; i++) am[i][j] += a[i] * wv;
            }
        }
        #pragma unroll
        for (int i = 0; i < 4; i++) {
            int g = ty + 16 * i;
            #pragma unroll
            for (int j = 0; j < 8; j++) {
                int o = tx + 16 * j;
                float v = am[i][j];
                __nv_bfloat16 hv = __float2bfloat16(v);
                float r = v - __bfloat162float(hv);
                size_t idx = ((size_t)b * CC + o) * INNER + h * DH + g;
                Mthi[idx] = hv;
                Mtlo[idx] = __float2bfloat16(r);
            }
        }
    }
}

// ---------------- K5: fused scatter + projection on tensor cores ----------------
__global__ __launch_bounds__(256)
void final_mma_kernel(const __nv_bfloat16* __restrict__ Whi,
                      const __nv_bfloat16* __restrict__ Wlo,
                      const __nv_bfloat16* __restrict__ Mthi,
                      const __nv_bfloat16* __restrict__ Mtlo,
                      const float* __restrict__ bout,
                      float* __restrict__ out)
{
    extern __shared__ uint32_t smem_u32[];

    const int pt = blockIdx.x;
    const int b  = pt >> 9;
    const int n0 = (pt & 511) * 128;

    const int tid  = threadIdx.x;
    const int wid  = tid >> 5;
    const int lane = tid & 31;
    const int grp  = lane >> 2;
    const int tid4 = lane & 3;
    const int wm   = wid & 1;
    const int wn   = wid >> 1;

    float acc[4][4][4];
    #pragma unroll
    for (int i = 0; i < 4; i++)
        #pragma unroll
        for (int j = 0; j < 4; j++)
            #pragma unroll
            for (int r = 0; r < 4; r++) acc[i][j][r] = 0.f;

    uint32_t sbase = (uint32_t)__cvta_generic_to_shared(smem_u32);

    auto load_fin = [&](uint32_t sb, int it) {
        const int h  = it >> 1;
        const int g0 = (it & 1) * 32;
        #pragma unroll
        for (int j = 0; j < 8; j++) {
            int id  = tid + j * 256;
            int arr = id >> 9;
            int c   = id & 511;
            int row = c >> 2;
            int c4  = c & 3;
            uint32_t woff = (uint32_t)row * 16 + ((c4 ^ (row & 3)) << 2);
            uint32_t saddr = sb + (arr * 2048 + woff) * 4;
            const __nv_bfloat16* g;
            if (arr < 2) {
                size_t off = (((size_t)(b * HEADS + h) * NN) + n0 + row) * GG + g0 + c4 * 8;
                g = (arr == 0 ? Whi : Wlo) + off;
            } else {
                size_t off = ((size_t)b * CC + row) * INNER + h * DH + g0 + c4 * 8;
                g = (arr == 2 ? Mthi : Mtlo) + off;
            }
            cp16(saddr, g, true);
        }
    };

    load_fin(sbase, 0);
    asm volatile("cp.async.commit_group;\n" ::: "memory");

    for (int it = 0; it < 16; ++it) {
        const int cur = it & 1;
        if (it + 1 < 16) {
            load_fin(sbase + (uint32_t)(1 - cur) * 32768, it + 1);
            asm volatile("cp.async.commit_group;\n" ::: "memory");
            asm volatile("cp.async.wait_group 1;\n" ::: "memory");
        } else {
            asm volatile("cp.async.wait_group 0;\n" ::: "memory");
        }
        __syncthreads();

        const uint32_t* Ahi = smem_u32 + (size_t)cur * 8192;
        const uint32_t* Alo = Ahi + 2048;
        const uint32_t* Bhi = Ahi + 4096;
        const uint32_t* Blo = Ahi + 6144;

        #pragma unroll
        for (int s = 0; s < 2; s++) {
            const int kwb = s * 8;
            uint32_t ah[4][4], al[4][4];
            #pragma unroll
            for (int mi = 0; mi < 4; mi++) {
                int r0 = wm * 64 + mi * 16 + grp;
                ah[mi][0] = lds_frag(Ahi, r0,     kwb + tid4);
                ah[mi][1] = lds_frag(Ahi, r0 + 8, kwb + tid4);
                ah[mi][2] = lds_frag(Ahi, r0,     kwb + tid4 + 4);
                ah[mi][3] = lds_frag(Ahi, r0 + 8, kwb + tid4 + 4);
                al[mi][0] = lds_frag(Alo, r0,     kwb + tid4);
                al[mi][1] = lds_frag(Alo, r0 + 8, kwb + tid4);
                al[mi][2] = lds_frag(Alo, r0,     kwb + tid4 + 4);
                al[mi][3] = lds_frag(Alo, r0 + 8, kwb + tid4 + 4);
            }
            uint32_t bh[4][2], bl[4][2];
            #pragma unroll
            for (int ni = 0; ni < 4; ni++) {
                int r0 = wn * 32 + ni * 8 + grp;
                bh[ni][0] = lds_frag(Bhi, r0, kwb + tid4);
                bh[ni][1] = lds_frag(Bhi, r0, kwb + tid4 + 4);
                bl[ni][0] = lds_frag(Blo, r0, kwb + tid4);
                bl[ni][1] = lds_frag(Blo, r0, kwb + tid4 + 4);
            }
            #pragma unroll
            for (int mi = 0; mi < 4; mi++)
                #pragma unroll
                for (int ni = 0; ni < 4; ni++)
                    mma_bf16(acc[mi][ni], ah[mi][0], ah[mi][1], ah[mi][2], ah[mi][3],
                             bh[ni][0], bh[ni][1]);
            #pragma unroll
            for (int mi = 0; mi < 4; mi++)
                #pragma unroll
                for (int ni = 0; ni < 4; ni++)
                    mma_bf16(acc[mi][ni], ah[mi][0], ah[mi][1], ah[mi][2], ah[mi][3],
                             bl[ni][0], bl[ni][1]);
            #pragma unroll
            for (int mi = 0; mi < 4; mi++)
                #pragma unroll
                for (int ni = 0; ni < 4; ni++)
                    mma_bf16(acc[mi][ni], al[mi][0], al[mi][1], al[mi][2], al[mi][3],
                             bh[ni][0], bh[ni][1]);
        }
        __syncthreads();
    }

    #pragma unroll
    for (int mi = 0; mi < 4; mi++) {
        int row = wm * 64 + mi * 16 + grp;
        int n  = n0 + row;
        #pragma unroll
        for (int ni = 0; ni < 4; ni++) {
            int oc = wn * 32 + ni * 8 + tid4 * 2;
            float b0v = bout[oc], b1v = bout[oc + 1];
            size_t base0 = ((size_t)b * NN + n) * CC + oc;
            out[base0]     = acc[mi][ni][0] + b0v;
            out[base0 + 1] = acc[mi][ni][1] + b1v;
            size_t base1 = ((size_t)b * NN + n + 8) * CC + oc;
            out[base1]     = acc[mi][ni][2] + b0v;
            out[base1 + 1] = acc[mi][ni][3] + b1v;
        }
    }
}

// ---------------- launch ----------------
extern "C" void kernel_launch(void* const* d_in, const int* in_sizes, int n_in,
                              void* d_out, int out_size) {
    const float* x     = (const float*)d_in[0];
    const float* Wfx   = (const float*)d_in[1];
    const float* bfx   = (const float*)d_in[2];
    const float* Wx    = (const float*)d_in[3];
    const float* bx    = (const float*)d_in[4];
    const float* Wsl   = (const float*)d_in[5];
    const float* bsl   = (const float*)d_in[6];
    const float* temp  = (const float*)d_in[7];
    const float* Wq    = (const float*)d_in[8];
    const float* Wk    = (const float*)d_in[9];
    const float* Wv    = (const float*)d_in[10];
    const float* Wout  = (const float*)d_in[11];
    const float* bout  = (const float*)d_in[12];
    float* out = (float*)d_out;

    float *p_fx, *p_tokp, *p_normp, *p_tok, *p_norm, *p_lb;
    __nv_bfloat16 *p_xhi, *p_xlo, *p_whi, *p_wlo;
    __nv_bfloat16 *p_swhi, *p_swlo, *p_Mthi, *p_Mtlo;
    cudaGetSymbolAddress((void**)&p_fx, g_fx);
    cudaGetSymbolAddress((void**)&p_tokp, g_tokp);
    cudaGetSymbolAddress((void**)&p_normp, g_normp);
    cudaGetSymbolAddress((void**)&p_tok, g_tok);
    cudaGetSymbolAddress((void**)&p_norm, g_norm);
    cudaGetSymbolAddress((void**)&p_lb, g_lbias);
    cudaGetSymbolAddress((void**)&p_xhi, g_xhi);
    cudaGetSymbolAddress((void**)&p_xlo, g_xlo);
    cudaGetSymbolAddress((void**)&p_whi, g_whi);
    cudaGetSymbolAddress((void**)&p_wlo, g_wlo);
    cudaGetSymbolAddress((void**)&p_swhi, g_swhi);
    cudaGetSymbolAddress((void**)&p_swlo, g_swlo);
    cudaGetSymbolAddress((void**)&p_Mthi, g_Mthi);
    cudaGetSymbolAddress((void**)&p_Mtlo, g_Mtlo);

    static bool attr_set = false;
    if (!attr_set) {
        cudaFuncSetAttribute(conv_mma_kernel,
                             cudaFuncAttributeMaxDynamicSharedMemorySize, 2 * CSTAGE);
        cudaFuncSetAttribute(final_mma_kernel,
                             cudaFuncAttributeMaxDynamicSharedMemorySize, 65536);
        attr_set = true;
    }

    dim3 blk(16, 16);

    // 0. staging: x split, fx weights split, combined logit weights, logit bias
    split_x_kernel<<<(BB * NN * CC) / 256, 256>>>(x, p_xhi, p_xlo);
    split_w_kernel<<<(512 * KTOT) / 256, 256>>>(Wfx, p_whi, p_wlo);
    combine_w_kernel<<<dim3(512, 9), 128>>>(Wx, Wsl, temp, p_whi, p_wlo);
    lbias_kernel<<<512, 32>>>(bx, Wsl, bsl, temp, p_lb);

    // 1. fused conv (128x256 tiles, 512 threads = 4 warps/SMSP)
    conv_mma_kernel<<<dim3(4, 512, BB), 512, 2 * CSTAGE>>>(
        p_xhi, p_xlo, p_whi, p_wlo, bfx, p_lb, p_fx, p_swhi, p_swlo);

    // 2. slice token split-K partials + reduce
    token_reduce_kernel<<<dim3(SPLITS, BB * HEADS), blk>>>(
        p_swhi, p_swlo, p_fx, p_tokp, p_normp);
    split_reduce_kernel<<<260, 256>>>(p_tokp, p_normp, p_tok, p_norm);

    // 3. tiny attention + fused Wout fold -> Mt (bf16 hi/lo)
    attn_kernel<<<BB * HEADS, blk>>>(p_tok, p_norm, Wq, Wk, Wv, Wout, p_Mthi, p_Mtlo);

    // 4. fused scatter + projection on tensor cores
    final_mma_kernel<<<1024, 256, 65536>>>(p_swhi, p_swlo, p_Mthi, p_Mtlo, bout, out);
}

// round 9
// speedup vs baseline: 1.1180x; 1.1180x over previous
#include <cuda_runtime.h>
#include <cuda_bf16.h>
#include <math.h>
#include <stdint.h>

// Problem constants
#define BB 2
#define HH 256
#define WW 256
#define NN 65536          // H*W
#define CC 128
#define HEADS 8
#define DH 64             // dim_head
#define GG 64             // SLICE
#define INNER 512         // HEADS*DH
#define SPLITS 64         // split-K for token reduction
#define CHUNK 1024        // tokens per split (NN/SPLITS)
#define KTOT 1152         // 9 taps * 128 channels

// ---------------- device scratch (static, no allocs) ----------------
__device__ float g_tokp[(size_t)SPLITS * BB * HEADS * GG * DH];
__device__ float g_normp[(size_t)SPLITS * BB * HEADS * GG];
__device__ float g_tok [(size_t)BB * HEADS * GG * DH];
__device__ float g_norm[(size_t)BB * HEADS * GG];
__device__ float g_lbias[INNER];                     // (bx·Wslice + bslice)/temp

// fx_mid as bf16 hi/lo pair  [b][n][inner]
__device__ __align__(16) __nv_bfloat16 g_fxhi[(size_t)BB * NN * INNER];
__device__ __align__(16) __nv_bfloat16 g_fxlo[(size_t)BB * NN * INNER];
// slice weights as bf16 hi/lo pair  [bh][n][g]
__device__ __align__(16) __nv_bfloat16 g_swhi[(size_t)BB * HEADS * NN * GG];
__device__ __align__(16) __nv_bfloat16 g_swlo[(size_t)BB * HEADS * NN * GG];
// Mt = (out_slice · Wout^T) transposed: [b][o][h*64+g], bf16 hi/lo
__device__ __align__(16) __nv_bfloat16 g_Mthi[(size_t)BB * CC * INNER];
__device__ __align__(16) __nv_bfloat16 g_Mtlo[(size_t)BB * CC * INNER];

// bf16 3-split staging for conv
__device__ __align__(16) __nv_bfloat16 g_xhi[(size_t)BB * NN * CC];
__device__ __align__(16) __nv_bfloat16 g_xlo[(size_t)BB * NN * CC];
// rows 0..511: Wfx cols; rows 512..1023: combined logit weights (Wx·Wslice/temp)
__device__ __align__(16) __nv_bfloat16 g_whi[(size_t)1024 * KTOT];
__device__ __align__(16) __nv_bfloat16 g_wlo[(size_t)1024 * KTOT];

// ---------------- prep kernels ----------------
__global__ void split_x_kernel(const float* __restrict__ x,
                               __nv_bfloat16* __restrict__ xhi,
                               __nv_bfloat16* __restrict__ xlo) {
    size_t i = (size_t)blockIdx.x * 256 + threadIdx.x;
    float f = x[i];
    __nv_bfloat16 h = __float2bfloat16(f);
    float r = f - __bfloat162float(h);
    xhi[i] = h;
    xlo[i] = __float2bfloat16(r);
}

// Wfx (fx conv weights) -> rows 0..511 of g_whi/g_wlo, transposed [oc][k]
__global__ void split_w_kernel(const float* __restrict__ Wfx,
                               __nv_bfloat16* __restrict__ whi,
                               __nv_bfloat16* __restrict__ wlo) {
    int i = blockIdx.x * 256 + threadIdx.x;   // 512*1152 total
    int oc = i / KTOT;
    int k  = i - oc * KTOT;
    float f = Wfx[(size_t)k * 512 + oc];
    __nv_bfloat16 h = __float2bfloat16(f);
    float r = f - __bfloat162float(h);
    whi[i] = h;
    wlo[i] = __float2bfloat16(r);
}

// W~[k][h*64+g] = (sum_d Wx[k][h*64+d]*Wslice[g][d]) / temp_h -> rows 512..1023
__global__ void combine_w_kernel(const float* __restrict__ Wx,
                                 const float* __restrict__ Wsl,
                                 const float* __restrict__ temp,
                                 __nv_bfloat16* __restrict__ whi,
                                 __nv_bfloat16* __restrict__ wlo) {
    __shared__ float ws[64];
    const int col = blockIdx.x;          // 0..511
    const int h = col >> 6, g = col & 63;
    const int tid = threadIdx.x;         // 128
    if (tid < 64) ws[tid] = Wsl[g * 64 + tid];
    __syncthreads();
    float t = fminf(fmaxf(temp[h], 0.1f), 5.0f);
    float invt = 1.0f / t;
    int k = blockIdx.y * 128 + tid;      // 9 y-blocks -> 0..1151
    const float* wr = Wx + (size_t)k * 512 + h * 64;
    float s = 0.f;
    #pragma unroll 8
    for (int d = 0; d < 64; d++) s += wr[d] * ws[d];
    s *= invt;
    __nv_bfloat16 hv = __float2bfloat16(s);
    size_t o = (size_t)(512 + col) * KTOT + k;
    whi[o] = hv;
    wlo[o] = __float2bfloat16(s - __bfloat162float(hv));
}

// lbias[h*64+g] = (bx_h · Wslice_g + bslice_g) / temp_h   (one block per col)
__global__ void lbias_kernel(const float* __restrict__ bx,
                             const float* __restrict__ Wsl,
                             const float* __restrict__ bsl,
                             const float* __restrict__ temp,
                             float* __restrict__ lb) {
    int col = blockIdx.x;                // 0..511
    int h = col >> 6, g = col & 63;
    int lane = threadIdx.x;              // 32
    float s = bx[h * 64 + lane] * Wsl[g * 64 + lane]
            + bx[h * 64 + 32 + lane] * Wsl[g * 64 + 32 + lane];
    #pragma unroll
    for (int o = 16; o > 0; o >>= 1)
        s += __shfl_xor_sync(0xffffffffu, s, o);
    if (lane == 0) {
        float t = fminf(fmaxf(temp[h], 0.1f), 5.0f);
        lb[col] = (s + bsl[g]) / t;
    }
}

// ---------------- shared MMA plumbing ----------------
__device__ __forceinline__ void cp16(uint32_t saddr, const void* g, bool valid) {
    int sz = valid ? 16 : 0;
    asm volatile("cp.async.cg.shared.global [%0], [%1], 16, %2;\n"
                 :: "r"(saddr), "l"(g), "r"(sz));
}

// 16-word rows (final kernel, kc=32 layout)
__device__ __forceinline__ uint32_t lds_frag(const uint32_t* base, int row, int kw) {
    return base[row * 16 + ((((kw >> 2) ^ (row & 3)) << 2) | (kw & 3))];
}

__device__ __forceinline__ void mma_bf16(float c[4], uint32_t a0, uint32_t a1,
                                         uint32_t a2, uint32_t a3,
                                         uint32_t b0, uint32_t b1) {
    asm volatile(
        "mma.sync.aligned.m16n8k16.row.col.f32.bf16.bf16.f32 "
        "{%0,%1,%2,%3}, {%4,%5,%6,%7}, {%8,%9}, {%0,%1,%2,%3};"
        : "+f"(c[0]), "+f"(c[1]), "+f"(c[2]), "+f"(c[3])
        : "r"(a0), "r"(a1), "r"(a2), "r"(a3), "r"(b0), "r"(b1));
}

__device__ __forceinline__ void ldsm4(uint32_t r[4], uint32_t addr) {
    asm volatile("ldmatrix.sync.aligned.m8n8.x4.shared.b16 {%0,%1,%2,%3}, [%4];"
                 : "=r"(r[0]), "=r"(r[1]), "=r"(r[2]), "=r"(r[3]) : "r"(addr));
}

__device__ __forceinline__ void ldsm4t(uint32_t r[4], uint32_t addr) {
    asm volatile("ldmatrix.sync.aligned.m8n8.x4.trans.shared.b16 {%0,%1,%2,%3}, [%4];"
                 : "=r"(r[0]), "=r"(r[1]), "=r"(r[2]), "=r"(r[3]) : "r"(addr));
}

// ---------------- conv: implicit GEMM 128x256, kc=64, ldmatrix feed (R7 config) ----------------
// ocb 0..1: fx output (bf16 hi/lo, cols ocb*256..+255); ocb 2..3: slice-weight softmax.
// Stage (96KB): Ahi 16K | Alo 16K | Bhi 32K | Blo 32K.
#define CSTAGE 98304

__device__ __forceinline__ void conv_load(
    uint32_t st,
    const __nv_bfloat16* __restrict__ Xhi, const __nv_bfloat16* __restrict__ Xlo,
    const __nv_bfloat16* __restrict__ Whi, const __nv_bfloat16* __restrict__ Wlo,
    int it, int b, int hrow, int w0, int ocb, int tid)
{
    const int kg  = it * 64;
    const int tap = kg >> 7;
    const int dy = tap / 3 - 1, dx = tap % 3 - 1;
    const int c0 = kg & 127;            // 0 or 64
    const int hp = hrow + dy;
    const bool hok = (hp >= 0) && (hp < HH);
    const int hpc = hok ? hp : 0;

    #pragma unroll
    for (int j = 0; j < 8; j++) {
        int id  = tid + j * 256;
        int arr = id >> 10;             // 0:Ahi 1:Alo
        int l   = id & 1023;
        int row = l >> 3;
        int gr  = l & 7;
        uint32_t saddr = st + arr * 16384 + row * 128 + ((gr ^ (row & 7)) << 4);
        int wp = w0 + row + dx;
        bool valid = hok && (wp >= 0) && (wp < WW);
        int wpc = valid ? wp : 0;
        const __nv_bfloat16* g = (arr == 0 ? Xhi : Xlo) +
            (((size_t)b * NN + (size_t)hpc * WW + wpc) * CC + c0 + gr * 8);
        cp16(saddr, g, valid);
    }
    #pragma unroll
    for (int j = 8; j < 24; j++) {
        int id  = tid + (j - 8) * 256;  // 0..4095
        int arr = id >> 11;             // 0:Bhi 1:Blo
        int l   = id & 2047;
        int row = l >> 3;
        int gr  = l & 7;
        uint32_t saddr = st + 32768 + arr * 32768 + row * 128 + ((gr ^ (row & 7)) << 4);
        const __nv_bfloat16* g = (arr == 0 ? Whi : Wlo) +
            ((size_t)(ocb * 256 + row) * KTOT + kg + gr * 8);
        cp16(saddr, g, true);
    }
}

__global__ __launch_bounds__(256, 1)
void conv_mma_kernel(const __nv_bfloat16* __restrict__ Xhi,
                     const __nv_bfloat16* __restrict__ Xlo,
                     const __nv_bfloat16* __restrict__ Whi,
                     const __nv_bfloat16* __restrict__ Wlo,
                     const float* __restrict__ bfx,
                     const float* __restrict__ lbias,
                     __nv_bfloat16* __restrict__ fxhi,
                     __nv_bfloat16* __restrict__ fxlo,
                     __nv_bfloat16* __restrict__ swhi,
                     __nv_bfloat16* __restrict__ swlo)
{
    extern __shared__ char smem[];           // 2 stages x 96KB

    const int ocb = blockIdx.x;              // 0..3
    const int pt  = blockIdx.y;              // 0..511
    const int b   = blockIdx.z;
    const int n0  = pt * 128;
    const int hrow = n0 >> 8;
    const int w0   = n0 & 255;

    const int tid  = threadIdx.x;
    const int wid  = tid >> 5;
    const int lane = tid & 31;
    const int grp  = lane >> 2;
    const int tid4 = lane & 3;
    const int wm   = wid & 1;                // 2 row-groups of 64
    const int wn   = wid >> 1;               // 4 col-groups of 64

    const int t8   = lane >> 3;
    const int r8   = lane & 7;
    const int a_roff = ((t8 & 1) << 3) + r8;
    const int a_gsel = t8 >> 1;
    const int b_roff = ((t8 >> 1) << 3) + r8;
    const int b_gsel = t8 & 1;

    float acc[4][8][4];
    #pragma unroll
    for (int i = 0; i < 4; i++)
        #pragma unroll
        for (int j = 0; j < 8; j++)
            #pragma unroll
            for (int r = 0; r < 4; r++) acc[i][j][r] = 0.f;

    uint32_t sbase = (uint32_t)__cvta_generic_to_shared(smem);

    conv_load(sbase, Xhi, Xlo, Whi, Wlo, 0, b, hrow, w0, ocb, tid);
    asm volatile("cp.async.commit_group;\n" ::: "memory");

    for (int it = 0; it < 18; ++it) {
        const int cur = it & 1;
        if (it + 1 < 18) {
            conv_load(sbase + (uint32_t)(1 - cur) * CSTAGE,
                      Xhi, Xlo, Whi, Wlo, it + 1, b, hrow, w0, ocb, tid);
            asm volatile("cp.async.commit_group;\n" ::: "memory");
            asm volatile("cp.async.wait_group 1;\n" ::: "memory");
        } else {
            asm volatile("cp.async.wait_group 0;\n" ::: "memory");
        }
        __syncthreads();

        const uint32_t stA = sbase + (uint32_t)cur * CSTAGE;
        const uint32_t stB = stA + 32768;

        #pragma unroll
        for (int s = 0; s < 4; s++) {
            uint32_t ah[4][4], al[4][4];
            #pragma unroll
            for (int mi = 0; mi < 4; mi++) {
                int row = wm * 64 + mi * 16 + a_roff;
                int g = 2 * s + a_gsel;
                uint32_t addr = stA + row * 128 + ((g ^ (row & 7)) << 4);
                ldsm4(ah[mi], addr);
                ldsm4(al[mi], addr + 16384);
            }
            #pragma unroll
            for (int np = 0; np < 4; np++) {
                int row = wn * 64 + np * 16 + b_roff;
                int g = 2 * s + b_gsel;
                uint32_t addr = stB + row * 128 + ((g ^ (row & 7)) << 4);
                uint32_t bh[4], bl[4];
                ldsm4(bh, addr);
                ldsm4(bl, addr + 32768);
                #pragma unroll
                for (int mi = 0; mi < 4; mi++) {
                    mma_bf16(acc[mi][2 * np],     ah[mi][0], ah[mi][1], ah[mi][2], ah[mi][3], bh[0], bh[1]);
                    mma_bf16(acc[mi][2 * np + 1], ah[mi][0], ah[mi][1], ah[mi][2], ah[mi][3], bh[2], bh[3]);
                }
                #pragma unroll
                for (int mi = 0; mi < 4; mi++) {
                    mma_bf16(acc[mi][2 * np],     ah[mi][0], ah[mi][1], ah[mi][2], ah[mi][3], bl[0], bl[1]);
                    mma_bf16(acc[mi][2 * np + 1], ah[mi][0], ah[mi][1], ah[mi][2], ah[mi][3], bl[2], bl[3]);
                }
                #pragma unroll
                for (int mi = 0; mi < 4; mi++) {
                    mma_bf16(acc[mi][2 * np],     al[mi][0], al[mi][1], al[mi][2], al[mi][3], bh[0], bh[1]);
                    mma_bf16(acc[mi][2 * np + 1], al[mi][0], al[mi][1], al[mi][2], al[mi][3], bh[2], bh[3]);
                }
            }
        }
        __syncthreads();
    }

    if (ocb < 2) {
        // fx output: bf16 hi/lo pairs with bias
        const int ocbase = ocb * 256;
        #pragma unroll
        for (int mi = 0; mi < 4; mi++) {
            int row = wm * 64 + mi * 16 + grp;
            int n  = n0 + row;
            #pragma unroll
            for (int ni = 0; ni < 8; ni++) {
                int col = wn * 64 + ni * 8 + tid4 * 2;
                int oc  = ocbase + col;
                float b0v = bfx[oc], b1v = bfx[oc + 1];
                float v0 = acc[mi][ni][0] + b0v;
                float v1 = acc[mi][ni][1] + b1v;
                float v2 = acc[mi][ni][2] + b0v;
                float v3 = acc[mi][ni][3] + b1v;
                __nv_bfloat16 h0 = __float2bfloat16(v0), h1 = __float2bfloat16(v1);
                __nv_bfloat16 h2 = __float2bfloat16(v2), h3 = __float2bfloat16(v3);
                __nv_bfloat162 ph0; ph0.x = h0; ph0.y = h1;
                __nv_bfloat162 pl0; pl0.x = __float2bfloat16(v0 - __bfloat162float(h0));
                                    pl0.y = __float2bfloat16(v1 - __bfloat162float(h1));
                __nv_bfloat162 ph1; ph1.x = h2; ph1.y = h3;
                __nv_bfloat162 pl1; pl1.x = __float2bfloat16(v2 - __bfloat162float(h2));
                                    pl1.y = __float2bfloat16(v3 - __bfloat162float(h3));
                size_t base0 = ((size_t)b * NN + n) * INNER + oc;
                size_t base1 = ((size_t)b * NN + n + 8) * INNER + oc;
                *(__nv_bfloat162*)(fxhi + base0) = ph0;
                *(__nv_bfloat162*)(fxlo + base0) = pl0;
                *(__nv_bfloat162*)(fxhi + base1) = ph1;
                *(__nv_bfloat162*)(fxlo + base1) = pl1;
            }
        }
    } else {
        // logits: stage to smem, softmax per (pixel, head), emit bf16 hi/lo
        float* sred = (float*)smem;          // [128][260]
        #pragma unroll
        for (int mi = 0; mi < 4; mi++) {
            int row = wm * 64 + mi * 16 + grp;
            #pragma unroll
            for (int ni = 0; ni < 8; ni++) {
                int col = wn * 64 + ni * 8 + tid4 * 2;
                sred[row * 260 + col]           = acc[mi][ni][0];
                sred[row * 260 + col + 1]       = acc[mi][ni][1];
                sred[(row + 8) * 260 + col]     = acc[mi][ni][2];
                sred[(row + 8) * 260 + col + 1] = acc[mi][ni][3];
            }
        }
        __syncthreads();

        #pragma unroll
        for (int pass = 0; pass < 2; pass++) {
            int tsk = tid + pass * 256;      // 0..511
            int row  = tsk >> 2;
            int hloc = tsk & 3;
            int h = (ocb - 2) * 4 + hloc;
            int n = n0 + row;
            const float* lb = lbias + h * 64;
            float* sr = sred + row * 260 + hloc * 64;

            float mx = -1e30f;
            #pragma unroll 8
            for (int g = 0; g < 64; g++) mx = fmaxf(mx, sr[g] + lb[g]);
            float ssum = 0.f;
            #pragma unroll 8
            for (int g = 0; g < 64; g++) {
                float e = __expf(sr[g] + lb[g] - mx);
                ssum += e;
                sr[g] = e;
            }
            float inv = 1.0f / ssum;

            size_t base = ((size_t)(b * HEADS + h) * NN + n) * GG;
            #pragma unroll
            for (int c = 0; c < 8; c++) {
                union { __nv_bfloat16 hb[8]; uint4 u; } Uh, Ul;
                #pragma unroll
                for (int e = 0; e < 8; e++) {
                    float v = sr[c * 8 + e] * inv;
                    __nv_bfloat16 hv = __float2bfloat16(v);
                    Uh.hb[e] = hv;
                    Ul.hb[e] = __float2bfloat16(v - __bfloat162float(hv));
                }
                ((uint4*)(swhi + base))[c] = Uh.u;
                ((uint4*)(swlo + base))[c] = Ul.u;
            }
        }
    }
}

// ---------------- K3: token reduction on tensor cores ----------------
// tok[g][d] = sum_n w[n][g]*fx[n][d]; norm[g] = sum_n w[n][g] (via ones-B MMA).
// Block: 128 threads (4 warps), each warp one 16-g strip. K=16 tokens/iter.
// Stage (8KB): whi 2K | wlo 2K | fxhi 2K | fxlo 2K. Rows 128B, granule-swizzled.
__global__ __launch_bounds__(128)
void token_mma_kernel(const __nv_bfloat16* __restrict__ whi,
                      const __nv_bfloat16* __restrict__ wlo,
                      const __nv_bfloat16* __restrict__ fxhi,
                      const __nv_bfloat16* __restrict__ fxlo,
                      float* __restrict__ tokp,
                      float* __restrict__ normp)
{
    __shared__ __align__(16) char smem[2 * 8192];

    const int bh = blockIdx.y;
    const int b = bh >> 3, h = bh & 7;
    const int split = blockIdx.x;
    const int nbase = split * CHUNK;

    const int tid  = threadIdx.x;
    const int wid  = tid >> 5;          // 0..3: g-strip wid*16
    const int lane = tid & 31;
    const int grp  = lane >> 2;
    const int tid4 = lane & 3;
    const int t8   = lane >> 3;
    const int r8   = lane & 7;
    // trans-ldsm lane map: row-in-tile (k index), granule select
    const int lrow = r8 + ((t8 >> 1) << 3);   // 0..15
    const int lgr  = t8 & 1;

    const uint32_t ONES = 0x3F803F80u;  // bf16(1.0) x2

    float acc[8][4];
    #pragma unroll
    for (int j = 0; j < 8; j++)
        #pragma unroll
        for (int r = 0; r < 4; r++) acc[j][r] = 0.f;
    float accn[4] = {};

    uint32_t sbase = (uint32_t)__cvta_generic_to_shared(smem);

    // loader: 4 arrays x 16 rows x 8 granules = 512 lines / 128 threads = 4 each
    auto load = [&](uint32_t st, int t0) {
        #pragma unroll
        for (int j = 0; j < 4; j++) {
            int id  = tid + j * 128;
            int arr = id >> 7;          // 0:whi 1:wlo 2:fxhi 3:fxlo
            int l   = id & 127;
            int row = l >> 3;
            int gr  = l & 7;
            uint32_t saddr = st + arr * 2048 + row * 128 + ((gr ^ (row & 7)) << 4);
            int n = nbase + t0 + row;
            const __nv_bfloat16* g;
            if (arr < 2) {
                g = (arr == 0 ? whi : wlo) + ((size_t)bh * NN + n) * GG + gr * 8;
            } else {
                g = (arr == 2 ? fxhi : fxlo) +
                    ((size_t)b * NN + n) * INNER + h * DH + gr * 8;
            }
            cp16(saddr, g, true);
        }
    };

    load(sbase, 0);
    asm volatile("cp.async.commit_group;\n" ::: "memory");

    for (int it = 0; it < 64; ++it) {
        const int cur = it & 1;
        if (it + 1 < 64) {
            load(sbase + (uint32_t)(1 - cur) * 8192, (it + 1) * 16);
            asm volatile("cp.async.commit_group;\n" ::: "memory");
            asm volatile("cp.async.wait_group 1;\n" ::: "memory");
        } else {
            asm volatile("cp.async.wait_group 0;\n" ::: "memory");
        }
        __syncthreads();

        const uint32_t st = sbase + (uint32_t)cur * 8192;

        // A = w^T fragments for this warp's g-strip (granules wid*2 + lgr)
        uint32_t awh[4], awl[4];
        {
            int gr = wid * 2 + lgr;
            uint32_t addr = st + lrow * 128 + ((gr ^ (lrow & 7)) << 4);
            ldsm4t(awh, addr);
            ldsm4t(awl, addr + 2048);
        }
        // norm: ones-B MMAs
        mma_bf16(accn, awh[0], awh[1], awh[2], awh[3], ONES, ONES);
        mma_bf16(accn, awl[0], awl[1], awl[2], awl[3], ONES, ONES);

        // B = fx^T fragments per d-region (16 cols each)
        #pragma unroll
        for (int j = 0; j < 4; j++) {
            int gr = j * 2 + lgr;
            uint32_t addr = st + 4096 + lrow * 128 + ((gr ^ (lrow & 7)) << 4);
            uint32_t bfh[4], bfl[4];
            ldsm4t(bfh, addr);
            ldsm4t(bfl, addr + 2048);
            // n-lo frag {r0,r2}, n-hi frag {r1,r3}
            mma_bf16(acc[2 * j],     awh[0], awh[1], awh[2], awh[3], bfh[0], bfh[2]);
            mma_bf16(acc[2 * j + 1], awh[0], awh[1], awh[2], awh[3], bfh[1], bfh[3]);
            mma_bf16(acc[2 * j],     awh[0], awh[1], awh[2], awh[3], bfl[0], bfl[2]);
            mma_bf16(acc[2 * j + 1], awh[0], awh[1], awh[2], awh[3], bfl[1], bfl[3]);
            mma_bf16(acc[2 * j],     awl[0], awl[1], awl[2], awl[3], bfh[0], bfh[2]);
            mma_bf16(acc[2 * j + 1], awl[0], awl[1], awl[2], awl[3], bfh[1], bfh[3]);
        }
        __syncthreads();
    }

    // epilogue: write tokp + normp
    const size_t base = ((size_t)split * (BB * HEADS) + bh) * (GG * DH);
    const int g0 = wid * 16 + grp;
    #pragma unroll
    for (int nf = 0; nf < 8; nf++) {
        int d = (nf >> 1) * 16 + (nf & 1) * 8 + tid4 * 2;
        tokp[base + (size_t)g0 * DH + d]           = acc[nf][0];
        tokp[base + (size_t)g0 * DH + d + 1]       = acc[nf][1];
        tokp[base + (size_t)(g0 + 8) * DH + d]     = acc[nf][2];
        tokp[base + (size_t)(g0 + 8) * DH + d + 1] = acc[nf][3];
    }
    if (tid4 == 0) {
        size_t nb = ((size_t)split * (BB * HEADS) + bh) * GG;
        normp[nb + g0]     = accn[0];
        normp[nb + g0 + 8] = accn[2];
    }
}

// ---------------- K3b: deterministic split reduction ----------------
__global__ void split_reduce_kernel(const float* __restrict__ tokp,
                                    const float* __restrict__ normp,
                                    float* __restrict__ tok,
                                    float* __restrict__ norm) {
    const int blk = blockIdx.x;
    const int tid = threadIdx.x;
    if (blk < 256) {
        int idx = blk * 256 + tid;
        float s = 0.f;
        #pragma unroll 8
        for (int sp = 0; sp < SPLITS; sp++)
            s += tokp[(size_t)sp * 65536 + idx];
        tok[idx] = s;
    } else {
        int idx = (blk - 256) * 256 + tid;
        float s = 0.f;
        #pragma unroll 8
        for (int sp = 0; sp < SPLITS; sp++)
            s += normp[(size_t)sp * 1024 + idx];
        norm[idx] = s;
    }
}

// ---------------- K4: tiny attention per (b,h), emits Mt bf16 hi/lo ----------------
__global__ void attn_kernel(const float* __restrict__ tok,
                            const float* __restrict__ norm,
                            const float* __restrict__ Wq,
                            const float* __restrict__ Wk,
                            const float* __restrict__ Wv,
                            const float* __restrict__ Wout,
                            __nv_bfloat16* __restrict__ Mthi,
                            __nv_bfloat16* __restrict__ Mtlo) {
    const int bh = blockIdx.x;
    const int b = bh >> 3, h = bh & 7;
    const int tx = threadIdx.x, ty = threadIdx.y;
    const int tid = ty * 16 + tx;

    __shared__ float A[64][65];
    __shared__ float Bm[64][65];
    __shared__ float Cm[64][65];

    #pragma unroll
    for (int e = 0; e < 16; e++) {
        int idx = tid + e * 256;
        int g = idx >> 6, d = idx & 63;
        A[g][d] = tok[(size_t)bh * 4096 + idx] / (norm[bh * 64 + g] + 1e-5f);
    }
    __syncthreads();

    {
        float aq[4][4] = {}, ak[4][4] = {};
        #pragma unroll
        for (int kk = 0; kk < 64; kk++) {
            float a[4];
            #pragma unroll
            for (int i = 0; i < 4; i++) a[i] = A[ty + 16 * i][kk];
            #pragma unroll
            for (int j = 0; j < 4; j++) {
                float wq = __ldg(&Wq[(tx + 16 * j) * 64 + kk]);
                float wk = __ldg(&Wk[(tx + 16 * j) * 64 + kk]);
                #pragma unroll
                for (int i = 0; i < 4; i++) {
                    aq[i][j] += a[i] * wq;
                    ak[i][j] += a[i] * wk;
                }
            }
        }
        #pragma unroll
        for (int i = 0; i < 4; i++)
            #pragma unroll
            for (int j = 0; j < 4; j++) {
                Bm[ty + 16 * i][tx + 16 * j] = aq[i][j];
                Cm[ty + 16 * i][tx + 16 * j] = ak[i][j];
            }
    }
    __syncthreads();

    {
        float L[4][4] = {};
        #pragma unroll
        for (int kk = 0; kk < 64; kk++) {
            float a[4], bv[4];
            #pragma unroll
            for (int i = 0; i < 4; i++) a[i] = Bm[ty + 16 * i][kk];
            #pragma unroll
            for (int j = 0; j < 4; j++) bv[j] = Cm[tx + 16 * j][kk];
            #pragma unroll
            for (int i = 0; i < 4; i++)
                #pragma unroll
                for (int j = 0; j < 4; j++)
                    L[i][j] += a[i] * bv[j];
        }
        #pragma unroll
        for (int i = 0; i < 4; i++) {
            #pragma unroll
            for (int j = 0; j < 4; j++) L[i][j] *= 0.125f;
            float mx = L[i][0];
            #pragma unroll
            for (int j = 1; j < 4; j++) mx = fmaxf(mx, L[i][j]);
            #pragma unroll
            for (int o = 1; o < 16; o <<= 1)
                mx = fmaxf(mx, __shfl_xor_sync(0xffffffffu, mx, o, 16));
            float s = 0.f;
            #pragma unroll
            for (int j = 0; j < 4; j++) { L[i][j] = __expf(L[i][j] - mx); s += L[i][j]; }
            #pragma unroll
            for (int o = 1; o < 16; o <<= 1)
                s += __shfl_xor_sync(0xffffffffu, s, o, 16);
            float inv = 1.0f / s;
            #pragma unroll
            for (int j = 0; j < 4; j++)
                A[ty + 16 * i][tx + 16 * j] = L[i][j] * inv;
        }
    }
    __syncthreads();

    #pragma unroll
    for (int e = 0; e < 16; e++) {
        int idx = tid + e * 256;
        int g = idx >> 6;
        Bm[g][idx & 63] = tok[(size_t)bh * 4096 + idx] / (norm[bh * 64 + g] + 1e-5f);
    }
    __syncthreads();

    {
        float av[4][4] = {};
        #pragma unroll
        for (int kk = 0; kk < 64; kk++) {
            float a[4];
            #pragma unroll
            for (int i = 0; i < 4; i++) a[i] = Bm[ty + 16 * i][kk];
            #pragma unroll
            for (int j = 0; j < 4; j++) {
                float wv = __ldg(&Wv[(tx + 16 * j) * 64 + kk]);
                #pragma unroll
                for (int i = 0; i < 4; i++) av[i][j] += a[i] * wv;
            }
        }
        __syncthreads();
        #pragma unroll
        for (int i = 0; i < 4; i++)
            #pragma unroll
            for (int j = 0; j < 4; j++)
                Cm[ty + 16 * i][tx + 16 * j] = av[i][j];
    }
    __syncthreads();

    {
        float ao[4][4] = {};
        #pragma unroll
        for (int kk = 0; kk < 64; kk++) {
            float a[4], bv[4];
            #pragma unroll
            for (int i = 0; i < 4; i++) a[i] = A[ty + 16 * i][kk];
            #pragma unroll
            for (int j = 0; j < 4; j++) bv[j] = Cm[kk][tx + 16 * j];
            #pragma unroll
            for (int i = 0; i < 4; i++)
                #pragma unroll
                for (int j = 0; j < 4; j++)
                    ao[i][j] += a[i] * bv[j];
        }
        __syncthreads();
        #pragma unroll
        for (int i = 0; i < 4; i++)
            #pragma unroll
            for (int j = 0; j < 4; j++)
                Bm[ty + 16 * i][tx + 16 * j] = ao[i][j];
    }
    __syncthreads();

    {
        float am[4][8] = {};
        #pragma unroll
        for (int kk = 0; kk < 64; kk++) {
            float a[4];
            #pragma unroll
            for (int i = 0; i < 4; i++) a[i] = Bm[ty + 16 * i][kk];
            #pragma unroll
            for (int j = 0; j < 8; j++) {
                float wv = __ldg(&Wout[(size_t)(tx + 16 * j) * INNER + h * DH + kk]);
                #pragma unroll
                for (int i = 0; i < 4; i++) am[i][j] += a[i] * wv;
            }
        }
        #pragma unroll
        for (int i = 0; i < 4; i++) {
            int g = ty + 16 * i;
            #pragma unroll
            for (int j = 0; j < 8; j++) {
                int o = tx + 16 * j;
                float v = am[i][j];
                __nv_bfloat16 hv = __float2bfloat16(v);
                float r = v - __bfloat162float(hv);
                size_t idx = ((size_t)b * CC + o) * INNER + h * DH + g;
                Mthi[idx] = hv;
                Mtlo[idx] = __float2bfloat16(r);
            }
        }
    }
}

// ---------------- K5: fused scatter + projection on tensor cores ----------------
__global__ __launch_bounds__(256)
void final_mma_kernel(const __nv_bfloat16* __restrict__ Whi,
                      const __nv_bfloat16* __restrict__ Wlo,
                      const __nv_bfloat16* __restrict__ Mthi,
                      const __nv_bfloat16* __restrict__ Mtlo,
                      const float* __restrict__ bout,
                      float* __restrict__ out)
{
    extern __shared__ uint32_t smem_u32[];

    const int pt = blockIdx.x;
    const int b  = pt >> 9;
    const int n0 = (pt & 511) * 128;

    const int tid  = threadIdx.x;
    const int wid  = tid >> 5;
    const int lane = tid & 31;
    const int grp  = lane >> 2;
    const int tid4 = lane & 3;
    const int wm   = wid & 1;
    const int wn   = wid >> 1;

    float acc[4][4][4];
    #pragma unroll
    for (int i = 0; i < 4; i++)
        #pragma unroll
        for (int j = 0; j < 4; j++)
            #pragma unroll
            for (int r = 0; r < 4; r++) acc[i][j][r] = 0.f;

    uint32_t sbase = (uint32_t)__cvta_generic_to_shared(smem_u32);

    auto load_fin = [&](uint32_t sb, int it) {
        const int h  = it >> 1;
        const int g0 = (it & 1) * 32;
        #pragma unroll
        for (int j = 0; j < 8; j++) {
            int id  = tid + j * 256;
            int arr = id >> 9;
            int c   = id & 511;
            int row = c >> 2;
            int c4  = c & 3;
            uint32_t woff = (uint32_t)row * 16 + ((c4 ^ (row & 3)) << 2);
            uint32_t saddr = sb + (arr * 2048 + woff) * 4;
            const __nv_bfloat16* g;
            if (arr < 2) {
                size_t off = (((size_t)(b * HEADS + h) * NN) + n0 + row) * GG + g0 + c4 * 8;
                g = (arr == 0 ? Whi : Wlo) + off;
            } else {
                size_t off = ((size_t)b * CC + row) * INNER + h * DH + g0 + c4 * 8;
                g = (arr == 2 ? Mthi : Mtlo) + off;
            }
            cp16(saddr, g, true);
        }
    };

    load_fin(sbase, 0);
    asm volatile("cp.async.commit_group;\n" ::: "memory");

    for (int it = 0; it < 16; ++it) {
        const int cur = it & 1;
        if (it + 1 < 16) {
            load_fin(sbase + (uint32_t)(1 - cur) * 32768, it + 1);
            asm volatile("cp.async.commit_group;\n" ::: "memory");
            asm volatile("cp.async.wait_group 1;\n" ::: "memory");
        } else {
            asm volatile("cp.async.wait_group 0;\n" ::: "memory");
        }
        __syncthreads();

        const uint32_t* Ahi = smem_u32 + (size_t)cur * 8192;
        const uint32_t* Alo = Ahi + 2048;
        const uint32_t* Bhi = Ahi + 4096;
        const uint32_t* Blo = Ahi + 6144;

        #pragma unroll
        for (int s = 0; s < 2; s++) {
            const int kwb = s * 8;
            uint32_t ah[4][4], al[4][4];
            #pragma unroll
            for (int mi = 0; mi < 4; mi++) {
                int r0 = wm * 64 + mi * 16 + grp;
                ah[mi][0] = lds_frag(Ahi, r0,     kwb + tid4);
                ah[mi][1] = lds_frag(Ahi, r0 + 8, kwb + tid4);
                ah[mi][2] = lds_frag(Ahi, r0,     kwb + tid4 + 4);
                ah[mi][3] = lds_frag(Ahi, r0 + 8, kwb + tid4 + 4);
                al[mi][0] = lds_frag(Alo, r0,     kwb + tid4);
                al[mi][1] = lds_frag(Alo, r0 + 8, kwb + tid4);
                al[mi][2] = lds_frag(Alo, r0,     kwb + tid4 + 4);
                al[mi][3] = lds_frag(Alo, r0 + 8, kwb + tid4 + 4);
            }
            uint32_t bh[4][2], bl[4][2];
            #pragma unroll
            for (int ni = 0; ni < 4; ni++) {
                int r0 = wn * 32 + ni * 8 + grp;
                bh[ni][0] = lds_frag(Bhi, r0, kwb + tid4);
                bh[ni][1] = lds_frag(Bhi, r0, kwb + tid4 + 4);
                bl[ni][0] = lds_frag(Blo, r0, kwb + tid4);
                bl[ni][1] = lds_frag(Blo, r0, kwb + tid4 + 4);
            }
            #pragma unroll
            for (int mi = 0; mi < 4; mi++)
                #pragma unroll
                for (int ni = 0; ni < 4; ni++)
                    mma_bf16(acc[mi][ni], ah[mi][0], ah[mi][1], ah[mi][2], ah[mi][3],
                             bh[ni][0], bh[ni][1]);
            #pragma unroll
            for (int mi = 0; mi < 4; mi++)
                #pragma unroll
                for (int ni = 0; ni < 4; ni++)
                    mma_bf16(acc[mi][ni], ah[mi][0], ah[mi][1], ah[mi][2], ah[mi][3],
                             bl[ni][0], bl[ni][1]);
            #pragma unroll
            for (int mi = 0; mi < 4; mi++)
                #pragma unroll
                for (int ni = 0; ni < 4; ni++)
                    mma_bf16(acc[mi][ni], al[mi][0], al[mi][1], al[mi][2], al[mi][3],
                             bh[ni][0], bh[ni][1]);
        }
        __syncthreads();
    }

    #pragma unroll
    for (int mi = 0; mi < 4; mi++) {
        int row = wm * 64 + mi * 16 + grp;
        int n  = n0 + row;
        #pragma unroll
        for (int ni = 0; ni < 4; ni++) {
            int oc = wn * 32 + ni * 8 + tid4 * 2;
            float b0v = bout[oc], b1v = bout[oc + 1];
            size_t base0 = ((size_t)b * NN + n) * CC + oc;
            out[base0]     = acc[mi][ni][0] + b0v;
            out[base0 + 1] = acc[mi][ni][1] + b1v;
            size_t base1 = ((size_t)b * NN + n + 8) * CC + oc;
            out[base1]     = acc[mi][ni][2] + b0v;
            out[base1 + 1] = acc[mi][ni][3] + b1v;
        }
    }
}

// ---------------- launch ----------------
extern "C" void kernel_launch(void* const* d_in, const int* in_sizes, int n_in,
                              void* d_out, int out_size) {
    const float* x     = (const float*)d_in[0];
    const float* Wfx   = (const float*)d_in[1];
    const float* bfx   = (const float*)d_in[2];
    const float* Wx    = (const float*)d_in[3];
    const float* bx    = (const float*)d_in[4];
    const float* Wsl   = (const float*)d_in[5];
    const float* bsl   = (const float*)d_in[6];
    const float* temp  = (const float*)d_in[7];
    const float* Wq    = (const float*)d_in[8];
    const float* Wk    = (const float*)d_in[9];
    const float* Wv    = (const float*)d_in[10];
    const float* Wout  = (const float*)d_in[11];
    const float* bout  = (const float*)d_in[12];
    float* out = (float*)d_out;

    float *p_tokp, *p_normp, *p_tok, *p_norm, *p_lb;
    __nv_bfloat16 *p_xhi, *p_xlo, *p_whi, *p_wlo;
    __nv_bfloat16 *p_fxhi, *p_fxlo;
    __nv_bfloat16 *p_swhi, *p_swlo, *p_Mthi, *p_Mtlo;
    cudaGetSymbolAddress((void**)&p_tokp, g_tokp);
    cudaGetSymbolAddress((void**)&p_normp, g_normp);
    cudaGetSymbolAddress((void**)&p_tok, g_tok);
    cudaGetSymbolAddress((void**)&p_norm, g_norm);
    cudaGetSymbolAddress((void**)&p_lb, g_lbias);
    cudaGetSymbolAddress((void**)&p_xhi, g_xhi);
    cudaGetSymbolAddress((void**)&p_xlo, g_xlo);
    cudaGetSymbolAddress((void**)&p_whi, g_whi);
    cudaGetSymbolAddress((void**)&p_wlo, g_wlo);
    cudaGetSymbolAddress((void**)&p_fxhi, g_fxhi);
    cudaGetSymbolAddress((void**)&p_fxlo, g_fxlo);
    cudaGetSymbolAddress((void**)&p_swhi, g_swhi);
    cudaGetSymbolAddress((void**)&p_swlo, g_swlo);
    cudaGetSymbolAddress((void**)&p_Mthi, g_Mthi);
    cudaGetSymbolAddress((void**)&p_Mtlo, g_Mtlo);

    static bool attr_set = false;
    if (!attr_set) {
        cudaFuncSetAttribute(conv_mma_kernel,
                             cudaFuncAttributeMaxDynamicSharedMemorySize, 2 * CSTAGE);
        cudaFuncSetAttribute(final_mma_kernel,
                             cudaFuncAttributeMaxDynamicSharedMemorySize, 65536);
        attr_set = true;
    }

    dim3 blk(16, 16);

    // 0. staging: x split, fx weights split, combined logit weights, logit bias
    split_x_kernel<<<(BB * NN * CC) / 256, 256>>>(x, p_xhi, p_xlo);
    split_w_kernel<<<(512 * KTOT) / 256, 256>>>(Wfx, p_whi, p_wlo);
    combine_w_kernel<<<dim3(512, 9), 128>>>(Wx, Wsl, temp, p_whi, p_wlo);
    lbias_kernel<<<512, 32>>>(bx, Wsl, bsl, temp, p_lb);

    // 1. fused conv (R7 proven config, 256 threads): fx bf16 hi/lo + softmax
    conv_mma_kernel<<<dim3(4, 512, BB), 256, 2 * CSTAGE>>>(
        p_xhi, p_xlo, p_whi, p_wlo, bfx, p_lb, p_fxhi, p_fxlo, p_swhi, p_swlo);

    // 2. slice token reduction on tensor cores + split reduce
    token_mma_kernel<<<dim3(SPLITS, BB * HEADS), 128>>>(
        p_swhi, p_swlo, p_fxhi, p_fxlo, p_tokp, p_normp);
    split_reduce_kernel<<<260, 256>>>(p_tokp, p_normp, p_tok, p_norm);

    // 3. tiny attention + fused Wout fold -> Mt (bf16 hi/lo)
    attn_kernel<<<BB * HEADS, blk>>>(p_tok, p_norm, Wq, Wk, Wv, Wout, p_Mthi, p_Mtlo);

    // 4. fused scatter + projection on tensor cores
    final_mma_kernel<<<1024, 256, 65536>>>(p_swhi, p_swlo, p_Mthi, p_Mtlo, bout, out);
}

// round 10
// speedup vs baseline: 1.1364x; 1.0165x over previous
#include <cuda_runtime.h>
#include <cuda_bf16.h>
#include <math.h>
#include <stdint.h>

// Problem constants
#define BB 2
#define HH 256
#define WW 256
#define NN 65536          // H*W
#define CC 128
#define HEADS 8
#define DH 64             // dim_head
#define GG 64             // SLICE
#define INNER 512         // HEADS*DH
#define SPLITS 64         // split-K for token reduction
#define CHUNK 1024        // tokens per split (NN/SPLITS)
#define KTOT 1152         // 9 taps * 128 channels

// ---------------- device scratch (static, no allocs) ----------------
__device__ float g_tokp[(size_t)SPLITS * BB * HEADS * GG * DH];
__device__ float g_normp[(size_t)SPLITS * BB * HEADS * GG];
__device__ float g_tok [(size_t)BB * HEADS * GG * DH];
__device__ float g_norm[(size_t)BB * HEADS * GG];
__device__ float g_lbias[INNER];                     // (bx·Wslice + bslice)/temp

// fx_mid as bf16 hi/lo pair  [b][n][inner]
__device__ __align__(16) __nv_bfloat16 g_fxhi[(size_t)BB * NN * INNER];
__device__ __align__(16) __nv_bfloat16 g_fxlo[(size_t)BB * NN * INNER];
// slice weights as bf16 hi/lo pair  [bh][n][g]
__device__ __align__(16) __nv_bfloat16 g_swhi[(size_t)BB * HEADS * NN * GG];
__device__ __align__(16) __nv_bfloat16 g_swlo[(size_t)BB * HEADS * NN * GG];
// Mt = (out_slice · Wout^T) transposed: [b][o][h*64+g], bf16 hi/lo
__device__ __align__(16) __nv_bfloat16 g_Mthi[(size_t)BB * CC * INNER];
__device__ __align__(16) __nv_bfloat16 g_Mtlo[(size_t)BB * CC * INNER];

// bf16 3-split staging for conv
__device__ __align__(16) __nv_bfloat16 g_xhi[(size_t)BB * NN * CC];
__device__ __align__(16) __nv_bfloat16 g_xlo[(size_t)BB * NN * CC];
// rows 0..511: Wfx cols; rows 512..1023: combined logit weights (Wx·Wslice/temp)
__device__ __align__(16) __nv_bfloat16 g_whi[(size_t)1024 * KTOT];
__device__ __align__(16) __nv_bfloat16 g_wlo[(size_t)1024 * KTOT];

// ---------------- prep kernels ----------------
__global__ void split_x_kernel(const float* __restrict__ x,
                               __nv_bfloat16* __restrict__ xhi,
                               __nv_bfloat16* __restrict__ xlo) {
    size_t i = (size_t)blockIdx.x * 256 + threadIdx.x;
    float f = x[i];
    __nv_bfloat16 h = __float2bfloat16(f);
    float r = f - __bfloat162float(h);
    xhi[i] = h;
    xlo[i] = __float2bfloat16(r);
}

// Wfx (fx conv weights) -> rows 0..511 of g_whi/g_wlo, transposed [oc][k]
__global__ void split_w_kernel(const float* __restrict__ Wfx,
                               __nv_bfloat16* __restrict__ whi,
                               __nv_bfloat16* __restrict__ wlo) {
    int i = blockIdx.x * 256 + threadIdx.x;   // 512*1152 total
    int oc = i / KTOT;
    int k  = i - oc * KTOT;
    float f = Wfx[(size_t)k * 512 + oc];
    __nv_bfloat16 h = __float2bfloat16(f);
    float r = f - __bfloat162float(h);
    whi[i] = h;
    wlo[i] = __float2bfloat16(r);
}

// y<9:  W~[k][h*64+g] = (sum_d Wx[k][h*64+d]*Wslice[g][d]) / temp_h -> rows 512..1023
// y==9: lbias[h*64+g] = (bx_h · Wslice_g + bslice_g) / temp_h
__global__ void combine_w_kernel(const float* __restrict__ Wx,
                                 const float* __restrict__ Wsl,
                                 const float* __restrict__ bx,
                                 const float* __restrict__ bsl,
                                 const float* __restrict__ temp,
                                 __nv_bfloat16* __restrict__ whi,
                                 __nv_bfloat16* __restrict__ wlo,
                                 float* __restrict__ lb) {
    __shared__ float ws[64];
    const int col = blockIdx.x;          // 0..511
    const int h = col >> 6, g = col & 63;
    const int tid = threadIdx.x;         // 128
    if (tid < 64) ws[tid] = Wsl[g * 64 + tid];
    __syncthreads();
    float t = fminf(fmaxf(temp[h], 0.1f), 5.0f);
    float invt = 1.0f / t;

    if (blockIdx.y == 9) {
        if (tid < 32) {
            float s = bx[h * 64 + tid] * ws[tid]
                    + bx[h * 64 + 32 + tid] * ws[32 + tid];
            #pragma unroll
            for (int o = 16; o > 0; o >>= 1)
                s += __shfl_xor_sync(0xffffffffu, s, o);
            if (tid == 0) lb[col] = (s + bsl[g]) * invt;
        }
        return;
    }

    int k = blockIdx.y * 128 + tid;      // 9 y-blocks -> 0..1151
    const float* wr = Wx + (size_t)k * 512 + h * 64;
    float s = 0.f;
    #pragma unroll 8
    for (int d = 0; d < 64; d++) s += wr[d] * ws[d];
    s *= invt;
    __nv_bfloat16 hv = __float2bfloat16(s);
    size_t o = (size_t)(512 + col) * KTOT + k;
    whi[o] = hv;
    wlo[o] = __float2bfloat16(s - __bfloat162float(hv));
}

// ---------------- shared MMA plumbing ----------------
__device__ __forceinline__ void cp16(uint32_t saddr, const void* g, bool valid) {
    int sz = valid ? 16 : 0;
    asm volatile("cp.async.cg.shared.global [%0], [%1], 16, %2;\n"
                 :: "r"(saddr), "l"(g), "r"(sz));
}

__device__ __forceinline__ void mma_bf16(float c[4], uint32_t a0, uint32_t a1,
                                         uint32_t a2, uint32_t a3,
                                         uint32_t b0, uint32_t b1) {
    asm volatile(
        "mma.sync.aligned.m16n8k16.row.col.f32.bf16.bf16.f32 "
        "{%0,%1,%2,%3}, {%4,%5,%6,%7}, {%8,%9}, {%0,%1,%2,%3};"
        : "+f"(c[0]), "+f"(c[1]), "+f"(c[2]), "+f"(c[3])
        : "r"(a0), "r"(a1), "r"(a2), "r"(a3), "r"(b0), "r"(b1));
}

__device__ __forceinline__ void ldsm4(uint32_t r[4], uint32_t addr) {
    asm volatile("ldmatrix.sync.aligned.m8n8.x4.shared.b16 {%0,%1,%2,%3}, [%4];"
                 : "=r"(r[0]), "=r"(r[1]), "=r"(r[2]), "=r"(r[3]) : "r"(addr));
}

__device__ __forceinline__ void ldsm4t(uint32_t r[4], uint32_t addr) {
    asm volatile("ldmatrix.sync.aligned.m8n8.x4.trans.shared.b16 {%0,%1,%2,%3}, [%4];"
                 : "=r"(r[0]), "=r"(r[1]), "=r"(r[2]), "=r"(r[3]) : "r"(addr));
}

// ---------------- conv: implicit GEMM 128x256, kc=64, ldmatrix feed (R7 config) ----------------
// ocb 0..1: fx output (bf16 hi/lo, cols ocb*256..+255); ocb 2..3: slice-weight softmax.
// Stage (96KB): Ahi 16K | Alo 16K | Bhi 32K | Blo 32K.
#define CSTAGE 98304

__device__ __forceinline__ void conv_load(
    uint32_t st,
    const __nv_bfloat16* __restrict__ Xhi, const __nv_bfloat16* __restrict__ Xlo,
    const __nv_bfloat16* __restrict__ Whi, const __nv_bfloat16* __restrict__ Wlo,
    int it, int b, int hrow, int w0, int ocb, int tid)
{
    const int kg  = it * 64;
    const int tap = kg >> 7;
    const int dy = tap / 3 - 1, dx = tap % 3 - 1;
    const int c0 = kg & 127;            // 0 or 64
    const int hp = hrow + dy;
    const bool hok = (hp >= 0) && (hp < HH);
    const int hpc = hok ? hp : 0;

    #pragma unroll
    for (int j = 0; j < 8; j++) {
        int id  = tid + j * 256;
        int arr = id >> 10;             // 0:Ahi 1:Alo
        int l   = id & 1023;
        int row = l >> 3;
        int gr  = l & 7;
        uint32_t saddr = st + arr * 16384 + row * 128 + ((gr ^ (row & 7)) << 4);
        int wp = w0 + row + dx;
        bool valid = hok && (wp >= 0) && (wp < WW);
        int wpc = valid ? wp : 0;
        const __nv_bfloat16* g = (arr == 0 ? Xhi : Xlo) +
            (((size_t)b * NN + (size_t)hpc * WW + wpc) * CC + c0 + gr * 8);
        cp16(saddr, g, valid);
    }
    #pragma unroll
    for (int j = 8; j < 24; j++) {
        int id  = tid + (j - 8) * 256;  // 0..4095
        int arr = id >> 11;             // 0:Bhi 1:Blo
        int l   = id & 2047;
        int row = l >> 3;
        int gr  = l & 7;
        uint32_t saddr = st + 32768 + arr * 32768 + row * 128 + ((gr ^ (row & 7)) << 4);
        const __nv_bfloat16* g = (arr == 0 ? Whi : Wlo) +
            ((size_t)(ocb * 256 + row) * KTOT + kg + gr * 8);
        cp16(saddr, g, true);
    }
}

__global__ __launch_bounds__(256, 1)
void conv_mma_kernel(const __nv_bfloat16* __restrict__ Xhi,
                     const __nv_bfloat16* __restrict__ Xlo,
                     const __nv_bfloat16* __restrict__ Whi,
                     const __nv_bfloat16* __restrict__ Wlo,
                     const float* __restrict__ bfx,
                     const float* __restrict__ lbias,
                     __nv_bfloat16* __restrict__ fxhi,
                     __nv_bfloat16* __restrict__ fxlo,
                     __nv_bfloat16* __restrict__ swhi,
                     __nv_bfloat16* __restrict__ swlo)
{
    extern __shared__ char smem[];           // 2 stages x 96KB

    const int ocb = blockIdx.x;              // 0..3
    const int pt  = blockIdx.y;              // 0..511
    const int b   = blockIdx.z;
    const int n0  = pt * 128;
    const int hrow = n0 >> 8;
    const int w0   = n0 & 255;

    const int tid  = threadIdx.x;
    const int wid  = tid >> 5;
    const int lane = tid & 31;
    const int grp  = lane >> 2;
    const int tid4 = lane & 3;
    const int wm   = wid & 1;                // 2 row-groups of 64
    const int wn   = wid >> 1;               // 4 col-groups of 64

    const int t8   = lane >> 3;
    const int r8   = lane & 7;
    const int a_roff = ((t8 & 1) << 3) + r8;
    const int a_gsel = t8 >> 1;
    const int b_roff = ((t8 >> 1) << 3) + r8;
    const int b_gsel = t8 & 1;

    float acc[4][8][4];
    #pragma unroll
    for (int i = 0; i < 4; i++)
        #pragma unroll
        for (int j = 0; j < 8; j++)
            #pragma unroll
            for (int r = 0; r < 4; r++) acc[i][j][r] = 0.f;

    uint32_t sbase = (uint32_t)__cvta_generic_to_shared(smem);

    conv_load(sbase, Xhi, Xlo, Whi, Wlo, 0, b, hrow, w0, ocb, tid);
    asm volatile("cp.async.commit_group;\n" ::: "memory");

    for (int it = 0; it < 18; ++it) {
        const int cur = it & 1;
        if (it + 1 < 18) {
            conv_load(sbase + (uint32_t)(1 - cur) * CSTAGE,
                      Xhi, Xlo, Whi, Wlo, it + 1, b, hrow, w0, ocb, tid);
            asm volatile("cp.async.commit_group;\n" ::: "memory");
            asm volatile("cp.async.wait_group 1;\n" ::: "memory");
        } else {
            asm volatile("cp.async.wait_group 0;\n" ::: "memory");
        }
        __syncthreads();

        const uint32_t stA = sbase + (uint32_t)cur * CSTAGE;
        const uint32_t stB = stA + 32768;

        #pragma unroll
        for (int s = 0; s < 4; s++) {
            uint32_t ah[4][4], al[4][4];
            #pragma unroll
            for (int mi = 0; mi < 4; mi++) {
                int row = wm * 64 + mi * 16 + a_roff;
                int g = 2 * s + a_gsel;
                uint32_t addr = stA + row * 128 + ((g ^ (row & 7)) << 4);
                ldsm4(ah[mi], addr);
                ldsm4(al[mi], addr + 16384);
            }
            #pragma unroll
            for (int np = 0; np < 4; np++) {
                int row = wn * 64 + np * 16 + b_roff;
                int g = 2 * s + b_gsel;
                uint32_t addr = stB + row * 128 + ((g ^ (row & 7)) << 4);
                uint32_t bh[4], bl[4];
                ldsm4(bh, addr);
                ldsm4(bl, addr + 32768);
                #pragma unroll
                for (int mi = 0; mi < 4; mi++) {
                    mma_bf16(acc[mi][2 * np],     ah[mi][0], ah[mi][1], ah[mi][2], ah[mi][3], bh[0], bh[1]);
                    mma_bf16(acc[mi][2 * np + 1], ah[mi][0], ah[mi][1], ah[mi][2], ah[mi][3], bh[2], bh[3]);
                }
                #pragma unroll
                for (int mi = 0; mi < 4; mi++) {
                    mma_bf16(acc[mi][2 * np],     ah[mi][0], ah[mi][1], ah[mi][2], ah[mi][3], bl[0], bl[1]);
                    mma_bf16(acc[mi][2 * np + 1], ah[mi][0], ah[mi][1], ah[mi][2], ah[mi][3], bl[2], bl[3]);
                }
                #pragma unroll
                for (int mi = 0; mi < 4; mi++) {
                    mma_bf16(acc[mi][2 * np],     al[mi][0], al[mi][1], al[mi][2], al[mi][3], bh[0], bh[1]);
                    mma_bf16(acc[mi][2 * np + 1], al[mi][0], al[mi][1], al[mi][2], al[mi][3], bh[2], bh[3]);
                }
            }
        }
        __syncthreads();
    }

    if (ocb < 2) {
        // fx output: bf16 hi/lo pairs with bias
        const int ocbase = ocb * 256;
        #pragma unroll
        for (int mi = 0; mi < 4; mi++) {
            int row = wm * 64 + mi * 16 + grp;
            int n  = n0 + row;
            #pragma unroll
            for (int ni = 0; ni < 8; ni++) {
                int col = wn * 64 + ni * 8 + tid4 * 2;
                int oc  = ocbase + col;
                float b0v = bfx[oc], b1v = bfx[oc + 1];
                float v0 = acc[mi][ni][0] + b0v;
                float v1 = acc[mi][ni][1] + b1v;
                float v2 = acc[mi][ni][2] + b0v;
                float v3 = acc[mi][ni][3] + b1v;
                __nv_bfloat16 h0 = __float2bfloat16(v0), h1 = __float2bfloat16(v1);
                __nv_bfloat16 h2 = __float2bfloat16(v2), h3 = __float2bfloat16(v3);
                __nv_bfloat162 ph0; ph0.x = h0; ph0.y = h1;
                __nv_bfloat162 pl0; pl0.x = __float2bfloat16(v0 - __bfloat162float(h0));
                                    pl0.y = __float2bfloat16(v1 - __bfloat162float(h1));
                __nv_bfloat162 ph1; ph1.x = h2; ph1.y = h3;
                __nv_bfloat162 pl1; pl1.x = __float2bfloat16(v2 - __bfloat162float(h2));
                                    pl1.y = __float2bfloat16(v3 - __bfloat162float(h3));
                size_t base0 = ((size_t)b * NN + n) * INNER + oc;
                size_t base1 = ((size_t)b * NN + n + 8) * INNER + oc;
                *(__nv_bfloat162*)(fxhi + base0) = ph0;
                *(__nv_bfloat162*)(fxlo + base0) = pl0;
                *(__nv_bfloat162*)(fxhi + base1) = ph1;
                *(__nv_bfloat162*)(fxlo + base1) = pl1;
            }
        }
    } else {
        // logits: stage to smem, softmax per (pixel, head), emit bf16 hi/lo
        float* sred = (float*)smem;          // [128][260]
        #pragma unroll
        for (int mi = 0; mi < 4; mi++) {
            int row = wm * 64 + mi * 16 + grp;
            #pragma unroll
            for (int ni = 0; ni < 8; ni++) {
                int col = wn * 64 + ni * 8 + tid4 * 2;
                sred[row * 260 + col]           = acc[mi][ni][0];
                sred[row * 260 + col + 1]       = acc[mi][ni][1];
                sred[(row + 8) * 260 + col]     = acc[mi][ni][2];
                sred[(row + 8) * 260 + col + 1] = acc[mi][ni][3];
            }
        }
        __syncthreads();

        #pragma unroll
        for (int pass = 0; pass < 2; pass++) {
            int tsk = tid + pass * 256;      // 0..511
            int row  = tsk >> 2;
            int hloc = tsk & 3;
            int h = (ocb - 2) * 4 + hloc;
            int n = n0 + row;
            const float* lb = lbias + h * 64;
            float* sr = sred + row * 260 + hloc * 64;

            float mx = -1e30f;
            #pragma unroll 8
            for (int g = 0; g < 64; g++) mx = fmaxf(mx, sr[g] + lb[g]);
            float ssum = 0.f;
            #pragma unroll 8
            for (int g = 0; g < 64; g++) {
                float e = __expf(sr[g] + lb[g] - mx);
                ssum += e;
                sr[g] = e;
            }
            float inv = 1.0f / ssum;

            size_t base = ((size_t)(b * HEADS + h) * NN + n) * GG;
            #pragma unroll
            for (int c = 0; c < 8; c++) {
                union { __nv_bfloat16 hb[8]; uint4 u; } Uh, Ul;
                #pragma unroll
                for (int e = 0; e < 8; e++) {
                    float v = sr[c * 8 + e] * inv;
                    __nv_bfloat16 hv = __float2bfloat16(v);
                    Uh.hb[e] = hv;
                    Ul.hb[e] = __float2bfloat16(v - __bfloat162float(hv));
                }
                ((uint4*)(swhi + base))[c] = Uh.u;
                ((uint4*)(swlo + base))[c] = Ul.u;
            }
        }
    }
}

// ---------------- K3: token reduction on tensor cores ----------------
__global__ __launch_bounds__(128)
void token_mma_kernel(const __nv_bfloat16* __restrict__ whi,
                      const __nv_bfloat16* __restrict__ wlo,
                      const __nv_bfloat16* __restrict__ fxhi,
                      const __nv_bfloat16* __restrict__ fxlo,
                      float* __restrict__ tokp,
                      float* __restrict__ normp)
{
    __shared__ __align__(16) char smem[2 * 8192];

    const int bh = blockIdx.y;
    const int b = bh >> 3, h = bh & 7;
    const int split = blockIdx.x;
    const int nbase = split * CHUNK;

    const int tid  = threadIdx.x;
    const int wid  = tid >> 5;          // 0..3: g-strip wid*16
    const int lane = tid & 31;
    const int grp  = lane >> 2;
    const int tid4 = lane & 3;
    const int t8   = lane >> 3;
    const int r8   = lane & 7;
    const int lrow = r8 + ((t8 >> 1) << 3);   // 0..15
    const int lgr  = t8 & 1;

    const uint32_t ONES = 0x3F803F80u;  // bf16(1.0) x2

    float acc[8][4];
    #pragma unroll
    for (int j = 0; j < 8; j++)
        #pragma unroll
        for (int r = 0; r < 4; r++) acc[j][r] = 0.f;
    float accn[4] = {};

    uint32_t sbase = (uint32_t)__cvta_generic_to_shared(smem);

    auto load = [&](uint32_t st, int t0) {
        #pragma unroll
        for (int j = 0; j < 4; j++) {
            int id  = tid + j * 128;
            int arr = id >> 7;          // 0:whi 1:wlo 2:fxhi 3:fxlo
            int l   = id & 127;
            int row = l >> 3;
            int gr  = l & 7;
            uint32_t saddr = st + arr * 2048 + row * 128 + ((gr ^ (row & 7)) << 4);
            int n = nbase + t0 + row;
            const __nv_bfloat16* g;
            if (arr < 2) {
                g = (arr == 0 ? whi : wlo) + ((size_t)bh * NN + n) * GG + gr * 8;
            } else {
                g = (arr == 2 ? fxhi : fxlo) +
                    ((size_t)b * NN + n) * INNER + h * DH + gr * 8;
            }
            cp16(saddr, g, true);
        }
    };

    load(sbase, 0);
    asm volatile("cp.async.commit_group;\n" ::: "memory");

    for (int it = 0; it < 64; ++it) {
        const int cur = it & 1;
        if (it + 1 < 64) {
            load(sbase + (uint32_t)(1 - cur) * 8192, (it + 1) * 16);
            asm volatile("cp.async.commit_group;\n" ::: "memory");
            asm volatile("cp.async.wait_group 1;\n" ::: "memory");
        } else {
            asm volatile("cp.async.wait_group 0;\n" ::: "memory");
        }
        __syncthreads();

        const uint32_t st = sbase + (uint32_t)cur * 8192;

        uint32_t awh[4], awl[4];
        {
            int gr = wid * 2 + lgr;
            uint32_t addr = st + lrow * 128 + ((gr ^ (lrow & 7)) << 4);
            ldsm4t(awh, addr);
            ldsm4t(awl, addr + 2048);
        }
        mma_bf16(accn, awh[0], awh[1], awh[2], awh[3], ONES, ONES);
        mma_bf16(accn, awl[0], awl[1], awl[2], awl[3], ONES, ONES);

        #pragma unroll
        for (int j = 0; j < 4; j++) {
            int gr = j * 2 + lgr;
            uint32_t addr = st + 4096 + lrow * 128 + ((gr ^ (lrow & 7)) << 4);
            uint32_t bfh[4], bfl[4];
            ldsm4t(bfh, addr);
            ldsm4t(bfl, addr + 2048);
            mma_bf16(acc[2 * j],     awh[0], awh[1], awh[2], awh[3], bfh[0], bfh[2]);
            mma_bf16(acc[2 * j + 1], awh[0], awh[1], awh[2], awh[3], bfh[1], bfh[3]);
            mma_bf16(acc[2 * j],     awh[0], awh[1], awh[2], awh[3], bfl[0], bfl[2]);
            mma_bf16(acc[2 * j + 1], awh[0], awh[1], awh[2], awh[3], bfl[1], bfl[3]);
            mma_bf16(acc[2 * j],     awl[0], awl[1], awl[2], awl[3], bfh[0], bfh[2]);
            mma_bf16(acc[2 * j + 1], awl[0], awl[1], awl[2], awl[3], bfh[1], bfh[3]);
        }
        __syncthreads();
    }

    const size_t base = ((size_t)split * (BB * HEADS) + bh) * (GG * DH);
    const int g0 = wid * 16 + grp;
    #pragma unroll
    for (int nf = 0; nf < 8; nf++) {
        int d = (nf >> 1) * 16 + (nf & 1) * 8 + tid4 * 2;
        tokp[base + (size_t)g0 * DH + d]           = acc[nf][0];
        tokp[base + (size_t)g0 * DH + d + 1]       = acc[nf][1];
        tokp[base + (size_t)(g0 + 8) * DH + d]     = acc[nf][2];
        tokp[base + (size_t)(g0 + 8) * DH + d + 1] = acc[nf][3];
    }
    if (tid4 == 0) {
        size_t nb = ((size_t)split * (BB * HEADS) + bh) * GG;
        normp[nb + g0]     = accn[0];
        normp[nb + g0 + 8] = accn[2];
    }
}

// ---------------- K3b: deterministic split reduction ----------------
__global__ void split_reduce_kernel(const float* __restrict__ tokp,
                                    const float* __restrict__ normp,
                                    float* __restrict__ tok,
                                    float* __restrict__ norm) {
    const int blk = blockIdx.x;
    const int tid = threadIdx.x;
    if (blk < 256) {
        int idx = blk * 256 + tid;
        float s = 0.f;
        #pragma unroll 8
        for (int sp = 0; sp < SPLITS; sp++)
            s += tokp[(size_t)sp * 65536 + idx];
        tok[idx] = s;
    } else {
        int idx = (blk - 256) * 256 + tid;
        float s = 0.f;
        #pragma unroll 8
        for (int sp = 0; sp < SPLITS; sp++)
            s += normp[(size_t)sp * 1024 + idx];
        norm[idx] = s;
    }
}

// ---------------- K4: tiny attention per (b,h), emits Mt bf16 hi/lo ----------------
__global__ void attn_kernel(const float* __restrict__ tok,
                            const float* __restrict__ norm,
                            const float* __restrict__ Wq,
                            const float* __restrict__ Wk,
                            const float* __restrict__ Wv,
                            const float* __restrict__ Wout,
                            __nv_bfloat16* __restrict__ Mthi,
                            __nv_bfloat16* __restrict__ Mtlo) {
    const int bh = blockIdx.x;
    const int b = bh >> 3, h = bh & 7;
    const int tx = threadIdx.x, ty = threadIdx.y;
    const int tid = ty * 16 + tx;

    __shared__ float A[64][65];
    __shared__ float Bm[64][65];
    __shared__ float Cm[64][65];

    #pragma unroll
    for (int e = 0; e < 16; e++) {
        int idx = tid + e * 256;
        int g = idx >> 6, d = idx & 63;
        A[g][d] = tok[(size_t)bh * 4096 + idx] / (norm[bh * 64 + g] + 1e-5f);
    }
    __syncthreads();

    {
        float aq[4][4] = {}, ak[4][4] = {};
        #pragma unroll
        for (int kk = 0; kk < 64; kk++) {
            float a[4];
            #pragma unroll
            for (int i = 0; i < 4; i++) a[i] = A[ty + 16 * i][kk];
            #pragma unroll
            for (int j = 0; j < 4; j++) {
                float wq = __ldg(&Wq[(tx + 16 * j) * 64 + kk]);
                float wk = __ldg(&Wk[(tx + 16 * j) * 64 + kk]);
                #pragma unroll
                for (int i = 0; i < 4; i++) {
                    aq[i][j] += a[i] * wq;
                    ak[i][j] += a[i] * wk;
                }
            }
        }
        #pragma unroll
        for (int i = 0; i < 4; i++)
            #pragma unroll
            for (int j = 0; j < 4; j++) {
                Bm[ty + 16 * i][tx + 16 * j] = aq[i][j];
                Cm[ty + 16 * i][tx + 16 * j] = ak[i][j];
            }
    }
    __syncthreads();

    {
        float L[4][4] = {};
        #pragma unroll
        for (int kk = 0; kk < 64; kk++) {
            float a[4], bv[4];
            #pragma unroll
            for (int i = 0; i < 4; i++) a[i] = Bm[ty + 16 * i][kk];
            #pragma unroll
            for (int j = 0; j < 4; j++) bv[j] = Cm[tx + 16 * j][kk];
            #pragma unroll
            for (int i = 0; i < 4; i++)
                #pragma unroll
                for (int j = 0; j < 4; j++)
                    L[i][j] += a[i] * bv[j];
        }
        #pragma unroll
        for (int i = 0; i < 4; i++) {
            #pragma unroll
            for (int j = 0; j < 4; j++) L[i][j] *= 0.125f;
            float mx = L[i][0];
            #pragma unroll
            for (int j = 1; j < 4; j++) mx = fmaxf(mx, L[i][j]);
            #pragma unroll
            for (int o = 1; o < 16; o <<= 1)
                mx = fmaxf(mx, __shfl_xor_sync(0xffffffffu, mx, o, 16));
            float s = 0.f;
            #pragma unroll
            for (int j = 0; j < 4; j++) { L[i][j] = __expf(L[i][j] - mx); s += L[i][j]; }
            #pragma unroll
            for (int o = 1; o < 16; o <<= 1)
                s += __shfl_xor_sync(0xffffffffu, s, o, 16);
            float inv = 1.0f / s;
            #pragma unroll
            for (int j = 0; j < 4; j++)
                A[ty + 16 * i][tx + 16 * j] = L[i][j] * inv;
        }
    }
    __syncthreads();

    #pragma unroll
    for (int e = 0; e < 16; e++) {
        int idx = tid + e * 256;
        int g = idx >> 6;
        Bm[g][idx & 63] = tok[(size_t)bh * 4096 + idx] / (norm[bh * 64 + g] + 1e-5f);
    }
    __syncthreads();

    {
        float av[4][4] = {};
        #pragma unroll
        for (int kk = 0; kk < 64; kk++) {
            float a[4];
            #pragma unroll
            for (int i = 0; i < 4; i++) a[i] = Bm[ty + 16 * i][kk];
            #pragma unroll
            for (int j = 0; j < 4; j++) {
                float wv = __ldg(&Wv[(tx + 16 * j) * 64 + kk]);
                #pragma unroll
                for (int i = 0; i < 4; i++) av[i][j] += a[i] * wv;
            }
        }
        __syncthreads();
        #pragma unroll
        for (int i = 0; i < 4; i++)
            #pragma unroll
            for (int j = 0; j < 4; j++)
                Cm[ty + 16 * i][tx + 16 * j] = av[i][j];
    }
    __syncthreads();

    {
        float ao[4][4] = {};
        #pragma unroll
        for (int kk = 0; kk < 64; kk++) {
            float a[4], bv[4];
            #pragma unroll
            for (int i = 0; i < 4; i++) a[i] = A[ty + 16 * i][kk];
            #pragma unroll
            for (int j = 0; j < 4; j++) bv[j] = Cm[kk][tx + 16 * j];
            #pragma unroll
            for (int i = 0; i < 4; i++)
                #pragma unroll
                for (int j = 0; j < 4; j++)
                    ao[i][j] += a[i] * bv[j];
        }
        __syncthreads();
        #pragma unroll
        for (int i = 0; i < 4; i++)
            #pragma unroll
            for (int j = 0; j < 4; j++)
                Bm[ty + 16 * i][tx + 16 * j] = ao[i][j];
    }
    __syncthreads();

    {
        float am[4][8] = {};
        #pragma unroll
        for (int kk = 0; kk < 64; kk++) {
            float a[4];
            #pragma unroll
            for (int i = 0; i < 4; i++) a[i] = Bm[ty + 16 * i][kk];
            #pragma unroll
            for (int j = 0; j < 8; j++) {
                float wv = __ldg(&Wout[(size_t)(tx + 16 * j) * INNER + h * DH + kk]);
                #pragma unroll
                for (int i = 0; i < 4; i++) am[i][j] += a[i] * wv;
            }
        }
        #pragma unroll
        for (int i = 0; i < 4; i++) {
            int g = ty + 16 * i;
            #pragma unroll
            for (int j = 0; j < 8; j++) {
                int o = tx + 16 * j;
                float v = am[i][j];
                __nv_bfloat16 hv = __float2bfloat16(v);
                float r = v - __bfloat162float(hv);
                size_t idx = ((size_t)b * CC + o) * INNER + h * DH + g;
                Mthi[idx] = hv;
                Mtlo[idx] = __float2bfloat16(r);
            }
        }
    }
}

// ---------------- K5: fused scatter + projection, kc=64, ldmatrix ----------------
// out[n][o] = bout[o] + sum_{h,g} w[bh][n][g] * Mt[b][o][h*64+g]
// Chunk it = head it (kc=64 = one head). Stage (64KB): whi 16K | wlo 16K | Mthi 16K | Mtlo 16K.
#define FSTAGE 65536

__global__ __launch_bounds__(256)
void final_mma_kernel(const __nv_bfloat16* __restrict__ Whi,
                      const __nv_bfloat16* __restrict__ Wlo,
                      const __nv_bfloat16* __restrict__ Mthi,
                      const __nv_bfloat16* __restrict__ Mtlo,
                      const float* __restrict__ bout,
                      float* __restrict__ out)
{
    extern __shared__ char smem[];

    const int pt = blockIdx.x;
    const int b  = pt >> 9;
    const int n0 = (pt & 511) * 128;

    const int tid  = threadIdx.x;
    const int wid  = tid >> 5;
    const int lane = tid & 31;
    const int grp  = lane >> 2;
    const int tid4 = lane & 3;
    const int wm   = wid & 1;                // 2 row-groups of 64
    const int wn   = wid >> 1;               // 4 col-groups of 32

    const int t8   = lane >> 3;
    const int r8   = lane & 7;
    const int a_roff = ((t8 & 1) << 3) + r8;
    const int a_gsel = t8 >> 1;
    const int b_roff = ((t8 >> 1) << 3) + r8;
    const int b_gsel = t8 & 1;

    float acc[4][4][4];
    #pragma unroll
    for (int i = 0; i < 4; i++)
        #pragma unroll
        for (int j = 0; j < 4; j++)
            #pragma unroll
            for (int r = 0; r < 4; r++) acc[i][j][r] = 0.f;

    uint32_t sbase = (uint32_t)__cvta_generic_to_shared(smem);

    // loader: 4 arrays x 128 rows x 8 granules = 4096 lines / 256 threads = 16 each
    auto load_fin = [&](uint32_t st, int h) {
        #pragma unroll
        for (int j = 0; j < 16; j++) {
            int id  = tid + j * 256;
            int arr = id >> 10;              // 0:whi 1:wlo 2:Mthi 3:Mtlo
            int l   = id & 1023;
            int row = l >> 3;
            int gr  = l & 7;
            uint32_t saddr = st + arr * 16384 + row * 128 + ((gr ^ (row & 7)) << 4);
            const __nv_bfloat16* g;
            if (arr < 2) {
                g = (arr == 0 ? Whi : Wlo) +
                    (((size_t)(b * HEADS + h) * NN) + n0 + row) * GG + gr * 8;
            } else {
                g = (arr == 2 ? Mthi : Mtlo) +
                    ((size_t)b * CC + row) * INNER + h * DH + gr * 8;
            }
            cp16(saddr, g, true);
        }
    };

    load_fin(sbase, 0);
    asm volatile("cp.async.commit_group;\n" ::: "memory");

    for (int it = 0; it < 8; ++it) {
        const int cur = it & 1;
        if (it + 1 < 8) {
            load_fin(sbase + (uint32_t)(1 - cur) * FSTAGE, it + 1);
            asm volatile("cp.async.commit_group;\n" ::: "memory");
            asm volatile("cp.async.wait_group 1;\n" ::: "memory");
        } else {
            asm volatile("cp.async.wait_group 0;\n" ::: "memory");
        }
        __syncthreads();

        const uint32_t stA = sbase + (uint32_t)cur * FSTAGE;
        const uint32_t stB = stA + 32768;

        #pragma unroll
        for (int s = 0; s < 4; s++) {
            uint32_t ah[4][4], al[4][4];
            #pragma unroll
            for (int mi = 0; mi < 4; mi++) {
                int row = wm * 64 + mi * 16 + a_roff;
                int g = 2 * s + a_gsel;
                uint32_t addr = stA + row * 128 + ((g ^ (row & 7)) << 4);
                ldsm4(ah[mi], addr);
                ldsm4(al[mi], addr + 16384);
            }
            #pragma unroll
            for (int np = 0; np < 2; np++) {
                int row = wn * 32 + np * 16 + b_roff;
                int g = 2 * s + b_gsel;
                uint32_t addr = stB + row * 128 + ((g ^ (row & 7)) << 4);
                uint32_t bh[4], bl[4];
                ldsm4(bh, addr);
                ldsm4(bl, addr + 16384);
                #pragma unroll
                for (int mi = 0; mi < 4; mi++) {
                    mma_bf16(acc[mi][2 * np],     ah[mi][0], ah[mi][1], ah[mi][2], ah[mi][3], bh[0], bh[1]);
                    mma_bf16(acc[mi][2 * np + 1], ah[mi][0], ah[mi][1], ah[mi][2], ah[mi][3], bh[2], bh[3]);
                }
                #pragma unroll
                for (int mi = 0; mi < 4; mi++) {
                    mma_bf16(acc[mi][2 * np],     ah[mi][0], ah[mi][1], ah[mi][2], ah[mi][3], bl[0], bl[1]);
                    mma_bf16(acc[mi][2 * np + 1], ah[mi][0], ah[mi][1], ah[mi][2], ah[mi][3], bl[2], bl[3]);
                }
                #pragma unroll
                for (int mi = 0; mi < 4; mi++) {
                    mma_bf16(acc[mi][2 * np],     al[mi][0], al[mi][1], al[mi][2], al[mi][3], bh[0], bh[1]);
                    mma_bf16(acc[mi][2 * np + 1], al[mi][0], al[mi][1], al[mi][2], al[mi][3], bh[2], bh[3]);
                }
            }
        }
        __syncthreads();
    }

    #pragma unroll
    for (int mi = 0; mi < 4; mi++) {
        int row = wm * 64 + mi * 16 + grp;
        int n  = n0 + row;
        #pragma unroll
        for (int ni = 0; ni < 4; ni++) {
            int oc = wn * 32 + ni * 8 + tid4 * 2;
            float b0v = bout[oc], b1v = bout[oc + 1];
            size_t base0 = ((size_t)b * NN + n) * CC + oc;
            out[base0]     = acc[mi][ni][0] + b0v;
            out[base0 + 1] = acc[mi][ni][1] + b1v;
            size_t base1 = ((size_t)b * NN + n + 8) * CC + oc;
            out[base1]     = acc[mi][ni][2] + b0v;
            out[base1 + 1] = acc[mi][ni][3] + b1v;
        }
    }
}

// ---------------- launch ----------------
extern "C" void kernel_launch(void* const* d_in, const int* in_sizes, int n_in,
                              void* d_out, int out_size) {
    const float* x     = (const float*)d_in[0];
    const float* Wfx   = (const float*)d_in[1];
    const float* bfx   = (const float*)d_in[2];
    const float* Wx    = (const float*)d_in[3];
    const float* bx    = (const float*)d_in[4];
    const float* Wsl   = (const float*)d_in[5];
    const float* bsl   = (const float*)d_in[6];
    const float* temp  = (const float*)d_in[7];
    const float* Wq    = (const float*)d_in[8];
    const float* Wk    = (const float*)d_in[9];
    const float* Wv    = (const float*)d_in[10];
    const float* Wout  = (const float*)d_in[11];
    const float* bout  = (const float*)d_in[12];
    float* out = (float*)d_out;

    float *p_tokp, *p_normp, *p_tok, *p_norm, *p_lb;
    __nv_bfloat16 *p_xhi, *p_xlo, *p_whi, *p_wlo;
    __nv_bfloat16 *p_fxhi, *p_fxlo;
    __nv_bfloat16 *p_swhi, *p_swlo, *p_Mthi, *p_Mtlo;
    cudaGetSymbolAddress((void**)&p_tokp, g_tokp);
    cudaGetSymbolAddress((void**)&p_normp, g_normp);
    cudaGetSymbolAddress((void**)&p_tok, g_tok);
    cudaGetSymbolAddress((void**)&p_norm, g_norm);
    cudaGetSymbolAddress((void**)&p_lb, g_lbias);
    cudaGetSymbolAddress((void**)&p_xhi, g_xhi);
    cudaGetSymbolAddress((void**)&p_xlo, g_xlo);
    cudaGetSymbolAddress((void**)&p_whi, g_whi);
    cudaGetSymbolAddress((void**)&p_wlo, g_wlo);
    cudaGetSymbolAddress((void**)&p_fxhi, g_fxhi);
    cudaGetSymbolAddress((void**)&p_fxlo, g_fxlo);
    cudaGetSymbolAddress((void**)&p_swhi, g_swhi);
    cudaGetSymbolAddress((void**)&p_swlo, g_swlo);
    cudaGetSymbolAddress((void**)&p_Mthi, g_Mthi);
    cudaGetSymbolAddress((void**)&p_Mtlo, g_Mtlo);

    static bool attr_set = false;
    if (!attr_set) {
        cudaFuncSetAttribute(conv_mma_kernel,
                             cudaFuncAttributeMaxDynamicSharedMemorySize, 2 * CSTAGE);
        cudaFuncSetAttribute(final_mma_kernel,
                             cudaFuncAttributeMaxDynamicSharedMemorySize, 2 * FSTAGE);
        attr_set = true;
    }

    dim3 blk(16, 16);

    // 0. staging (3 launches; conv is launch #4 for ncu visibility)
    split_x_kernel<<<(BB * NN * CC) / 256, 256>>>(x, p_xhi, p_xlo);
    split_w_kernel<<<(512 * KTOT) / 256, 256>>>(Wfx, p_whi, p_wlo);
    combine_w_kernel<<<dim3(512, 10), 128>>>(Wx, Wsl, bx, bsl, temp, p_whi, p_wlo, p_lb);

    // 1. fused conv (launch #4): fx bf16 hi/lo + softmax slice weights
    conv_mma_kernel<<<dim3(4, 512, BB), 256, 2 * CSTAGE>>>(
        p_xhi, p_xlo, p_whi, p_wlo, bfx, p_lb, p_fxhi, p_fxlo, p_swhi, p_swlo);

    // 2. slice token reduction on tensor cores + split reduce
    token_mma_kernel<<<dim3(SPLITS, BB * HEADS), 128>>>(
        p_swhi, p_swlo, p_fxhi, p_fxlo, p_tokp, p_normp);
    split_reduce_kernel<<<260, 256>>>(p_tokp, p_normp, p_tok, p_norm);

    // 3. tiny attention + fused Wout fold -> Mt (bf16 hi/lo)
    attn_kernel<<<BB * HEADS, blk>>>(p_tok, p_norm, Wq, Wk, Wv, Wout, p_Mthi, p_Mtlo);

    // 4. fused scatter + projection, kc=64 + ldmatrix
    final_mma_kernel<<<1024, 256, 2 * FSTAGE>>>(p_swhi, p_swlo, p_Mthi, p_Mtlo, bout, out);
}

// round 11
// speedup vs baseline: 1.1975x; 1.0538x over previous
#include <cuda_runtime.h>
#include <cuda_bf16.h>
#include <math.h>
#include <stdint.h>

// Problem constants
#define BB 2
#define HH 256
#define WW 256
#define NN 65536          // H*W
#define CC 128
#define HEADS 8
#define DH 64             // dim_head
#define GG 64             // SLICE
#define INNER 512         // HEADS*DH
#define SPLITS 64         // split-K for token reduction
#define CHUNK 1024        // tokens per split (NN/SPLITS)
#define KTOT 1152         // 9 taps * 128 channels

// ---------------- device scratch (static, no allocs) ----------------
__device__ float g_tokp[(size_t)SPLITS * BB * HEADS * GG * DH];
__device__ float g_normp[(size_t)SPLITS * BB * HEADS * GG];
__device__ float g_tok [(size_t)BB * HEADS * GG * DH];
__device__ float g_norm[(size_t)BB * HEADS * GG];
__device__ float g_lbias[INNER];                     // (bx·Wslice + bslice)/temp

// fx_mid as bf16 hi/lo pair  [b][n][inner]
__device__ __align__(16) __nv_bfloat16 g_fxhi[(size_t)BB * NN * INNER];
__device__ __align__(16) __nv_bfloat16 g_fxlo[(size_t)BB * NN * INNER];
// slice weights as bf16 hi/lo pair  [bh][n][g]
__device__ __align__(16) __nv_bfloat16 g_swhi[(size_t)BB * HEADS * NN * GG];
__device__ __align__(16) __nv_bfloat16 g_swlo[(size_t)BB * HEADS * NN * GG];
// Mt = (out_slice · Wout^T) transposed: [b][o][h*64+g], bf16 hi/lo
__device__ __align__(16) __nv_bfloat16 g_Mthi[(size_t)BB * CC * INNER];
__device__ __align__(16) __nv_bfloat16 g_Mtlo[(size_t)BB * CC * INNER];

// bf16 3-split staging for conv
__device__ __align__(16) __nv_bfloat16 g_xhi[(size_t)BB * NN * CC];
__device__ __align__(16) __nv_bfloat16 g_xlo[(size_t)BB * NN * CC];
// rows 0..511: Wfx cols; rows 512..1023: combined logit weights (Wx·Wslice/temp)
__device__ __align__(16) __nv_bfloat16 g_whi[(size_t)1024 * KTOT];
__device__ __align__(16) __nv_bfloat16 g_wlo[(size_t)1024 * KTOT];

// ---------------- prep kernels ----------------
__global__ void split_x_kernel(const float* __restrict__ x,
                               __nv_bfloat16* __restrict__ xhi,
                               __nv_bfloat16* __restrict__ xlo) {
    size_t i = (size_t)blockIdx.x * 256 + threadIdx.x;
    float f = x[i];
    __nv_bfloat16 h = __float2bfloat16(f);
    float r = f - __bfloat162float(h);
    xhi[i] = h;
    xlo[i] = __float2bfloat16(r);
}

// Wfx (fx conv weights) -> rows 0..511 of g_whi/g_wlo, transposed [oc][k]
__global__ void split_w_kernel(const float* __restrict__ Wfx,
                               __nv_bfloat16* __restrict__ whi,
                               __nv_bfloat16* __restrict__ wlo) {
    int i = blockIdx.x * 256 + threadIdx.x;   // 512*1152 total
    int oc = i / KTOT;
    int k  = i - oc * KTOT;
    float f = Wfx[(size_t)k * 512 + oc];
    __nv_bfloat16 h = __float2bfloat16(f);
    float r = f - __bfloat162float(h);
    whi[i] = h;
    wlo[i] = __float2bfloat16(r);
}

// y<9:  W~[k][h*64+g] = (sum_d Wx[k][h*64+d]*Wslice[g][d]) / temp_h -> rows 512..1023
// y==9: lbias[h*64+g] = (bx_h · Wslice_g + bslice_g) / temp_h
__global__ void combine_w_kernel(const float* __restrict__ Wx,
                                 const float* __restrict__ Wsl,
                                 const float* __restrict__ bx,
                                 const float* __restrict__ bsl,
                                 const float* __restrict__ temp,
                                 __nv_bfloat16* __restrict__ whi,
                                 __nv_bfloat16* __restrict__ wlo,
                                 float* __restrict__ lb) {
    __shared__ float ws[64];
    const int col = blockIdx.x;          // 0..511
    const int h = col >> 6, g = col & 63;
    const int tid = threadIdx.x;         // 128
    if (tid < 64) ws[tid] = Wsl[g * 64 + tid];
    __syncthreads();
    float t = fminf(fmaxf(temp[h], 0.1f), 5.0f);
    float invt = 1.0f / t;

    if (blockIdx.y == 9) {
        if (tid < 32) {
            float s = bx[h * 64 + tid] * ws[tid]
                    + bx[h * 64 + 32 + tid] * ws[32 + tid];
            #pragma unroll
            for (int o = 16; o > 0; o >>= 1)
                s += __shfl_xor_sync(0xffffffffu, s, o);
            if (tid == 0) lb[col] = (s + bsl[g]) * invt;
        }
        return;
    }

    int k = blockIdx.y * 128 + tid;      // 9 y-blocks -> 0..1151
    const float* wr = Wx + (size_t)k * 512 + h * 64;
    float s = 0.f;
    #pragma unroll 8
    for (int d = 0; d < 64; d++) s += wr[d] * ws[d];
    s *= invt;
    __nv_bfloat16 hv = __float2bfloat16(s);
    size_t o = (size_t)(512 + col) * KTOT + k;
    whi[o] = hv;
    wlo[o] = __float2bfloat16(s - __bfloat162float(hv));
}

// ---------------- shared MMA plumbing ----------------
__device__ __forceinline__ void cp16(uint32_t saddr, const void* g, bool valid) {
    int sz = valid ? 16 : 0;
    asm volatile("cp.async.cg.shared.global [%0], [%1], 16, %2;\n"
                 :: "r"(saddr), "l"(g), "r"(sz));
}

__device__ __forceinline__ void mma_bf16(float c[4], uint32_t a0, uint32_t a1,
                                         uint32_t a2, uint32_t a3,
                                         uint32_t b0, uint32_t b1) {
    asm volatile(
        "mma.sync.aligned.m16n8k16.row.col.f32.bf16.bf16.f32 "
        "{%0,%1,%2,%3}, {%4,%5,%6,%7}, {%8,%9}, {%0,%1,%2,%3};"
        : "+f"(c[0]), "+f"(c[1]), "+f"(c[2]), "+f"(c[3])
        : "r"(a0), "r"(a1), "r"(a2), "r"(a3), "r"(b0), "r"(b1));
}

__device__ __forceinline__ void ldsm4(uint32_t r[4], uint32_t addr) {
    asm volatile("ldmatrix.sync.aligned.m8n8.x4.shared.b16 {%0,%1,%2,%3}, [%4];"
                 : "=r"(r[0]), "=r"(r[1]), "=r"(r[2]), "=r"(r[3]) : "r"(addr));
}

__device__ __forceinline__ void ldsm4t(uint32_t r[4], uint32_t addr) {
    asm volatile("ldmatrix.sync.aligned.m8n8.x4.trans.shared.b16 {%0,%1,%2,%3}, [%4];"
                 : "=r"(r[0]), "=r"(r[1]), "=r"(r[2]), "=r"(r[3]) : "r"(addr));
}

// packed kc=32 tile: 128 logical rows x 32 bf16, two logical rows per 128B phys row.
// s-granule = (gr | ((r&1)<<2)) ^ ((r>>1)&7); verified conflict-free for LDSM phases.
__device__ __forceinline__ uint32_t sw32(int row, int gr) {
    return (uint32_t)(row >> 1) * 128 +
           (uint32_t)(((gr | ((row & 1) << 2)) ^ ((row >> 1) & 7)) << 4);
}

// ---------------- conv: implicit GEMM 128x128, kc=32, 4 warps, 2 CTAs/SM ----------------
// ocb 0..3: fx output (cols ocb*128); ocb 4..7: slice-weight softmax (2 heads each).
// Stage (32KB): Ahi 8K | Alo 8K | Bhi 8K | Blo 8K. 3 stages = 96KB -> 2 CTAs/SM.
#define CSTAGE 32768
#define NCHUNK 36

__device__ __forceinline__ void conv_load(
    uint32_t st,
    const __nv_bfloat16* __restrict__ Xhi, const __nv_bfloat16* __restrict__ Xlo,
    const __nv_bfloat16* __restrict__ Whi, const __nv_bfloat16* __restrict__ Wlo,
    int it, int b, int hrow, int w0, int ocb, int tid)
{
    const int kg  = it * 32;
    const int tap = kg >> 7;
    const int dy = tap / 3 - 1, dx = tap % 3 - 1;
    const int c0 = kg & 127;            // 0/32/64/96
    const int hp = hrow + dy;
    const bool hok = (hp >= 0) && (hp < HH);
    const int hpc = hok ? hp : 0;

    // A: 2 arrays x 128 rows x 4 granules = 1024 lines (8 per thread)
    #pragma unroll
    for (int j = 0; j < 8; j++) {
        int id  = tid + j * 128;
        int arr = id >> 9;              // 0:Ahi 1:Alo
        int l   = id & 511;
        int row = l >> 2;
        int gr  = l & 3;
        uint32_t saddr = st + arr * 8192 + sw32(row, gr);
        int wp = w0 + row + dx;
        bool valid = hok && (wp >= 0) && (wp < WW);
        int wpc = valid ? wp : 0;
        const __nv_bfloat16* g = (arr == 0 ? Xhi : Xlo) +
            (((size_t)b * NN + (size_t)hpc * WW + wpc) * CC + c0 + gr * 8);
        cp16(saddr, g, valid);
    }
    // B: 2 arrays x 128 rows x 4 granules = 1024 lines (8 per thread)
    #pragma unroll
    for (int j = 0; j < 8; j++) {
        int id  = tid + j * 128;
        int arr = id >> 9;              // 0:Bhi 1:Blo
        int l   = id & 511;
        int row = l >> 2;
        int gr  = l & 3;
        uint32_t saddr = st + 16384 + arr * 8192 + sw32(row, gr);
        const __nv_bfloat16* g = (arr == 0 ? Whi : Wlo) +
            ((size_t)(ocb * 128 + row) * KTOT + kg + gr * 8);
        cp16(saddr, g, true);
    }
}

__global__ __launch_bounds__(128, 2)
void conv_mma_kernel(const __nv_bfloat16* __restrict__ Xhi,
                     const __nv_bfloat16* __restrict__ Xlo,
                     const __nv_bfloat16* __restrict__ Whi,
                     const __nv_bfloat16* __restrict__ Wlo,
                     const float* __restrict__ bfx,
                     const float* __restrict__ lbias,
                     __nv_bfloat16* __restrict__ fxhi,
                     __nv_bfloat16* __restrict__ fxlo,
                     __nv_bfloat16* __restrict__ swhi,
                     __nv_bfloat16* __restrict__ swlo)
{
    extern __shared__ char smem[];           // 3 stages x 32KB

    const int ocb = blockIdx.x;              // 0..7
    const int pt  = blockIdx.y;              // 0..511
    const int b   = blockIdx.z;
    const int n0  = pt * 128;
    const int hrow = n0 >> 8;
    const int w0   = n0 & 255;

    const int tid  = threadIdx.x;            // 0..127
    const int wid  = tid >> 5;               // 0..3
    const int lane = tid & 31;
    const int grp  = lane >> 2;
    const int tid4 = lane & 3;
    const int wm   = wid & 1;                // 2 row-groups of 64
    const int wn   = wid >> 1;               // 2 col-groups of 64

    const int t8   = lane >> 3;
    const int r8   = lane & 7;
    const int a_roff = ((t8 & 1) << 3) + r8;
    const int a_gsel = t8 >> 1;
    const int b_roff = ((t8 >> 1) << 3) + r8;
    const int b_gsel = t8 & 1;

    float acc[4][8][4];
    #pragma unroll
    for (int i = 0; i < 4; i++)
        #pragma unroll
        for (int j = 0; j < 8; j++)
            #pragma unroll
            for (int r = 0; r < 4; r++) acc[i][j][r] = 0.f;

    uint32_t sbase = (uint32_t)__cvta_generic_to_shared(smem);

    conv_load(sbase, Xhi, Xlo, Whi, Wlo, 0, b, hrow, w0, ocb, tid);
    asm volatile("cp.async.commit_group;\n" ::: "memory");
    conv_load(sbase + CSTAGE, Xhi, Xlo, Whi, Wlo, 1, b, hrow, w0, ocb, tid);
    asm volatile("cp.async.commit_group;\n" ::: "memory");

    for (int it = 0; it < NCHUNK; ++it) {
        const int cur = it % 3;
        if (it + 2 < NCHUNK)
            conv_load(sbase + (uint32_t)((it + 2) % 3) * CSTAGE,
                      Xhi, Xlo, Whi, Wlo, it + 2, b, hrow, w0, ocb, tid);
        asm volatile("cp.async.commit_group;\n" ::: "memory");
        asm volatile("cp.async.wait_group 2;\n" ::: "memory");
        __syncthreads();

        const uint32_t stA = sbase + (uint32_t)cur * CSTAGE;
        const uint32_t stB = stA + 16384;

        #pragma unroll
        for (int s = 0; s < 2; s++) {
            uint32_t ah[4][4], al[4][4];
            #pragma unroll
            for (int mi = 0; mi < 4; mi++) {
                int row = wm * 64 + mi * 16 + a_roff;
                int g = 2 * s + a_gsel;
                uint32_t addr = stA + sw32(row, g);
                ldsm4(ah[mi], addr);
                ldsm4(al[mi], addr + 8192);
            }
            #pragma unroll
            for (int np = 0; np < 4; np++) {
                int row = wn * 64 + np * 16 + b_roff;
                int g = 2 * s + b_gsel;
                uint32_t addr = stB + sw32(row, g);
                uint32_t bh[4], bl[4];
                ldsm4(bh, addr);
                ldsm4(bl, addr + 8192);
                #pragma unroll
                for (int mi = 0; mi < 4; mi++) {
                    mma_bf16(acc[mi][2 * np],     ah[mi][0], ah[mi][1], ah[mi][2], ah[mi][3], bh[0], bh[1]);
                    mma_bf16(acc[mi][2 * np + 1], ah[mi][0], ah[mi][1], ah[mi][2], ah[mi][3], bh[2], bh[3]);
                }
                #pragma unroll
                for (int mi = 0; mi < 4; mi++) {
                    mma_bf16(acc[mi][2 * np],     ah[mi][0], ah[mi][1], ah[mi][2], ah[mi][3], bl[0], bl[1]);
                    mma_bf16(acc[mi][2 * np + 1], ah[mi][0], ah[mi][1], ah[mi][2], ah[mi][3], bl[2], bl[3]);
                }
                #pragma unroll
                for (int mi = 0; mi < 4; mi++) {
                    mma_bf16(acc[mi][2 * np],     al[mi][0], al[mi][1], al[mi][2], al[mi][3], bh[0], bh[1]);
                    mma_bf16(acc[mi][2 * np + 1], al[mi][0], al[mi][1], al[mi][2], al[mi][3], bh[2], bh[3]);
                }
            }
        }
        __syncthreads();
    }

    if (ocb < 4) {
        // fx output: bf16 hi/lo pairs with bias (cols ocb*128 .. +127)
        const int ocbase = ocb * 128;
        #pragma unroll
        for (int mi = 0; mi < 4; mi++) {
            int row = wm * 64 + mi * 16 + grp;
            int n  = n0 + row;
            #pragma unroll
            for (int ni = 0; ni < 8; ni++) {
                int col = wn * 64 + ni * 8 + tid4 * 2;
                int oc  = ocbase + col;
                float b0v = bfx[oc], b1v = bfx[oc + 1];
                float v0 = acc[mi][ni][0] + b0v;
                float v1 = acc[mi][ni][1] + b1v;
                float v2 = acc[mi][ni][2] + b0v;
                float v3 = acc[mi][ni][3] + b1v;
                __nv_bfloat16 h0 = __float2bfloat16(v0), h1 = __float2bfloat16(v1);
                __nv_bfloat16 h2 = __float2bfloat16(v2), h3 = __float2bfloat16(v3);
                __nv_bfloat162 ph0; ph0.x = h0; ph0.y = h1;
                __nv_bfloat162 pl0; pl0.x = __float2bfloat16(v0 - __bfloat162float(h0));
                                    pl0.y = __float2bfloat16(v1 - __bfloat162float(h1));
                __nv_bfloat162 ph1; ph1.x = h2; ph1.y = h3;
                __nv_bfloat162 pl1; pl1.x = __float2bfloat16(v2 - __bfloat162float(h2));
                                    pl1.y = __float2bfloat16(v3 - __bfloat162float(h3));
                size_t base0 = ((size_t)b * NN + n) * INNER + oc;
                size_t base1 = ((size_t)b * NN + n + 8) * INNER + oc;
                *(__nv_bfloat162*)(fxhi + base0) = ph0;
                *(__nv_bfloat162*)(fxlo + base0) = pl0;
                *(__nv_bfloat162*)(fxhi + base1) = ph1;
                *(__nv_bfloat162*)(fxlo + base1) = pl1;
            }
        }
    } else {
        // logits: stage to smem, softmax per (pixel, head), emit bf16 hi/lo
        float* sred = (float*)smem;          // [128][132] = 67.5KB <= 96KB
        #pragma unroll
        for (int mi = 0; mi < 4; mi++) {
            int row = wm * 64 + mi * 16 + grp;
            #pragma unroll
            for (int ni = 0; ni < 8; ni++) {
                int col = wn * 64 + ni * 8 + tid4 * 2;
                sred[row * 132 + col]           = acc[mi][ni][0];
                sred[row * 132 + col + 1]       = acc[mi][ni][1];
                sred[(row + 8) * 132 + col]     = acc[mi][ni][2];
                sred[(row + 8) * 132 + col + 1] = acc[mi][ni][3];
            }
        }
        __syncthreads();

        #pragma unroll
        for (int pass = 0; pass < 2; pass++) {
            int tsk = tid + pass * 128;      // 0..255
            int row  = tsk >> 1;
            int hloc = tsk & 1;
            int h = (ocb - 4) * 2 + hloc;
            int n = n0 + row;
            const float* lb = lbias + h * 64;
            float* sr = sred + row * 132 + hloc * 64;

            float mx = -1e30f;
            #pragma unroll 8
            for (int g = 0; g < 64; g++) mx = fmaxf(mx, sr[g] + lb[g]);
            float ssum = 0.f;
            #pragma unroll 8
            for (int g = 0; g < 64; g++) {
                float e = __expf(sr[g] + lb[g] - mx);
                ssum += e;
                sr[g] = e;
            }
            float inv = 1.0f / ssum;

            size_t base = ((size_t)(b * HEADS + h) * NN + n) * GG;
            #pragma unroll
            for (int c = 0; c < 8; c++) {
                union { __nv_bfloat16 hb[8]; uint4 u; } Uh, Ul;
                #pragma unroll
                for (int e = 0; e < 8; e++) {
                    float v = sr[c * 8 + e] * inv;
                    __nv_bfloat16 hv = __float2bfloat16(v);
                    Uh.hb[e] = hv;
                    Ul.hb[e] = __float2bfloat16(v - __bfloat162float(hv));
                }
                ((uint4*)(swhi + base))[c] = Uh.u;
                ((uint4*)(swlo + base))[c] = Ul.u;
            }
        }
    }
}

// ---------------- K3: token reduction on tensor cores ----------------
__global__ __launch_bounds__(128)
void token_mma_kernel(const __nv_bfloat16* __restrict__ whi,
                      const __nv_bfloat16* __restrict__ wlo,
                      const __nv_bfloat16* __restrict__ fxhi,
                      const __nv_bfloat16* __restrict__ fxlo,
                      float* __restrict__ tokp,
                      float* __restrict__ normp)
{
    __shared__ __align__(16) char smem[2 * 8192];

    const int bh = blockIdx.y;
    const int b = bh >> 3, h = bh & 7;
    const int split = blockIdx.x;
    const int nbase = split * CHUNK;

    const int tid  = threadIdx.x;
    const int wid  = tid >> 5;          // 0..3: g-strip wid*16
    const int lane = tid & 31;
    const int grp  = lane >> 2;
    const int tid4 = lane & 3;
    const int t8   = lane >> 3;
    const int r8   = lane & 7;
    const int lrow = r8 + ((t8 >> 1) << 3);   // 0..15
    const int lgr  = t8 & 1;

    const uint32_t ONES = 0x3F803F80u;  // bf16(1.0) x2

    float acc[8][4];
    #pragma unroll
    for (int j = 0; j < 8; j++)
        #pragma unroll
        for (int r = 0; r < 4; r++) acc[j][r] = 0.f;
    float accn[4] = {};

    uint32_t sbase = (uint32_t)__cvta_generic_to_shared(smem);

    auto load = [&](uint32_t st, int t0) {
        #pragma unroll
        for (int j = 0; j < 4; j++) {
            int id  = tid + j * 128;
            int arr = id >> 7;          // 0:whi 1:wlo 2:fxhi 3:fxlo
            int l   = id & 127;
            int row = l >> 3;
            int gr  = l & 7;
            uint32_t saddr = st + arr * 2048 + row * 128 + ((gr ^ (row & 7)) << 4);
            int n = nbase + t0 + row;
            const __nv_bfloat16* g;
            if (arr < 2) {
                g = (arr == 0 ? whi : wlo) + ((size_t)bh * NN + n) * GG + gr * 8;
            } else {
                g = (arr == 2 ? fxhi : fxlo) +
                    ((size_t)b * NN + n) * INNER + h * DH + gr * 8;
            }
            cp16(saddr, g, true);
        }
    };

    load(sbase, 0);
    asm volatile("cp.async.commit_group;\n" ::: "memory");

    for (int it = 0; it < 64; ++it) {
        const int cur = it & 1;
        if (it + 1 < 64) {
            load(sbase + (uint32_t)(1 - cur) * 8192, (it + 1) * 16);
            asm volatile("cp.async.commit_group;\n" ::: "memory");
            asm volatile("cp.async.wait_group 1;\n" ::: "memory");
        } else {
            asm volatile("cp.async.wait_group 0;\n" ::: "memory");
        }
        __syncthreads();

        const uint32_t st = sbase + (uint32_t)cur * 8192;

        uint32_t awh[4], awl[4];
        {
            int gr = wid * 2 + lgr;
            uint32_t addr = st + lrow * 128 + ((gr ^ (lrow & 7)) << 4);
            ldsm4t(awh, addr);
            ldsm4t(awl, addr + 2048);
        }
        mma_bf16(accn, awh[0], awh[1], awh[2], awh[3], ONES, ONES);
        mma_bf16(accn, awl[0], awl[1], awl[2], awl[3], ONES, ONES);

        #pragma unroll
        for (int j = 0; j < 4; j++) {
            int gr = j * 2 + lgr;
            uint32_t addr = st + 4096 + lrow * 128 + ((gr ^ (lrow & 7)) << 4);
            uint32_t bfh[4], bfl[4];
            ldsm4t(bfh, addr);
            ldsm4t(bfl, addr + 2048);
            mma_bf16(acc[2 * j],     awh[0], awh[1], awh[2], awh[3], bfh[0], bfh[2]);
            mma_bf16(acc[2 * j + 1], awh[0], awh[1], awh[2], awh[3], bfh[1], bfh[3]);
            mma_bf16(acc[2 * j],     awh[0], awh[1], awh[2], awh[3], bfl[0], bfl[2]);
            mma_bf16(acc[2 * j + 1], awh[0], awh[1], awh[2], awh[3], bfl[1], bfl[3]);
            mma_bf16(acc[2 * j],     awl[0], awl[1], awl[2], awl[3], bfh[0], bfh[2]);
            mma_bf16(acc[2 * j + 1], awl[0], awl[1], awl[2], awl[3], bfh[1], bfh[3]);
        }
        __syncthreads();
    }

    const size_t base = ((size_t)split * (BB * HEADS) + bh) * (GG * DH);
    const int g0 = wid * 16 + grp;
    #pragma unroll
    for (int nf = 0; nf < 8; nf++) {
        int d = (nf >> 1) * 16 + (nf & 1) * 8 + tid4 * 2;
        tokp[base + (size_t)g0 * DH + d]           = acc[nf][0];
        tokp[base + (size_t)g0 * DH + d + 1]       = acc[nf][1];
        tokp[base + (size_t)(g0 + 8) * DH + d]     = acc[nf][2];
        tokp[base + (size_t)(g0 + 8) * DH + d + 1] = acc[nf][3];
    }
    if (tid4 == 0) {
        size_t nb = ((size_t)split * (BB * HEADS) + bh) * GG;
        normp[nb + g0]     = accn[0];
        normp[nb + g0 + 8] = accn[2];
    }
}

// ---------------- K3b: deterministic split reduction ----------------
__global__ void split_reduce_kernel(const float* __restrict__ tokp,
                                    const float* __restrict__ normp,
                                    float* __restrict__ tok,
                                    float* __restrict__ norm) {
    const int blk = blockIdx.x;
    const int tid = threadIdx.x;
    if (blk < 256) {
        int idx = blk * 256 + tid;
        float s = 0.f;
        #pragma unroll 8
        for (int sp = 0; sp < SPLITS; sp++)
            s += tokp[(size_t)sp * 65536 + idx];
        tok[idx] = s;
    } else {
        int idx = (blk - 256) * 256 + tid;
        float s = 0.f;
        #pragma unroll 8
        for (int sp = 0; sp < SPLITS; sp++)
            s += normp[(size_t)sp * 1024 + idx];
        norm[idx] = s;
    }
}

// ---------------- K4: tiny attention per (b,h), emits Mt bf16 hi/lo ----------------
__global__ void attn_kernel(const float* __restrict__ tok,
                            const float* __restrict__ norm,
                            const float* __restrict__ Wq,
                            const float* __restrict__ Wk,
                            const float* __restrict__ Wv,
                            const float* __restrict__ Wout,
                            __nv_bfloat16* __restrict__ Mthi,
                            __nv_bfloat16* __restrict__ Mtlo) {
    const int bh = blockIdx.x;
    const int b = bh >> 3, h = bh & 7;
    const int tx = threadIdx.x, ty = threadIdx.y;
    const int tid = ty * 16 + tx;

    __shared__ float A[64][65];
    __shared__ float Bm[64][65];
    __shared__ float Cm[64][65];

    #pragma unroll
    for (int e = 0; e < 16; e++) {
        int idx = tid + e * 256;
        int g = idx >> 6, d = idx & 63;
        A[g][d] = tok[(size_t)bh * 4096 + idx] / (norm[bh * 64 + g] + 1e-5f);
    }
    __syncthreads();

    {
        float aq[4][4] = {}, ak[4][4] = {};
        #pragma unroll
        for (int kk = 0; kk < 64; kk++) {
            float a[4];
            #pragma unroll
            for (int i = 0; i < 4; i++) a[i] = A[ty + 16 * i][kk];
            #pragma unroll
            for (int j = 0; j < 4; j++) {
                float wq = __ldg(&Wq[(tx + 16 * j) * 64 + kk]);
                float wk = __ldg(&Wk[(tx + 16 * j) * 64 + kk]);
                #pragma unroll
                for (int i = 0; i < 4; i++) {
                    aq[i][j] += a[i] * wq;
                    ak[i][j] += a[i] * wk;
                }
            }
        }
        #pragma unroll
        for (int i = 0; i < 4; i++)
            #pragma unroll
            for (int j = 0; j < 4; j++) {
                Bm[ty + 16 * i][tx + 16 * j] = aq[i][j];
                Cm[ty + 16 * i][tx + 16 * j] = ak[i][j];
            }
    }
    __syncthreads();

    {
        float L[4][4] = {};
        #pragma unroll
        for (int kk = 0; kk < 64; kk++) {
            float a[4], bv[4];
            #pragma unroll
            for (int i = 0; i < 4; i++) a[i] = Bm[ty + 16 * i][kk];
            #pragma unroll
            for (int j = 0; j < 4; j++) bv[j] = Cm[tx + 16 * j][kk];
            #pragma unroll
            for (int i = 0; i < 4; i++)
                #pragma unroll
                for (int j = 0; j < 4; j++)
                    L[i][j] += a[i] * bv[j];
        }
        #pragma unroll
        for (int i = 0; i < 4; i++) {
            #pragma unroll
            for (int j = 0; j < 4; j++) L[i][j] *= 0.125f;
            float mx = L[i][0];
            #pragma unroll
            for (int j = 1; j < 4; j++) mx = fmaxf(mx, L[i][j]);
            #pragma unroll
            for (int o = 1; o < 16; o <<= 1)
                mx = fmaxf(mx, __shfl_xor_sync(0xffffffffu, mx, o, 16));
            float s = 0.f;
            #pragma unroll
            for (int j = 0; j < 4; j++) { L[i][j] = __expf(L[i][j] - mx); s += L[i][j]; }
            #pragma unroll
            for (int o = 1; o < 16; o <<= 1)
                s += __shfl_xor_sync(0xffffffffu, s, o, 16);
            float inv = 1.0f / s;
            #pragma unroll
            for (int j = 0; j < 4; j++)
                A[ty + 16 * i][tx + 16 * j] = L[i][j] * inv;
        }
    }
    __syncthreads();

    #pragma unroll
    for (int e = 0; e < 16; e++) {
        int idx = tid + e * 256;
        int g = idx >> 6;
        Bm[g][idx & 63] = tok[(size_t)bh * 4096 + idx] / (norm[bh * 64 + g] + 1e-5f);
    }
    __syncthreads();

    {
        float av[4][4] = {};
        #pragma unroll
        for (int kk = 0; kk < 64; kk++) {
            float a[4];
            #pragma unroll
            for (int i = 0; i < 4; i++) a[i] = Bm[ty + 16 * i][kk];
            #pragma unroll
            for (int j = 0; j < 4; j++) {
                float wv = __ldg(&Wv[(tx + 16 * j) * 64 + kk]);
                #pragma unroll
                for (int i = 0; i < 4; i++) av[i][j] += a[i] * wv;
            }
        }
        __syncthreads();
        #pragma unroll
        for (int i = 0; i < 4; i++)
            #pragma unroll
            for (int j = 0; j < 4; j++)
                Cm[ty + 16 * i][tx + 16 * j] = av[i][j];
    }
    __syncthreads();

    {
        float ao[4][4] = {};
        #pragma unroll
        for (int kk = 0; kk < 64; kk++) {
            float a[4], bv[4];
            #pragma unroll
            for (int i = 0; i < 4; i++) a[i] = A[ty + 16 * i][kk];
            #pragma unroll
            for (int j = 0; j < 4; j++) bv[j] = Cm[kk][tx + 16 * j];
            #pragma unroll
            for (int i = 0; i < 4; i++)
                #pragma unroll
                for (int j = 0; j < 4; j++)
                    ao[i][j] += a[i] * bv[j];
        }
        __syncthreads();
        #pragma unroll
        for (int i = 0; i < 4; i++)
            #pragma unroll
            for (int j = 0; j < 4; j++)
                Bm[ty + 16 * i][tx + 16 * j] = ao[i][j];
    }
    __syncthreads();

    {
        float am[4][8] = {};
        #pragma unroll
        for (int kk = 0; kk < 64; kk++) {
            float a[4];
            #pragma unroll
            for (int i = 0; i < 4; i++) a[i] = Bm[ty + 16 * i][kk];
            #pragma unroll
            for (int j = 0; j < 8; j++) {
                float wv = __ldg(&Wout[(size_t)(tx + 16 * j) * INNER + h * DH + kk]);
                #pragma unroll
                for (int i = 0; i < 4; i++) am[i][j] += a[i] * wv;
            }
        }
        #pragma unroll
        for (int i = 0; i < 4; i++) {
            int g = ty + 16 * i;
            #pragma unroll
            for (int j = 0; j < 8; j++) {
                int o = tx + 16 * j;
                float v = am[i][j];
                __nv_bfloat16 hv = __float2bfloat16(v);
                float r = v - __bfloat162float(hv);
                size_t idx = ((size_t)b * CC + o) * INNER + h * DH + g;
                Mthi[idx] = hv;
                Mtlo[idx] = __float2bfloat16(r);
            }
        }
    }
}

// ---------------- K5: fused scatter + projection, kc=64, ldmatrix ----------------
#define FSTAGE 65536

__global__ __launch_bounds__(256)
void final_mma_kernel(const __nv_bfloat16* __restrict__ Whi,
                      const __nv_bfloat16* __restrict__ Wlo,
                      const __nv_bfloat16* __restrict__ Mthi,
                      const __nv_bfloat16* __restrict__ Mtlo,
                      const float* __restrict__ bout,
                      float* __restrict__ out)
{
    extern __shared__ char smem[];

    const int pt = blockIdx.x;
    const int b  = pt >> 9;
    const int n0 = (pt & 511) * 128;

    const int tid  = threadIdx.x;
    const int wid  = tid >> 5;
    const int lane = tid & 31;
    const int grp  = lane >> 2;
    const int tid4 = lane & 3;
    const int wm   = wid & 1;                // 2 row-groups of 64
    const int wn   = wid >> 1;               // 4 col-groups of 32

    const int t8   = lane >> 3;
    const int r8   = lane & 7;
    const int a_roff = ((t8 & 1) << 3) + r8;
    const int a_gsel = t8 >> 1;
    const int b_roff = ((t8 >> 1) << 3) + r8;
    const int b_gsel = t8 & 1;

    float acc[4][4][4];
    #pragma unroll
    for (int i = 0; i < 4; i++)
        #pragma unroll
        for (int j = 0; j < 4; j++)
            #pragma unroll
            for (int r = 0; r < 4; r++) acc[i][j][r] = 0.f;

    uint32_t sbase = (uint32_t)__cvta_generic_to_shared(smem);

    auto load_fin = [&](uint32_t st, int h) {
        #pragma unroll
        for (int j = 0; j < 16; j++) {
            int id  = tid + j * 256;
            int arr = id >> 10;              // 0:whi 1:wlo 2:Mthi 3:Mtlo
            int l   = id & 1023;
            int row = l >> 3;
            int gr  = l & 7;
            uint32_t saddr = st + arr * 16384 + row * 128 + ((gr ^ (row & 7)) << 4);
            const __nv_bfloat16* g;
            if (arr < 2) {
                g = (arr == 0 ? Whi : Wlo) +
                    (((size_t)(b * HEADS + h) * NN) + n0 + row) * GG + gr * 8;
            } else {
                g = (arr == 2 ? Mthi : Mtlo) +
                    ((size_t)b * CC + row) * INNER + h * DH + gr * 8;
            }
            cp16(saddr, g, true);
        }
    };

    load_fin(sbase, 0);
    asm volatile("cp.async.commit_group;\n" ::: "memory");

    for (int it = 0; it < 8; ++it) {
        const int cur = it & 1;
        if (it + 1 < 8) {
            load_fin(sbase + (uint32_t)(1 - cur) * FSTAGE, it + 1);
            asm volatile("cp.async.commit_group;\n" ::: "memory");
            asm volatile("cp.async.wait_group 1;\n" ::: "memory");
        } else {
            asm volatile("cp.async.wait_group 0;\n" ::: "memory");
        }
        __syncthreads();

        const uint32_t stA = sbase + (uint32_t)cur * FSTAGE;
        const uint32_t stB = stA + 32768;

        #pragma unroll
        for (int s = 0; s < 4; s++) {
            uint32_t ah[4][4], al[4][4];
            #pragma unroll
            for (int mi = 0; mi < 4; mi++) {
                int row = wm * 64 + mi * 16 + a_roff;
                int g = 2 * s + a_gsel;
                uint32_t addr = stA + row * 128 + ((g ^ (row & 7)) << 4);
                ldsm4(ah[mi], addr);
                ldsm4(al[mi], addr + 16384);
            }
            #pragma unroll
            for (int np = 0; np < 2; np++) {
                int row = wn * 32 + np * 16 + b_roff;
                int g = 2 * s + b_gsel;
                uint32_t addr = stB + row * 128 + ((g ^ (row & 7)) << 4);
                uint32_t bh[4], bl[4];
                ldsm4(bh, addr);
                ldsm4(bl, addr + 16384);
                #pragma unroll
                for (int mi = 0; mi < 4; mi++) {
                    mma_bf16(acc[mi][2 * np],     ah[mi][0], ah[mi][1], ah[mi][2], ah[mi][3], bh[0], bh[1]);
                    mma_bf16(acc[mi][2 * np + 1], ah[mi][0], ah[mi][1], ah[mi][2], ah[mi][3], bh[2], bh[3]);
                }
                #pragma unroll
                for (int mi = 0; mi < 4; mi++) {
                    mma_bf16(acc[mi][2 * np],     ah[mi][0], ah[mi][1], ah[mi][2], ah[mi][3], bl[0], bl[1]);
                    mma_bf16(acc[mi][2 * np + 1], ah[mi][0], ah[mi][1], ah[mi][2], ah[mi][3], bl[2], bl[3]);
                }
                #pragma unroll
                for (int mi = 0; mi < 4; mi++) {
                    mma_bf16(acc[mi][2 * np],     al[mi][0], al[mi][1], al[mi][2], al[mi][3], bh[0], bh[1]);
                    mma_bf16(acc[mi][2 * np + 1], al[mi][0], al[mi][1], al[mi][2], al[mi][3], bh[2], bh[3]);
                }
            }
        }
        __syncthreads();
    }

    #pragma unroll
    for (int mi = 0; mi < 4; mi++) {
        int row = wm * 64 + mi * 16 + grp;
        int n  = n0 + row;
        #pragma unroll
        for (int ni = 0; ni < 4; ni++) {
            int oc = wn * 32 + ni * 8 + tid4 * 2;
            float b0v = bout[oc], b1v = bout[oc + 1];
            size_t base0 = ((size_t)b * NN + n) * CC + oc;
            out[base0]     = acc[mi][ni][0] + b0v;
            out[base0 + 1] = acc[mi][ni][1] + b1v;
            size_t base1 = ((size_t)b * NN + n + 8) * CC + oc;
            out[base1]     = acc[mi][ni][2] + b0v;
            out[base1 + 1] = acc[mi][ni][3] + b1v;
        }
    }
}

// ---------------- launch ----------------
extern "C" void kernel_launch(void* const* d_in, const int* in_sizes, int n_in,
                              void* d_out, int out_size) {
    const float* x     = (const float*)d_in[0];
    const float* Wfx   = (const float*)d_in[1];
    const float* bfx   = (const float*)d_in[2];
    const float* Wx    = (const float*)d_in[3];
    const float* bx    = (const float*)d_in[4];
    const float* Wsl   = (const float*)d_in[5];
    const float* bsl   = (const float*)d_in[6];
    const float* temp  = (const float*)d_in[7];
    const float* Wq    = (const float*)d_in[8];
    const float* Wk    = (const float*)d_in[9];
    const float* Wv    = (const float*)d_in[10];
    const float* Wout  = (const float*)d_in[11];
    const float* bout  = (const float*)d_in[12];
    float* out = (float*)d_out;

    float *p_tokp, *p_normp, *p_tok, *p_norm, *p_lb;
    __nv_bfloat16 *p_xhi, *p_xlo, *p_whi, *p_wlo;
    __nv_bfloat16 *p_fxhi, *p_fxlo;
    __nv_bfloat16 *p_swhi, *p_swlo, *p_Mthi, *p_Mtlo;
    cudaGetSymbolAddress((void**)&p_tokp, g_tokp);
    cudaGetSymbolAddress((void**)&p_normp, g_normp);
    cudaGetSymbolAddress((void**)&p_tok, g_tok);
    cudaGetSymbolAddress((void**)&p_norm, g_norm);
    cudaGetSymbolAddress((void**)&p_lb, g_lbias);
    cudaGetSymbolAddress((void**)&p_xhi, g_xhi);
    cudaGetSymbolAddress((void**)&p_xlo, g_xlo);
    cudaGetSymbolAddress((void**)&p_whi, g_whi);
    cudaGetSymbolAddress((void**)&p_wlo, g_wlo);
    cudaGetSymbolAddress((void**)&p_fxhi, g_fxhi);
    cudaGetSymbolAddress((void**)&p_fxlo, g_fxlo);
    cudaGetSymbolAddress((void**)&p_swhi, g_swhi);
    cudaGetSymbolAddress((void**)&p_swlo, g_swlo);
    cudaGetSymbolAddress((void**)&p_Mthi, g_Mthi);
    cudaGetSymbolAddress((void**)&p_Mtlo, g_Mtlo);

    static bool attr_set = false;
    if (!attr_set) {
        cudaFuncSetAttribute(conv_mma_kernel,
                             cudaFuncAttributeMaxDynamicSharedMemorySize, 3 * CSTAGE);
        cudaFuncSetAttribute(final_mma_kernel,
                             cudaFuncAttributeMaxDynamicSharedMemorySize, 2 * FSTAGE);
        attr_set = true;
    }

    dim3 blk(16, 16);

    // 0. staging (3 launches; conv is launch #4 for ncu visibility)
    split_x_kernel<<<(BB * NN * CC) / 256, 256>>>(x, p_xhi, p_xlo);
    split_w_kernel<<<(512 * KTOT) / 256, 256>>>(Wfx, p_whi, p_wlo);
    combine_w_kernel<<<dim3(512, 10), 128>>>(Wx, Wsl, bx, bsl, temp, p_whi, p_wlo, p_lb);

    // 1. fused conv (launch #4): 128x128 tiles, 4 warps, 2 CTAs/SM, 3-stage
    conv_mma_kernel<<<dim3(8, 512, BB), 128, 3 * CSTAGE>>>(
        p_xhi, p_xlo, p_whi, p_wlo, bfx, p_lb, p_fxhi, p_fxlo, p_swhi, p_swlo);

    // 2. slice token reduction on tensor cores + split reduce
    token_mma_kernel<<<dim3(SPLITS, BB * HEADS), 128>>>(
        p_swhi, p_swlo, p_fxhi, p_fxlo, p_tokp, p_normp);
    split_reduce_kernel<<<260, 256>>>(p_tokp, p_normp, p_tok, p_norm);

    // 3. tiny attention + fused Wout fold -> Mt (bf16 hi/lo)
    attn_kernel<<<BB * HEADS, blk>>>(p_tok, p_norm, Wq, Wk, Wv, Wout, p_Mthi, p_Mtlo);

    // 4. fused scatter + projection, kc=64 + ldmatrix
    final_mma_kernel<<<1024, 256, 2 * FSTAGE>>>(p_swhi, p_swlo, p_Mthi, p_Mtlo, bout, out);
}

// round 12
// speedup vs baseline: 1.2230x; 1.0214x over previous
#include <cuda_runtime.h>
#include <cuda_bf16.h>
#include <math.h>
#include <stdint.h>

// Problem constants
#define BB 2
#define HH 256
#define WW 256
#define NN 65536          // H*W
#define CC 128
#define HEADS 8
#define DH 64             // dim_head
#define GG 64             // SLICE
#define INNER 512         // HEADS*DH
#define SPLITS 64         // split-K for token reduction
#define CHUNK 1024        // tokens per split (NN/SPLITS)
#define KTOT 1152         // 9 taps * 128 channels

// ---------------- device scratch (static, no allocs) ----------------
__device__ float g_tokp[(size_t)SPLITS * BB * HEADS * GG * DH];
__device__ float g_normp[(size_t)SPLITS * BB * HEADS * GG];
__device__ float g_tok [(size_t)BB * HEADS * GG * DH];
__device__ float g_norm[(size_t)BB * HEADS * GG];
__device__ float g_lbias[INNER];                     // (bx·Wslice + bslice)/temp

// fx_mid as single bf16 (errors average out in slice_token mean)  [b][n][inner]
__device__ __align__(16) __nv_bfloat16 g_fxhi[(size_t)BB * NN * INNER];
// slice weights as bf16 hi/lo pair  [bh][n][g]
__device__ __align__(16) __nv_bfloat16 g_swhi[(size_t)BB * HEADS * NN * GG];
__device__ __align__(16) __nv_bfloat16 g_swlo[(size_t)BB * HEADS * NN * GG];
// Mt = (out_slice · Wout^T) transposed: [b][o][h*64+g], bf16 hi/lo
__device__ __align__(16) __nv_bfloat16 g_Mthi[(size_t)BB * CC * INNER];
__device__ __align__(16) __nv_bfloat16 g_Mtlo[(size_t)BB * CC * INNER];

// bf16 3-split staging for conv
__device__ __align__(16) __nv_bfloat16 g_xhi[(size_t)BB * NN * CC];
__device__ __align__(16) __nv_bfloat16 g_xlo[(size_t)BB * NN * CC];
// rows 0..511: Wfx cols; rows 512..1023: combined logit weights (Wx·Wslice/temp)
__device__ __align__(16) __nv_bfloat16 g_whi[(size_t)1024 * KTOT];
__device__ __align__(16) __nv_bfloat16 g_wlo[(size_t)1024 * KTOT];

// ---------------- prep kernels ----------------
__global__ void split_x_kernel(const float* __restrict__ x,
                               __nv_bfloat16* __restrict__ xhi,
                               __nv_bfloat16* __restrict__ xlo) {
    size_t i = (size_t)blockIdx.x * 256 + threadIdx.x;
    float f = x[i];
    __nv_bfloat16 h = __float2bfloat16(f);
    float r = f - __bfloat162float(h);
    xhi[i] = h;
    xlo[i] = __float2bfloat16(r);
}

// Wfx (fx conv weights) -> rows 0..511 of g_whi/g_wlo, transposed [oc][k]
__global__ void split_w_kernel(const float* __restrict__ Wfx,
                               __nv_bfloat16* __restrict__ whi,
                               __nv_bfloat16* __restrict__ wlo) {
    int i = blockIdx.x * 256 + threadIdx.x;   // 512*1152 total
    int oc = i / KTOT;
    int k  = i - oc * KTOT;
    float f = Wfx[(size_t)k * 512 + oc];
    __nv_bfloat16 h = __float2bfloat16(f);
    float r = f - __bfloat162float(h);
    whi[i] = h;
    wlo[i] = __float2bfloat16(r);
}

// y<9:  W~[k][h*64+g] = (sum_d Wx[k][h*64+d]*Wslice[g][d]) / temp_h -> rows 512..1023
// y==9: lbias[h*64+g] = (bx_h · Wslice_g + bslice_g) / temp_h
__global__ void combine_w_kernel(const float* __restrict__ Wx,
                                 const float* __restrict__ Wsl,
                                 const float* __restrict__ bx,
                                 const float* __restrict__ bsl,
                                 const float* __restrict__ temp,
                                 __nv_bfloat16* __restrict__ whi,
                                 __nv_bfloat16* __restrict__ wlo,
                                 float* __restrict__ lb) {
    __shared__ float ws[64];
    const int col = blockIdx.x;          // 0..511
    const int h = col >> 6, g = col & 63;
    const int tid = threadIdx.x;         // 128
    if (tid < 64) ws[tid] = Wsl[g * 64 + tid];
    __syncthreads();
    float t = fminf(fmaxf(temp[h], 0.1f), 5.0f);
    float invt = 1.0f / t;

    if (blockIdx.y == 9) {
        if (tid < 32) {
            float s = bx[h * 64 + tid] * ws[tid]
                    + bx[h * 64 + 32 + tid] * ws[32 + tid];
            #pragma unroll
            for (int o = 16; o > 0; o >>= 1)
                s += __shfl_xor_sync(0xffffffffu, s, o);
            if (tid == 0) lb[col] = (s + bsl[g]) * invt;
        }
        return;
    }

    int k = blockIdx.y * 128 + tid;      // 9 y-blocks -> 0..1151
    const float* wr = Wx + (size_t)k * 512 + h * 64;
    float s = 0.f;
    #pragma unroll 8
    for (int d = 0; d < 64; d++) s += wr[d] * ws[d];
    s *= invt;
    __nv_bfloat16 hv = __float2bfloat16(s);
    size_t o = (size_t)(512 + col) * KTOT + k;
    whi[o] = hv;
    wlo[o] = __float2bfloat16(s - __bfloat162float(hv));
}

// ---------------- shared MMA plumbing ----------------
__device__ __forceinline__ void cp16(uint32_t saddr, const void* g, bool valid) {
    int sz = valid ? 16 : 0;
    asm volatile("cp.async.cg.shared.global [%0], [%1], 16, %2;\n"
                 :: "r"(saddr), "l"(g), "r"(sz));
}

__device__ __forceinline__ void mma_bf16(float c[4], uint32_t a0, uint32_t a1,
                                         uint32_t a2, uint32_t a3,
                                         uint32_t b0, uint32_t b1) {
    asm volatile(
        "mma.sync.aligned.m16n8k16.row.col.f32.bf16.bf16.f32 "
        "{%0,%1,%2,%3}, {%4,%5,%6,%7}, {%8,%9}, {%0,%1,%2,%3};"
        : "+f"(c[0]), "+f"(c[1]), "+f"(c[2]), "+f"(c[3])
        : "r"(a0), "r"(a1), "r"(a2), "r"(a3), "r"(b0), "r"(b1));
}

__device__ __forceinline__ void ldsm4(uint32_t r[4], uint32_t addr) {
    asm volatile("ldmatrix.sync.aligned.m8n8.x4.shared.b16 {%0,%1,%2,%3}, [%4];"
                 : "=r"(r[0]), "=r"(r[1]), "=r"(r[2]), "=r"(r[3]) : "r"(addr));
}

__device__ __forceinline__ void ldsm4t(uint32_t r[4], uint32_t addr) {
    asm volatile("ldmatrix.sync.aligned.m8n8.x4.trans.shared.b16 {%0,%1,%2,%3}, [%4];"
                 : "=r"(r[0]), "=r"(r[1]), "=r"(r[2]), "=r"(r[3]) : "r"(addr));
}

// packed kc=32 tile: 128 logical rows x 32 bf16, two logical rows per 128B phys row.
__device__ __forceinline__ uint32_t sw32(int row, int gr) {
    return (uint32_t)(row >> 1) * 128 +
           (uint32_t)(((gr | ((row & 1) << 2)) ^ ((row >> 1) & 7)) << 4);
}

// ---------------- conv: implicit GEMM 128x128, kc=32, 4 warps, 2 CTAs/SM ----------------
// ocb 0..3: fx output (cols ocb*128); ocb 4..7: slice-weight softmax (2 heads each).
// Stage (32KB): Ahi 8K | Alo 8K | Bhi 8K | Blo 8K. 3 stages = 96KB -> 2 CTAs/SM.
#define CSTAGE 32768
#define NCHUNK 36

__device__ __forceinline__ void conv_load(
    uint32_t st,
    const __nv_bfloat16* __restrict__ Xhi, const __nv_bfloat16* __restrict__ Xlo,
    const __nv_bfloat16* __restrict__ Whi, const __nv_bfloat16* __restrict__ Wlo,
    int it, int b, int hrow, int w0, int ocb, int tid)
{
    const int kg  = it * 32;
    const int tap = kg >> 7;
    const int dy = tap / 3 - 1, dx = tap % 3 - 1;
    const int c0 = kg & 127;            // 0/32/64/96
    const int hp = hrow + dy;
    const bool hok = (hp >= 0) && (hp < HH);
    const int hpc = hok ? hp : 0;

    // A: 2 arrays x 128 rows x 4 granules = 1024 lines (8 per thread)
    #pragma unroll
    for (int j = 0; j < 8; j++) {
        int id  = tid + j * 128;
        int arr = id >> 9;              // 0:Ahi 1:Alo
        int l   = id & 511;
        int row = l >> 2;
        int gr  = l & 3;
        uint32_t saddr = st + arr * 8192 + sw32(row, gr);
        int wp = w0 + row + dx;
        bool valid = hok && (wp >= 0) && (wp < WW);
        int wpc = valid ? wp : 0;
        const __nv_bfloat16* g = (arr == 0 ? Xhi : Xlo) +
            (((size_t)b * NN + (size_t)hpc * WW + wpc) * CC + c0 + gr * 8);
        cp16(saddr, g, valid);
    }
    // B: 2 arrays x 128 rows x 4 granules = 1024 lines (8 per thread)
    #pragma unroll
    for (int j = 0; j < 8; j++) {
        int id  = tid + j * 128;
        int arr = id >> 9;              // 0:Bhi 1:Blo
        int l   = id & 511;
        int row = l >> 2;
        int gr  = l & 3;
        uint32_t saddr = st + 16384 + arr * 8192 + sw32(row, gr);
        const __nv_bfloat16* g = (arr == 0 ? Whi : Wlo) +
            ((size_t)(ocb * 128 + row) * KTOT + kg + gr * 8);
        cp16(saddr, g, true);
    }
}

__global__ __launch_bounds__(128, 2)
void conv_mma_kernel(const __nv_bfloat16* __restrict__ Xhi,
                     const __nv_bfloat16* __restrict__ Xlo,
                     const __nv_bfloat16* __restrict__ Whi,
                     const __nv_bfloat16* __restrict__ Wlo,
                     const float* __restrict__ bfx,
                     const float* __restrict__ lbias,
                     __nv_bfloat16* __restrict__ fxhi,
                     __nv_bfloat16* __restrict__ swhi,
                     __nv_bfloat16* __restrict__ swlo)
{
    extern __shared__ char smem[];           // 3 stages x 32KB

    const int ocb = blockIdx.x;              // 0..7
    const int pt  = blockIdx.y;              // 0..511
    const int b   = blockIdx.z;
    const int n0  = pt * 128;
    const int hrow = n0 >> 8;
    const int w0   = n0 & 255;

    const int tid  = threadIdx.x;            // 0..127
    const int wid  = tid >> 5;               // 0..3
    const int lane = tid & 31;
    const int grp  = lane >> 2;
    const int tid4 = lane & 3;
    const int wm   = wid & 1;                // 2 row-groups of 64
    const int wn   = wid >> 1;               // 2 col-groups of 64

    const int t8   = lane >> 3;
    const int r8   = lane & 7;
    const int a_roff = ((t8 & 1) << 3) + r8;
    const int a_gsel = t8 >> 1;
    const int b_roff = ((t8 >> 1) << 3) + r8;
    const int b_gsel = t8 & 1;

    float acc[4][8][4];
    #pragma unroll
    for (int i = 0; i < 4; i++)
        #pragma unroll
        for (int j = 0; j < 8; j++)
            #pragma unroll
            for (int r = 0; r < 4; r++) acc[i][j][r] = 0.f;

    uint32_t sbase = (uint32_t)__cvta_generic_to_shared(smem);

    conv_load(sbase, Xhi, Xlo, Whi, Wlo, 0, b, hrow, w0, ocb, tid);
    asm volatile("cp.async.commit_group;\n" ::: "memory");
    conv_load(sbase + CSTAGE, Xhi, Xlo, Whi, Wlo, 1, b, hrow, w0, ocb, tid);
    asm volatile("cp.async.commit_group;\n" ::: "memory");

    for (int it = 0; it < NCHUNK; ++it) {
        const int cur = it % 3;
        if (it + 2 < NCHUNK)
            conv_load(sbase + (uint32_t)((it + 2) % 3) * CSTAGE,
                      Xhi, Xlo, Whi, Wlo, it + 2, b, hrow, w0, ocb, tid);
        asm volatile("cp.async.commit_group;\n" ::: "memory");
        asm volatile("cp.async.wait_group 2;\n" ::: "memory");
        __syncthreads();

        const uint32_t stA = sbase + (uint32_t)cur * CSTAGE;
        const uint32_t stB = stA + 16384;

        #pragma unroll
        for (int s = 0; s < 2; s++) {
            uint32_t ah[4][4], al[4][4];
            #pragma unroll
            for (int mi = 0; mi < 4; mi++) {
                int row = wm * 64 + mi * 16 + a_roff;
                int g = 2 * s + a_gsel;
                uint32_t addr = stA + sw32(row, g);
                ldsm4(ah[mi], addr);
                ldsm4(al[mi], addr + 8192);
            }
            #pragma unroll
            for (int np = 0; np < 4; np++) {
                int row = wn * 64 + np * 16 + b_roff;
                int g = 2 * s + b_gsel;
                uint32_t addr = stB + sw32(row, g);
                uint32_t bh[4], bl[4];
                ldsm4(bh, addr);
                ldsm4(bl, addr + 8192);
                #pragma unroll
                for (int mi = 0; mi < 4; mi++) {
                    mma_bf16(acc[mi][2 * np],     ah[mi][0], ah[mi][1], ah[mi][2], ah[mi][3], bh[0], bh[1]);
                    mma_bf16(acc[mi][2 * np + 1], ah[mi][0], ah[mi][1], ah[mi][2], ah[mi][3], bh[2], bh[3]);
                }
                #pragma unroll
                for (int mi = 0; mi < 4; mi++) {
                    mma_bf16(acc[mi][2 * np],     ah[mi][0], ah[mi][1], ah[mi][2], ah[mi][3], bl[0], bl[1]);
                    mma_bf16(acc[mi][2 * np + 1], ah[mi][0], ah[mi][1], ah[mi][2], ah[mi][3], bl[2], bl[3]);
                }
                #pragma unroll
                for (int mi = 0; mi < 4; mi++) {
                    mma_bf16(acc[mi][2 * np],     al[mi][0], al[mi][1], al[mi][2], al[mi][3], bh[0], bh[1]);
                    mma_bf16(acc[mi][2 * np + 1], al[mi][0], al[mi][1], al[mi][2], al[mi][3], bh[2], bh[3]);
                }
            }
        }
        __syncthreads();
    }

    if (ocb < 4) {
        // fx output: single bf16 with bias (cols ocb*128 .. +127)
        const int ocbase = ocb * 128;
        #pragma unroll
        for (int mi = 0; mi < 4; mi++) {
            int row = wm * 64 + mi * 16 + grp;
            int n  = n0 + row;
            #pragma unroll
            for (int ni = 0; ni < 8; ni++) {
                int col = wn * 64 + ni * 8 + tid4 * 2;
                int oc  = ocbase + col;
                float b0v = bfx[oc], b1v = bfx[oc + 1];
                __nv_bfloat162 p0;
                p0.x = __float2bfloat16(acc[mi][ni][0] + b0v);
                p0.y = __float2bfloat16(acc[mi][ni][1] + b1v);
                __nv_bfloat162 p1;
                p1.x = __float2bfloat16(acc[mi][ni][2] + b0v);
                p1.y = __float2bfloat16(acc[mi][ni][3] + b1v);
                *(__nv_bfloat162*)(fxhi + ((size_t)b * NN + n) * INNER + oc) = p0;
                *(__nv_bfloat162*)(fxhi + ((size_t)b * NN + n + 8) * INNER + oc) = p1;
            }
        }
    } else {
        // logits: stage to smem, softmax per (pixel, head), emit bf16 hi/lo
        float* sred = (float*)smem;          // [128][132] = 67.5KB <= 96KB
        #pragma unroll
        for (int mi = 0; mi < 4; mi++) {
            int row = wm * 64 + mi * 16 + grp;
            #pragma unroll
            for (int ni = 0; ni < 8; ni++) {
                int col = wn * 64 + ni * 8 + tid4 * 2;
                sred[row * 132 + col]           = acc[mi][ni][0];
                sred[row * 132 + col + 1]       = acc[mi][ni][1];
                sred[(row + 8) * 132 + col]     = acc[mi][ni][2];
                sred[(row + 8) * 132 + col + 1] = acc[mi][ni][3];
            }
        }
        __syncthreads();

        #pragma unroll
        for (int pass = 0; pass < 2; pass++) {
            int tsk = tid + pass * 128;      // 0..255
            int row  = tsk >> 1;
            int hloc = tsk & 1;
            int h = (ocb - 4) * 2 + hloc;
            int n = n0 + row;
            const float* lb = lbias + h * 64;
            float* sr = sred + row * 132 + hloc * 64;

            float mx = -1e30f;
            #pragma unroll 8
            for (int g = 0; g < 64; g++) mx = fmaxf(mx, sr[g] + lb[g]);
            float ssum = 0.f;
            #pragma unroll 8
            for (int g = 0; g < 64; g++) {
                float e = __expf(sr[g] + lb[g] - mx);
                ssum += e;
                sr[g] = e;
            }
            float inv = 1.0f / ssum;

            size_t base = ((size_t)(b * HEADS + h) * NN + n) * GG;
            #pragma unroll
            for (int c = 0; c < 8; c++) {
                union { __nv_bfloat16 hb[8]; uint4 u; } Uh, Ul;
                #pragma unroll
                for (int e = 0; e < 8; e++) {
                    float v = sr[c * 8 + e] * inv;
                    __nv_bfloat16 hv = __float2bfloat16(v);
                    Uh.hb[e] = hv;
                    Ul.hb[e] = __float2bfloat16(v - __bfloat162float(hv));
                }
                ((uint4*)(swhi + base))[c] = Uh.u;
                ((uint4*)(swlo + base))[c] = Ul.u;
            }
        }
    }
}

// ---------------- K3: token reduction on tensor cores (fx single bf16) ----------------
// Stage (6KB): whi 2K | wlo 2K | fx 2K. 2 stages.
__global__ __launch_bounds__(128)
void token_mma_kernel(const __nv_bfloat16* __restrict__ whi,
                      const __nv_bfloat16* __restrict__ wlo,
                      const __nv_bfloat16* __restrict__ fx,
                      float* __restrict__ tokp,
                      float* __restrict__ normp)
{
    __shared__ __align__(16) char smem[2 * 6144];

    const int bh = blockIdx.y;
    const int b = bh >> 3, h = bh & 7;
    const int split = blockIdx.x;
    const int nbase = split * CHUNK;

    const int tid  = threadIdx.x;
    const int wid  = tid >> 5;          // 0..3: g-strip wid*16
    const int lane = tid & 31;
    const int grp  = lane >> 2;
    const int tid4 = lane & 3;
    const int t8   = lane >> 3;
    const int r8   = lane & 7;
    const int lrow = r8 + ((t8 >> 1) << 3);   // 0..15
    const int lgr  = t8 & 1;

    const uint32_t ONES = 0x3F803F80u;  // bf16(1.0) x2

    float acc[8][4];
    #pragma unroll
    for (int j = 0; j < 8; j++)
        #pragma unroll
        for (int r = 0; r < 4; r++) acc[j][r] = 0.f;
    float accn[4] = {};

    uint32_t sbase = (uint32_t)__cvta_generic_to_shared(smem);

    // loader: 3 arrays x 16 rows x 8 granules = 384 lines / 128 threads = 3 each
    auto load = [&](uint32_t st, int t0) {
        #pragma unroll
        for (int j = 0; j < 3; j++) {
            int id  = tid + j * 128;
            int arr = id >> 7;          // 0:whi 1:wlo 2:fx
            int l   = id & 127;
            int row = l >> 3;
            int gr  = l & 7;
            uint32_t saddr = st + arr * 2048 + row * 128 + ((gr ^ (row & 7)) << 4);
            int n = nbase + t0 + row;
            const __nv_bfloat16* g;
            if (arr < 2) {
                g = (arr == 0 ? whi : wlo) + ((size_t)bh * NN + n) * GG + gr * 8;
            } else {
                g = fx + ((size_t)b * NN + n) * INNER + h * DH + gr * 8;
            }
            cp16(saddr, g, true);
        }
    };

    load(sbase, 0);
    asm volatile("cp.async.commit_group;\n" ::: "memory");

    for (int it = 0; it < 64; ++it) {
        const int cur = it & 1;
        if (it + 1 < 64) {
            load(sbase + (uint32_t)(1 - cur) * 6144, (it + 1) * 16);
            asm volatile("cp.async.commit_group;\n" ::: "memory");
            asm volatile("cp.async.wait_group 1;\n" ::: "memory");
        } else {
            asm volatile("cp.async.wait_group 0;\n" ::: "memory");
        }
        __syncthreads();

        const uint32_t st = sbase + (uint32_t)cur * 6144;

        uint32_t awh[4], awl[4];
        {
            int gr = wid * 2 + lgr;
            uint32_t addr = st + lrow * 128 + ((gr ^ (lrow & 7)) << 4);
            ldsm4t(awh, addr);
            ldsm4t(awl, addr + 2048);
        }
        mma_bf16(accn, awh[0], awh[1], awh[2], awh[3], ONES, ONES);
        mma_bf16(accn, awl[0], awl[1], awl[2], awl[3], ONES, ONES);

        #pragma unroll
        for (int j = 0; j < 4; j++) {
            int gr = j * 2 + lgr;
            uint32_t addr = st + 4096 + lrow * 128 + ((gr ^ (lrow & 7)) << 4);
            uint32_t bf[4];
            ldsm4t(bf, addr);
            mma_bf16(acc[2 * j],     awh[0], awh[1], awh[2], awh[3], bf[0], bf[2]);
            mma_bf16(acc[2 * j + 1], awh[0], awh[1], awh[2], awh[3], bf[1], bf[3]);
            mma_bf16(acc[2 * j],     awl[0], awl[1], awl[2], awl[3], bf[0], bf[2]);
            mma_bf16(acc[2 * j + 1], awl[0], awl[1], awl[2], awl[3], bf[1], bf[3]);
        }
        __syncthreads();
    }

    const size_t base = ((size_t)split * (BB * HEADS) + bh) * (GG * DH);
    const int g0 = wid * 16 + grp;
    #pragma unroll
    for (int nf = 0; nf < 8; nf++) {
        int d = (nf >> 1) * 16 + (nf & 1) * 8 + tid4 * 2;
        tokp[base + (size_t)g0 * DH + d]           = acc[nf][0];
        tokp[base + (size_t)g0 * DH + d + 1]       = acc[nf][1];
        tokp[base + (size_t)(g0 + 8) * DH + d]     = acc[nf][2];
        tokp[base + (size_t)(g0 + 8) * DH + d + 1] = acc[nf][3];
    }
    if (tid4 == 0) {
        size_t nb = ((size_t)split * (BB * HEADS) + bh) * GG;
        normp[nb + g0]     = accn[0];
        normp[nb + g0 + 8] = accn[2];
    }
}

// ---------------- K3b: deterministic split reduction ----------------
__global__ void split_reduce_kernel(const float* __restrict__ tokp,
                                    const float* __restrict__ normp,
                                    float* __restrict__ tok,
                                    float* __restrict__ norm) {
    const int blk = blockIdx.x;
    const int tid = threadIdx.x;
    if (blk < 256) {
        int idx = blk * 256 + tid;
        float s = 0.f;
        #pragma unroll 8
        for (int sp = 0; sp < SPLITS; sp++)
            s += tokp[(size_t)sp * 65536 + idx];
        tok[idx] = s;
    } else {
        int idx = (blk - 256) * 256 + tid;
        float s = 0.f;
        #pragma unroll 8
        for (int sp = 0; sp < SPLITS; sp++)
            s += normp[(size_t)sp * 1024 + idx];
        norm[idx] = s;
    }
}

// ---------------- K4: tiny attention per (b,h), emits Mt bf16 hi/lo ----------------
__global__ void attn_kernel(const float* __restrict__ tok,
                            const float* __restrict__ norm,
                            const float* __restrict__ Wq,
                            const float* __restrict__ Wk,
                            const float* __restrict__ Wv,
                            const float* __restrict__ Wout,
                            __nv_bfloat16* __restrict__ Mthi,
                            __nv_bfloat16* __restrict__ Mtlo) {
    const int bh = blockIdx.x;
    const int b = bh >> 3, h = bh & 7;
    const int tx = threadIdx.x, ty = threadIdx.y;
    const int tid = ty * 16 + tx;

    __shared__ float A[64][65];
    __shared__ float Bm[64][65];
    __shared__ float Cm[64][65];

    #pragma unroll
    for (int e = 0; e < 16; e++) {
        int idx = tid + e * 256;
        int g = idx >> 6, d = idx & 63;
        A[g][d] = tok[(size_t)bh * 4096 + idx] / (norm[bh * 64 + g] + 1e-5f);
    }
    __syncthreads();

    {
        float aq[4][4] = {}, ak[4][4] = {};
        #pragma unroll
        for (int kk = 0; kk < 64; kk++) {
            float a[4];
            #pragma unroll
            for (int i = 0; i < 4; i++) a[i] = A[ty + 16 * i][kk];
            #pragma unroll
            for (int j = 0; j < 4; j++) {
                float wq = __ldg(&Wq[(tx + 16 * j) * 64 + kk]);
                float wk = __ldg(&Wk[(tx + 16 * j) * 64 + kk]);
                #pragma unroll
                for (int i = 0; i < 4; i++) {
                    aq[i][j] += a[i] * wq;
                    ak[i][j] += a[i] * wk;
                }
            }
        }
        #pragma unroll
        for (int i = 0; i < 4; i++)
            #pragma unroll
            for (int j = 0; j < 4; j++) {
                Bm[ty + 16 * i][tx + 16 * j] = aq[i][j];
                Cm[ty + 16 * i][tx + 16 * j] = ak[i][j];
            }
    }
    __syncthreads();

    {
        float L[4][4] = {};
        #pragma unroll
        for (int kk = 0; kk < 64; kk++) {
            float a[4], bv[4];
            #pragma unroll
            for (int i = 0; i < 4; i++) a[i] = Bm[ty + 16 * i][kk];
            #pragma unroll
            for (int j = 0; j < 4; j++) bv[j] = Cm[tx + 16 * j][kk];
            #pragma unroll
            for (int i = 0; i < 4; i++)
                #pragma unroll
                for (int j = 0; j < 4; j++)
                    L[i][j] += a[i] * bv[j];
        }
        #pragma unroll
        for (int i = 0; i < 4; i++) {
            #pragma unroll
            for (int j = 0; j < 4; j++) L[i][j] *= 0.125f;
            float mx = L[i][0];
            #pragma unroll
            for (int j = 1; j < 4; j++) mx = fmaxf(mx, L[i][j]);
            #pragma unroll
            for (int o = 1; o < 16; o <<= 1)
                mx = fmaxf(mx, __shfl_xor_sync(0xffffffffu, mx, o, 16));
            float s = 0.f;
            #pragma unroll
            for (int j = 0; j < 4; j++) { L[i][j] = __expf(L[i][j] - mx); s += L[i][j]; }
            #pragma unroll
            for (int o = 1; o < 16; o <<= 1)
                s += __shfl_xor_sync(0xffffffffu, s, o, 16);
            float inv = 1.0f / s;
            #pragma unroll
            for (int j = 0; j < 4; j++)
                A[ty + 16 * i][tx + 16 * j] = L[i][j] * inv;
        }
    }
    __syncthreads();

    #pragma unroll
    for (int e = 0; e < 16; e++) {
        int idx = tid + e * 256;
        int g = idx >> 6;
        Bm[g][idx & 63] = tok[(size_t)bh * 4096 + idx] / (norm[bh * 64 + g] + 1e-5f);
    }
    __syncthreads();

    {
        float av[4][4] = {};
        #pragma unroll
        for (int kk = 0; kk < 64; kk++) {
            float a[4];
            #pragma unroll
            for (int i = 0; i < 4; i++) a[i] = Bm[ty + 16 * i][kk];
            #pragma unroll
            for (int j = 0; j < 4; j++) {
                float wv = __ldg(&Wv[(tx + 16 * j) * 64 + kk]);
                #pragma unroll
                for (int i = 0; i < 4; i++) av[i][j] += a[i] * wv;
            }
        }
        __syncthreads();
        #pragma unroll
        for (int i = 0; i < 4; i++)
            #pragma unroll
            for (int j = 0; j < 4; j++)
                Cm[ty + 16 * i][tx + 16 * j] = av[i][j];
    }
    __syncthreads();

    {
        float ao[4][4] = {};
        #pragma unroll
        for (int kk = 0; kk < 64; kk++) {
            float a[4], bv[4];
            #pragma unroll
            for (int i = 0; i < 4; i++) a[i] = A[ty + 16 * i][kk];
            #pragma unroll
            for (int j = 0; j < 4; j++) bv[j] = Cm[kk][tx + 16 * j];
            #pragma unroll
            for (int i = 0; i < 4; i++)
                #pragma unroll
                for (int j = 0; j < 4; j++)
                    ao[i][j] += a[i] * bv[j];
        }
        __syncthreads();
        #pragma unroll
        for (int i = 0; i < 4; i++)
            #pragma unroll
            for (int j = 0; j < 4; j++)
                Bm[ty + 16 * i][tx + 16 * j] = ao[i][j];
    }
    __syncthreads();

    {
        float am[4][8] = {};
        #pragma unroll
        for (int kk = 0; kk < 64; kk++) {
            float a[4];
            #pragma unroll
            for (int i = 0; i < 4; i++) a[i] = Bm[ty + 16 * i][kk];
            #pragma unroll
            for (int j = 0; j < 8; j++) {
                float wv = __ldg(&Wout[(size_t)(tx + 16 * j) * INNER + h * DH + kk]);
                #pragma unroll
                for (int i = 0; i < 4; i++) am[i][j] += a[i] * wv;
            }
        }
        #pragma unroll
        for (int i = 0; i < 4; i++) {
            int g = ty + 16 * i;
            #pragma unroll
            for (int j = 0; j < 8; j++) {
                int o = tx + 16 * j;
                float v = am[i][j];
                __nv_bfloat16 hv = __float2bfloat16(v);
                float r = v - __bfloat162float(hv);
                size_t idx = ((size_t)b * CC + o) * INNER + h * DH + g;
                Mthi[idx] = hv;
                Mtlo[idx] = __float2bfloat16(r);
            }
        }
    }
}

// ---------------- K5: fused scatter + projection, kc=64, ldmatrix ----------------
#define FSTAGE 65536

__global__ __launch_bounds__(256)
void final_mma_kernel(const __nv_bfloat16* __restrict__ Whi,
                      const __nv_bfloat16* __restrict__ Wlo,
                      const __nv_bfloat16* __restrict__ Mthi,
                      const __nv_bfloat16* __restrict__ Mtlo,
                      const float* __restrict__ bout,
                      float* __restrict__ out)
{
    extern __shared__ char smem[];

    const int pt = blockIdx.x;
    const int b  = pt >> 9;
    const int n0 = (pt & 511) * 128;

    const int tid  = threadIdx.x;
    const int wid  = tid >> 5;
    const int lane = tid & 31;
    const int grp  = lane >> 2;
    const int tid4 = lane & 3;
    const int wm   = wid & 1;                // 2 row-groups of 64
    const int wn   = wid >> 1;               // 4 col-groups of 32

    const int t8   = lane >> 3;
    const int r8   = lane & 7;
    const int a_roff = ((t8 & 1) << 3) + r8;
    const int a_gsel = t8 >> 1;
    const int b_roff = ((t8 >> 1) << 3) + r8;
    const int b_gsel = t8 & 1;

    float acc[4][4][4];
    #pragma unroll
    for (int i = 0; i < 4; i++)
        #pragma unroll
        for (int j = 0; j < 4; j++)
            #pragma unroll
            for (int r = 0; r < 4; r++) acc[i][j][r] = 0.f;

    uint32_t sbase = (uint32_t)__cvta_generic_to_shared(smem);

    auto load_fin = [&](uint32_t st, int h) {
        #pragma unroll
        for (int j = 0; j < 16; j++) {
            int id  = tid + j * 256;
            int arr = id >> 10;              // 0:whi 1:wlo 2:Mthi 3:Mtlo
            int l   = id & 1023;
            int row = l >> 3;
            int gr  = l & 7;
            uint32_t saddr = st + arr * 16384 + row * 128 + ((gr ^ (row & 7)) << 4);
            const __nv_bfloat16* g;
            if (arr < 2) {
                g = (arr == 0 ? Whi : Wlo) +
                    (((size_t)(b * HEADS + h) * NN) + n0 + row) * GG + gr * 8;
            } else {
                g = (arr == 2 ? Mthi : Mtlo) +
                    ((size_t)b * CC + row) * INNER + h * DH + gr * 8;
            }
            cp16(saddr, g, true);
        }
    };

    load_fin(sbase, 0);
    asm volatile("cp.async.commit_group;\n" ::: "memory");

    for (int it = 0; it < 8; ++it) {
        const int cur = it & 1;
        if (it + 1 < 8) {
            load_fin(sbase + (uint32_t)(1 - cur) * FSTAGE, it + 1);
            asm volatile("cp.async.commit_group;\n" ::: "memory");
            asm volatile("cp.async.wait_group 1;\n" ::: "memory");
        } else {
            asm volatile("cp.async.wait_group 0;\n" ::: "memory");
        }
        __syncthreads();

        const uint32_t stA = sbase + (uint32_t)cur * FSTAGE;
        const uint32_t stB = stA + 32768;

        #pragma unroll
        for (int s = 0; s < 4; s++) {
            uint32_t ah[4][4], al[4][4];
            #pragma unroll
            for (int mi = 0; mi < 4; mi++) {
                int row = wm * 64 + mi * 16 + a_roff;
                int g = 2 * s + a_gsel;
                uint32_t addr = stA + row * 128 + ((g ^ (row & 7)) << 4);
                ldsm4(ah[mi], addr);
                ldsm4(al[mi], addr + 16384);
            }
            #pragma unroll
            for (int np = 0; np < 2; np++) {
                int row = wn * 32 + np * 16 + b_roff;
                int g = 2 * s + b_gsel;
                uint32_t addr = stB + row * 128 + ((g ^ (row & 7)) << 4);
                uint32_t bh[4], bl[4];
                ldsm4(bh, addr);
                ldsm4(bl, addr + 16384);
                #pragma unroll
                for (int mi = 0; mi < 4; mi++) {
                    mma_bf16(acc[mi][2 * np],     ah[mi][0], ah[mi][1], ah[mi][2], ah[mi][3], bh[0], bh[1]);
                    mma_bf16(acc[mi][2 * np + 1], ah[mi][0], ah[mi][1], ah[mi][2], ah[mi][3], bh[2], bh[3]);
                }
                #pragma unroll
                for (int mi = 0; mi < 4; mi++) {
                    mma_bf16(acc[mi][2 * np],     ah[mi][0], ah[mi][1], ah[mi][2], ah[mi][3], bl[0], bl[1]);
                    mma_bf16(acc[mi][2 * np + 1], ah[mi][0], ah[mi][1], ah[mi][2], ah[mi][3], bl[2], bl[3]);
                }
                #pragma unroll
                for (int mi = 0; mi < 4; mi++) {
                    mma_bf16(acc[mi][2 * np],     al[mi][0], al[mi][1], al[mi][2], al[mi][3], bh[0], bh[1]);
                    mma_bf16(acc[mi][2 * np + 1], al[mi][0], al[mi][1], al[mi][2], al[mi][3], bh[2], bh[3]);
                }
            }
        }
        __syncthreads();
    }

    #pragma unroll
    for (int mi = 0; mi < 4; mi++) {
        int row = wm * 64 + mi * 16 + grp;
        int n  = n0 + row;
        #pragma unroll
        for (int ni = 0; ni < 4; ni++) {
            int oc = wn * 32 + ni * 8 + tid4 * 2;
            float b0v = bout[oc], b1v = bout[oc + 1];
            size_t base0 = ((size_t)b * NN + n) * CC + oc;
            out[base0]     = acc[mi][ni][0] + b0v;
            out[base0 + 1] = acc[mi][ni][1] + b1v;
            size_t base1 = ((size_t)b * NN + n + 8) * CC + oc;
            out[base1]     = acc[mi][ni][2] + b0v;
            out[base1 + 1] = acc[mi][ni][3] + b1v;
        }
    }
}

// ---------------- launch ----------------
extern "C" void kernel_launch(void* const* d_in, const int* in_sizes, int n_in,
                              void* d_out, int out_size) {
    const float* x     = (const float*)d_in[0];
    const float* Wfx   = (const float*)d_in[1];
    const float* bfx   = (const float*)d_in[2];
    const float* Wx    = (const float*)d_in[3];
    const float* bx    = (const float*)d_in[4];
    const float* Wsl   = (const float*)d_in[5];
    const float* bsl   = (const float*)d_in[6];
    const float* temp  = (const float*)d_in[7];
    const float* Wq    = (const float*)d_in[8];
    const float* Wk    = (const float*)d_in[9];
    const float* Wv    = (const float*)d_in[10];
    const float* Wout  = (const float*)d_in[11];
    const float* bout  = (const float*)d_in[12];
    float* out = (float*)d_out;

    float *p_tokp, *p_normp, *p_tok, *p_norm, *p_lb;
    __nv_bfloat16 *p_xhi, *p_xlo, *p_whi, *p_wlo;
    __nv_bfloat16 *p_fxhi;
    __nv_bfloat16 *p_swhi, *p_swlo, *p_Mthi, *p_Mtlo;
    cudaGetSymbolAddress((void**)&p_tokp, g_tokp);
    cudaGetSymbolAddress((void**)&p_normp, g_normp);
    cudaGetSymbolAddress((void**)&p_tok, g_tok);
    cudaGetSymbolAddress((void**)&p_norm, g_norm);
    cudaGetSymbolAddress((void**)&p_lb, g_lbias);
    cudaGetSymbolAddress((void**)&p_xhi, g_xhi);
    cudaGetSymbolAddress((void**)&p_xlo, g_xlo);
    cudaGetSymbolAddress((void**)&p_whi, g_whi);
    cudaGetSymbolAddress((void**)&p_wlo, g_wlo);
    cudaGetSymbolAddress((void**)&p_fxhi, g_fxhi);
    cudaGetSymbolAddress((void**)&p_swhi, g_swhi);
    cudaGetSymbolAddress((void**)&p_swlo, g_swlo);
    cudaGetSymbolAddress((void**)&p_Mthi, g_Mthi);
    cudaGetSymbolAddress((void**)&p_Mtlo, g_Mtlo);

    static bool attr_set = false;
    if (!attr_set) {
        cudaFuncSetAttribute(conv_mma_kernel,
                             cudaFuncAttributeMaxDynamicSharedMemorySize, 3 * CSTAGE);
        cudaFuncSetAttribute(final_mma_kernel,
                             cudaFuncAttributeMaxDynamicSharedMemorySize, 2 * FSTAGE);
        attr_set = true;
    }

    dim3 blk(16, 16);

    // 0. staging (3 launches; conv is launch #4 for ncu visibility)
    split_x_kernel<<<(BB * NN * CC) / 256, 256>>>(x, p_xhi, p_xlo);
    split_w_kernel<<<(512 * KTOT) / 256, 256>>>(Wfx, p_whi, p_wlo);
    combine_w_kernel<<<dim3(512, 10), 128>>>(Wx, Wsl, bx, bsl, temp, p_whi, p_wlo, p_lb);

    // 1. fused conv (launch #4): 128x128 tiles, 4 warps, 2 CTAs/SM, 3-stage
    conv_mma_kernel<<<dim3(8, 512, BB), 128, 3 * CSTAGE>>>(
        p_xhi, p_xlo, p_whi, p_wlo, bfx, p_lb, p_fxhi, p_swhi, p_swlo);

    // 2. slice token reduction on tensor cores + split reduce
    token_mma_kernel<<<dim3(SPLITS, BB * HEADS), 128>>>(
        p_swhi, p_swlo, p_fxhi, p_tokp, p_normp);
    split_reduce_kernel<<<260, 256>>>(p_tokp, p_normp, p_tok, p_norm);

    // 3. tiny attention + fused Wout fold -> Mt (bf16 hi/lo)
    attn_kernel<<<BB * HEADS, blk>>>(p_tok, p_norm, Wq, Wk, Wv, Wout, p_Mthi, p_Mtlo);

    // 4. fused scatter + projection, kc=64 + ldmatrix
    final_mma_kernel<<<1024, 256, 2 * FSTAGE>>>(p_swhi, p_swlo, p_Mthi, p_Mtlo, bout, out);
}

// round 13
// speedup vs baseline: 1.2292x; 1.0050x over previous
#include <cuda_runtime.h>
#include <cuda_bf16.h>
#include <math.h>
#include <stdint.h>

// Problem constants
#define BB 2
#define HH 256
#define WW 256
#define NN 65536          // H*W
#define CC 128
#define HEADS 8
#define DH 64             // dim_head
#define GG 64             // SLICE
#define INNER 512         // HEADS*DH
#define SPLITS 64         // split-K for token reduction
#define CHUNK 1024        // tokens per split (NN/SPLITS)
#define KTOT 1152         // 9 taps * 128 channels

// ---------------- device scratch (static, no allocs) ----------------
__device__ float g_tokp[(size_t)SPLITS * BB * HEADS * GG * DH];
__device__ float g_normp[(size_t)SPLITS * BB * HEADS * GG];
__device__ float g_tok [(size_t)BB * HEADS * GG * DH];
__device__ float g_norm[(size_t)BB * HEADS * GG];
__device__ float g_lbias[INNER];                     // (bx·Wslice + bslice)/temp

// fx_mid as single bf16  [b][n][inner]
__device__ __align__(16) __nv_bfloat16 g_fxhi[(size_t)BB * NN * INNER];
// slice weights as bf16 hi/lo pair  [bh][n][g]
__device__ __align__(16) __nv_bfloat16 g_swhi[(size_t)BB * HEADS * NN * GG];
__device__ __align__(16) __nv_bfloat16 g_swlo[(size_t)BB * HEADS * NN * GG];
// Mt = (out_slice · Wout^T) transposed: [b][o][h*64+g], bf16 hi/lo
__device__ __align__(16) __nv_bfloat16 g_Mthi[(size_t)BB * CC * INNER];
__device__ __align__(16) __nv_bfloat16 g_Mtlo[(size_t)BB * CC * INNER];

// bf16 3-split staging for conv
__device__ __align__(16) __nv_bfloat16 g_xhi[(size_t)BB * NN * CC];
__device__ __align__(16) __nv_bfloat16 g_xlo[(size_t)BB * NN * CC];
// rows 0..511: Wfx cols; rows 512..1023: combined logit weights (Wx·Wslice/temp)
__device__ __align__(16) __nv_bfloat16 g_whi[(size_t)1024 * KTOT];
__device__ __align__(16) __nv_bfloat16 g_wlo[(size_t)1024 * KTOT];

// ---------------- prep kernels ----------------
__global__ void split_x_kernel(const float* __restrict__ x,
                               __nv_bfloat16* __restrict__ xhi,
                               __nv_bfloat16* __restrict__ xlo) {
    size_t i = (size_t)blockIdx.x * 256 + threadIdx.x;
    float f = x[i];
    __nv_bfloat16 h = __float2bfloat16(f);
    float r = f - __bfloat162float(h);
    xhi[i] = h;
    xlo[i] = __float2bfloat16(r);
}

__global__ void split_w_kernel(const float* __restrict__ Wfx,
                               __nv_bfloat16* __restrict__ whi,
                               __nv_bfloat16* __restrict__ wlo) {
    int i = blockIdx.x * 256 + threadIdx.x;   // 512*1152 total
    int oc = i / KTOT;
    int k  = i - oc * KTOT;
    float f = Wfx[(size_t)k * 512 + oc];
    __nv_bfloat16 h = __float2bfloat16(f);
    float r = f - __bfloat162float(h);
    whi[i] = h;
    wlo[i] = __float2bfloat16(r);
}

__global__ void combine_w_kernel(const float* __restrict__ Wx,
                                 const float* __restrict__ Wsl,
                                 const float* __restrict__ bx,
                                 const float* __restrict__ bsl,
                                 const float* __restrict__ temp,
                                 __nv_bfloat16* __restrict__ whi,
                                 __nv_bfloat16* __restrict__ wlo,
                                 float* __restrict__ lb) {
    __shared__ float ws[64];
    const int col = blockIdx.x;          // 0..511
    const int h = col >> 6, g = col & 63;
    const int tid = threadIdx.x;         // 128
    if (tid < 64) ws[tid] = Wsl[g * 64 + tid];
    __syncthreads();
    float t = fminf(fmaxf(temp[h], 0.1f), 5.0f);
    float invt = 1.0f / t;

    if (blockIdx.y == 9) {
        if (tid < 32) {
            float s = bx[h * 64 + tid] * ws[tid]
                    + bx[h * 64 + 32 + tid] * ws[32 + tid];
            #pragma unroll
            for (int o = 16; o > 0; o >>= 1)
                s += __shfl_xor_sync(0xffffffffu, s, o);
            if (tid == 0) lb[col] = (s + bsl[g]) * invt;
        }
        return;
    }

    int k = blockIdx.y * 128 + tid;      // 9 y-blocks -> 0..1151
    const float* wr = Wx + (size_t)k * 512 + h * 64;
    float s = 0.f;
    #pragma unroll 8
    for (int d = 0; d < 64; d++) s += wr[d] * ws[d];
    s *= invt;
    __nv_bfloat16 hv = __float2bfloat16(s);
    size_t o = (size_t)(512 + col) * KTOT + k;
    whi[o] = hv;
    wlo[o] = __float2bfloat16(s - __bfloat162float(hv));
}

// ---------------- shared MMA plumbing ----------------
__device__ __forceinline__ void cp16(uint32_t saddr, const void* g, bool valid) {
    int sz = valid ? 16 : 0;
    asm volatile("cp.async.cg.shared.global [%0], [%1], 16, %2;\n"
                 :: "r"(saddr), "l"(g), "r"(sz));
}

__device__ __forceinline__ void mma_bf16(float c[4], uint32_t a0, uint32_t a1,
                                         uint32_t a2, uint32_t a3,
                                         uint32_t b0, uint32_t b1) {
    asm volatile(
        "mma.sync.aligned.m16n8k16.row.col.f32.bf16.bf16.f32 "
        "{%0,%1,%2,%3}, {%4,%5,%6,%7}, {%8,%9}, {%0,%1,%2,%3};"
        : "+f"(c[0]), "+f"(c[1]), "+f"(c[2]), "+f"(c[3])
        : "r"(a0), "r"(a1), "r"(a2), "r"(a3), "r"(b0), "r"(b1));
}

__device__ __forceinline__ void ldsm4(uint32_t r[4], uint32_t addr) {
    asm volatile("ldmatrix.sync.aligned.m8n8.x4.shared.b16 {%0,%1,%2,%3}, [%4];"
                 : "=r"(r[0]), "=r"(r[1]), "=r"(r[2]), "=r"(r[3]) : "r"(addr));
}

__device__ __forceinline__ void ldsm4t(uint32_t r[4], uint32_t addr) {
    asm volatile("ldmatrix.sync.aligned.m8n8.x4.trans.shared.b16 {%0,%1,%2,%3}, [%4];"
                 : "=r"(r[0]), "=r"(r[1]), "=r"(r[2]), "=r"(r[3]) : "r"(addr));
}

// packed kc=32 tile: 128 logical rows x 32 bf16, two logical rows per 128B phys row.
__device__ __forceinline__ uint32_t sw32(int row, int gr) {
    return (uint32_t)(row >> 1) * 128 +
           (uint32_t)(((gr | ((row & 1) << 2)) ^ ((row >> 1) & 7)) << 4);
}

// ---------------- conv: implicit GEMM 128x128, kc=32, 4 warps, 2 CTAs/SM ----------------
#define CSTAGE 32768
#define NCHUNK 36

__device__ __forceinline__ void conv_load(
    uint32_t st,
    const __nv_bfloat16* __restrict__ Xhi, const __nv_bfloat16* __restrict__ Xlo,
    const __nv_bfloat16* __restrict__ Whi, const __nv_bfloat16* __restrict__ Wlo,
    int it, int b, int hrow, int w0, int ocb, int tid)
{
    const int kg  = it * 32;
    const int tap = kg >> 7;
    const int dy = tap / 3 - 1, dx = tap % 3 - 1;
    const int c0 = kg & 127;            // 0/32/64/96
    const int hp = hrow + dy;
    const bool hok = (hp >= 0) && (hp < HH);
    const int hpc = hok ? hp : 0;

    #pragma unroll
    for (int j = 0; j < 8; j++) {
        int id  = tid + j * 128;
        int arr = id >> 9;              // 0:Ahi 1:Alo
        int l   = id & 511;
        int row = l >> 2;
        int gr  = l & 3;
        uint32_t saddr = st + arr * 8192 + sw32(row, gr);
        int wp = w0 + row + dx;
        bool valid = hok && (wp >= 0) && (wp < WW);
        int wpc = valid ? wp : 0;
        const __nv_bfloat16* g = (arr == 0 ? Xhi : Xlo) +
            (((size_t)b * NN + (size_t)hpc * WW + wpc) * CC + c0 + gr * 8);
        cp16(saddr, g, valid);
    }
    #pragma unroll
    for (int j = 0; j < 8; j++) {
        int id  = tid + j * 128;
        int arr = id >> 9;              // 0:Bhi 1:Blo
        int l   = id & 511;
        int row = l >> 2;
        int gr  = l & 3;
        uint32_t saddr = st + 16384 + arr * 8192 + sw32(row, gr);
        const __nv_bfloat16* g = (arr == 0 ? Whi : Wlo) +
            ((size_t)(ocb * 128 + row) * KTOT + kg + gr * 8);
        cp16(saddr, g, true);
    }
}

__global__ __launch_bounds__(128, 2)
void conv_mma_kernel(const __nv_bfloat16* __restrict__ Xhi,
                     const __nv_bfloat16* __restrict__ Xlo,
                     const __nv_bfloat16* __restrict__ Whi,
                     const __nv_bfloat16* __restrict__ Wlo,
                     const float* __restrict__ bfx,
                     const float* __restrict__ lbias,
                     __nv_bfloat16* __restrict__ fxhi,
                     __nv_bfloat16* __restrict__ swhi,
                     __nv_bfloat16* __restrict__ swlo)
{
    extern __shared__ char smem[];           // 3 stages x 32KB

    const int ocb = blockIdx.x;              // 0..7
    const int pt  = blockIdx.y;              // 0..511
    const int b   = blockIdx.z;
    const int n0  = pt * 128;
    const int hrow = n0 >> 8;
    const int w0   = n0 & 255;

    const int tid  = threadIdx.x;            // 0..127
    const int wid  = tid >> 5;               // 0..3
    const int lane = tid & 31;
    const int grp  = lane >> 2;
    const int tid4 = lane & 3;
    const int wm   = wid & 1;                // 2 row-groups of 64
    const int wn   = wid >> 1;               // 2 col-groups of 64

    const int t8   = lane >> 3;
    const int r8   = lane & 7;
    const int a_roff = ((t8 & 1) << 3) + r8;
    const int a_gsel = t8 >> 1;
    const int b_roff = ((t8 >> 1) << 3) + r8;
    const int b_gsel = t8 & 1;

    float acc[4][8][4];
    #pragma unroll
    for (int i = 0; i < 4; i++)
        #pragma unroll
        for (int j = 0; j < 8; j++)
            #pragma unroll
            for (int r = 0; r < 4; r++) acc[i][j][r] = 0.f;

    uint32_t sbase = (uint32_t)__cvta_generic_to_shared(smem);

    conv_load(sbase, Xhi, Xlo, Whi, Wlo, 0, b, hrow, w0, ocb, tid);
    asm volatile("cp.async.commit_group;\n" ::: "memory");
    conv_load(sbase + CSTAGE, Xhi, Xlo, Whi, Wlo, 1, b, hrow, w0, ocb, tid);
    asm volatile("cp.async.commit_group;\n" ::: "memory");

    for (int it = 0; it < NCHUNK; ++it) {
        const int cur = it % 3;
        if (it + 2 < NCHUNK)
            conv_load(sbase + (uint32_t)((it + 2) % 3) * CSTAGE,
                      Xhi, Xlo, Whi, Wlo, it + 2, b, hrow, w0, ocb, tid);
        asm volatile("cp.async.commit_group;\n" ::: "memory");
        asm volatile("cp.async.wait_group 2;\n" ::: "memory");
        __syncthreads();

        const uint32_t stA = sbase + (uint32_t)cur * CSTAGE;
        const uint32_t stB = stA + 16384;

        #pragma unroll
        for (int s = 0; s < 2; s++) {
            uint32_t ah[4][4], al[4][4];
            #pragma unroll
            for (int mi = 0; mi < 4; mi++) {
                int row = wm * 64 + mi * 16 + a_roff;
                int g = 2 * s + a_gsel;
                uint32_t addr = stA + sw32(row, g);
                ldsm4(ah[mi], addr);
                ldsm4(al[mi], addr + 8192);
            }
            #pragma unroll
            for (int np = 0; np < 4; np++) {
                int row = wn * 64 + np * 16 + b_roff;
                int g = 2 * s + b_gsel;
                uint32_t addr = stB + sw32(row, g);
                uint32_t bh[4], bl[4];
                ldsm4(bh, addr);
                ldsm4(bl, addr + 8192);
                #pragma unroll
                for (int mi = 0; mi < 4; mi++) {
                    mma_bf16(acc[mi][2 * np],     ah[mi][0], ah[mi][1], ah[mi][2], ah[mi][3], bh[0], bh[1]);
                    mma_bf16(acc[mi][2 * np + 1], ah[mi][0], ah[mi][1], ah[mi][2], ah[mi][3], bh[2], bh[3]);
                }
                #pragma unroll
                for (int mi = 0; mi < 4; mi++) {
                    mma_bf16(acc[mi][2 * np],     ah[mi][0], ah[mi][1], ah[mi][2], ah[mi][3], bl[0], bl[1]);
                    mma_bf16(acc[mi][2 * np + 1], ah[mi][0], ah[mi][1], ah[mi][2], ah[mi][3], bl[2], bl[3]);
                }
                #pragma unroll
                for (int mi = 0; mi < 4; mi++) {
                    mma_bf16(acc[mi][2 * np],     al[mi][0], al[mi][1], al[mi][2], al[mi][3], bh[0], bh[1]);
                    mma_bf16(acc[mi][2 * np + 1], al[mi][0], al[mi][1], al[mi][2], al[mi][3], bh[2], bh[3]);
                }
            }
        }
        __syncthreads();
    }

    if (ocb < 4) {
        const int ocbase = ocb * 128;
        #pragma unroll
        for (int mi = 0; mi < 4; mi++) {
            int row = wm * 64 + mi * 16 + grp;
            int n  = n0 + row;
            #pragma unroll
            for (int ni = 0; ni < 8; ni++) {
                int col = wn * 64 + ni * 8 + tid4 * 2;
                int oc  = ocbase + col;
                float b0v = bfx[oc], b1v = bfx[oc + 1];
                __nv_bfloat162 p0;
                p0.x = __float2bfloat16(acc[mi][ni][0] + b0v);
                p0.y = __float2bfloat16(acc[mi][ni][1] + b1v);
                __nv_bfloat162 p1;
                p1.x = __float2bfloat16(acc[mi][ni][2] + b0v);
                p1.y = __float2bfloat16(acc[mi][ni][3] + b1v);
                *(__nv_bfloat162*)(fxhi + ((size_t)b * NN + n) * INNER + oc) = p0;
                *(__nv_bfloat162*)(fxhi + ((size_t)b * NN + n + 8) * INNER + oc) = p1;
            }
        }
    } else {
        float* sred = (float*)smem;          // [128][132]
        #pragma unroll
        for (int mi = 0; mi < 4; mi++) {
            int row = wm * 64 + mi * 16 + grp;
            #pragma unroll
            for (int ni = 0; ni < 8; ni++) {
                int col = wn * 64 + ni * 8 + tid4 * 2;
                sred[row * 132 + col]           = acc[mi][ni][0];
                sred[row * 132 + col + 1]       = acc[mi][ni][1];
                sred[(row + 8) * 132 + col]     = acc[mi][ni][2];
                sred[(row + 8) * 132 + col + 1] = acc[mi][ni][3];
            }
        }
        __syncthreads();

        #pragma unroll
        for (int pass = 0; pass < 2; pass++) {
            int tsk = tid + pass * 128;      // 0..255
            int row  = tsk >> 1;
            int hloc = tsk & 1;
            int h = (ocb - 4) * 2 + hloc;
            int n = n0 + row;
            const float* lb = lbias + h * 64;
            float* sr = sred + row * 132 + hloc * 64;

            float mx = -1e30f;
            #pragma unroll 8
            for (int g = 0; g < 64; g++) mx = fmaxf(mx, sr[g] + lb[g]);
            float ssum = 0.f;
            #pragma unroll 8
            for (int g = 0; g < 64; g++) {
                float e = __expf(sr[g] + lb[g] - mx);
                ssum += e;
                sr[g] = e;
            }
            float inv = 1.0f / ssum;

            size_t base = ((size_t)(b * HEADS + h) * NN + n) * GG;
            #pragma unroll
            for (int c = 0; c < 8; c++) {
                union { __nv_bfloat16 hb[8]; uint4 u; } Uh, Ul;
                #pragma unroll
                for (int e = 0; e < 8; e++) {
                    float v = sr[c * 8 + e] * inv;
                    __nv_bfloat16 hv = __float2bfloat16(v);
                    Uh.hb[e] = hv;
                    Ul.hb[e] = __float2bfloat16(v - __bfloat162float(hv));
                }
                ((uint4*)(swhi + base))[c] = Uh.u;
                ((uint4*)(swlo + base))[c] = Ul.u;
            }
        }
    }
}

// ---------------- K3: token reduction on tensor cores (fx single bf16) ----------------
__global__ __launch_bounds__(128)
void token_mma_kernel(const __nv_bfloat16* __restrict__ whi,
                      const __nv_bfloat16* __restrict__ wlo,
                      const __nv_bfloat16* __restrict__ fx,
                      float* __restrict__ tokp,
                      float* __restrict__ normp)
{
    __shared__ __align__(16) char smem[2 * 6144];

    const int bh = blockIdx.y;
    const int b = bh >> 3, h = bh & 7;
    const int split = blockIdx.x;
    const int nbase = split * CHUNK;

    const int tid  = threadIdx.x;
    const int wid  = tid >> 5;          // 0..3: g-strip wid*16
    const int lane = tid & 31;
    const int grp  = lane >> 2;
    const int tid4 = lane & 3;
    const int t8   = lane >> 3;
    const int r8   = lane & 7;
    const int lrow = r8 + ((t8 >> 1) << 3);   // 0..15
    const int lgr  = t8 & 1;

    const uint32_t ONES = 0x3F803F80u;  // bf16(1.0) x2

    float acc[8][4];
    #pragma unroll
    for (int j = 0; j < 8; j++)
        #pragma unroll
        for (int r = 0; r < 4; r++) acc[j][r] = 0.f;
    float accn[4] = {};

    uint32_t sbase = (uint32_t)__cvta_generic_to_shared(smem);

    auto load = [&](uint32_t st, int t0) {
        #pragma unroll
        for (int j = 0; j < 3; j++) {
            int id  = tid + j * 128;
            int arr = id >> 7;          // 0:whi 1:wlo 2:fx
            int l   = id & 127;
            int row = l >> 3;
            int gr  = l & 7;
            uint32_t saddr = st + arr * 2048 + row * 128 + ((gr ^ (row & 7)) << 4);
            int n = nbase + t0 + row;
            const __nv_bfloat16* g;
            if (arr < 2) {
                g = (arr == 0 ? whi : wlo) + ((size_t)bh * NN + n) * GG + gr * 8;
            } else {
                g = fx + ((size_t)b * NN + n) * INNER + h * DH + gr * 8;
            }
            cp16(saddr, g, true);
        }
    };

    load(sbase, 0);
    asm volatile("cp.async.commit_group;\n" ::: "memory");

    for (int it = 0; it < 64; ++it) {
        const int cur = it & 1;
        if (it + 1 < 64) {
            load(sbase + (uint32_t)(1 - cur) * 6144, (it + 1) * 16);
            asm volatile("cp.async.commit_group;\n" ::: "memory");
            asm volatile("cp.async.wait_group 1;\n" ::: "memory");
        } else {
            asm volatile("cp.async.wait_group 0;\n" ::: "memory");
        }
        __syncthreads();

        const uint32_t st = sbase + (uint32_t)cur * 6144;

        uint32_t awh[4], awl[4];
        {
            int gr = wid * 2 + lgr;
            uint32_t addr = st + lrow * 128 + ((gr ^ (lrow & 7)) << 4);
            ldsm4t(awh, addr);
            ldsm4t(awl, addr + 2048);
        }
        mma_bf16(accn, awh[0], awh[1], awh[2], awh[3], ONES, ONES);
        mma_bf16(accn, awl[0], awl[1], awl[2], awl[3], ONES, ONES);

        #pragma unroll
        for (int j = 0; j < 4; j++) {
            int gr = j * 2 + lgr;
            uint32_t addr = st + 4096 + lrow * 128 + ((gr ^ (lrow & 7)) << 4);
            uint32_t bf[4];
            ldsm4t(bf, addr);
            mma_bf16(acc[2 * j],     awh[0], awh[1], awh[2], awh[3], bf[0], bf[2]);
            mma_bf16(acc[2 * j + 1], awh[0], awh[1], awh[2], awh[3], bf[1], bf[3]);
            mma_bf16(acc[2 * j],     awl[0], awl[1], awl[2], awl[3], bf[0], bf[2]);
            mma_bf16(acc[2 * j + 1], awl[0], awl[1], awl[2], awl[3], bf[1], bf[3]);
        }
        __syncthreads();
    }

    const size_t base = ((size_t)split * (BB * HEADS) + bh) * (GG * DH);
    const int g0 = wid * 16 + grp;
    #pragma unroll
    for (int nf = 0; nf < 8; nf++) {
        int d = (nf >> 1) * 16 + (nf & 1) * 8 + tid4 * 2;
        tokp[base + (size_t)g0 * DH + d]           = acc[nf][0];
        tokp[base + (size_t)g0 * DH + d + 1]       = acc[nf][1];
        tokp[base + (size_t)(g0 + 8) * DH + d]     = acc[nf][2];
        tokp[base + (size_t)(g0 + 8) * DH + d + 1] = acc[nf][3];
    }
    if (tid4 == 0) {
        size_t nb = ((size_t)split * (BB * HEADS) + bh) * GG;
        normp[nb + g0]     = accn[0];
        normp[nb + g0 + 8] = accn[2];
    }
}

// ---------------- K3b: deterministic split reduction ----------------
__global__ void split_reduce_kernel(const float* __restrict__ tokp,
                                    const float* __restrict__ normp,
                                    float* __restrict__ tok,
                                    float* __restrict__ norm) {
    const int blk = blockIdx.x;
    const int tid = threadIdx.x;
    if (blk < 256) {
        int idx = blk * 256 + tid;
        float s = 0.f;
        #pragma unroll 8
        for (int sp = 0; sp < SPLITS; sp++)
            s += tokp[(size_t)sp * 65536 + idx];
        tok[idx] = s;
    } else {
        int idx = (blk - 256) * 256 + tid;
        float s = 0.f;
        #pragma unroll 8
        for (int sp = 0; sp < SPLITS; sp++)
            s += normp[(size_t)sp * 1024 + idx];
        norm[idx] = s;
    }
}

// ---------------- K4: tiny attention per (b,h), emits Mt bf16 hi/lo ----------------
__global__ void attn_kernel(const float* __restrict__ tok,
                            const float* __restrict__ norm,
                            const float* __restrict__ Wq,
                            const float* __restrict__ Wk,
                            const float* __restrict__ Wv,
                            const float* __restrict__ Wout,
                            __nv_bfloat16* __restrict__ Mthi,
                            __nv_bfloat16* __restrict__ Mtlo) {
    const int bh = blockIdx.x;
    const int b = bh >> 3, h = bh & 7;
    const int tx = threadIdx.x, ty = threadIdx.y;
    const int tid = ty * 16 + tx;

    __shared__ float A[64][65];
    __shared__ float Bm[64][65];
    __shared__ float Cm[64][65];

    #pragma unroll
    for (int e = 0; e < 16; e++) {
        int idx = tid + e * 256;
        int g = idx >> 6, d = idx & 63;
        A[g][d] = tok[(size_t)bh * 4096 + idx] / (norm[bh * 64 + g] + 1e-5f);
    }
    __syncthreads();

    {
        float aq[4][4] = {}, ak[4][4] = {};
        #pragma unroll
        for (int kk = 0; kk < 64; kk++) {
            float a[4];
            #pragma unroll
            for (int i = 0; i < 4; i++) a[i] = A[ty + 16 * i][kk];
            #pragma unroll
            for (int j = 0; j < 4; j++) {
                float wq = __ldg(&Wq[(tx + 16 * j) * 64 + kk]);
                float wk = __ldg(&Wk[(tx + 16 * j) * 64 + kk]);
                #pragma unroll
                for (int i = 0; i < 4; i++) {
                    aq[i][j] += a[i] * wq;
                    ak[i][j] += a[i] * wk;
                }
            }
        }
        #pragma unroll
        for (int i = 0; i < 4; i++)
            #pragma unroll
            for (int j = 0; j < 4; j++) {
                Bm[ty + 16 * i][tx + 16 * j] = aq[i][j];
                Cm[ty + 16 * i][tx + 16 * j] = ak[i][j];
            }
    }
    __syncthreads();

    {
        float L[4][4] = {};
        #pragma unroll
        for (int kk = 0; kk < 64; kk++) {
            float a[4], bv[4];
            #pragma unroll
            for (int i = 0; i < 4; i++) a[i] = Bm[ty + 16 * i][kk];
            #pragma unroll
            for (int j = 0; j < 4; j++) bv[j] = Cm[tx + 16 * j][kk];
            #pragma unroll
            for (int i = 0; i < 4; i++)
                #pragma unroll
                for (int j = 0; j < 4; j++)
                    L[i][j] += a[i] * bv[j];
        }
        #pragma unroll
        for (int i = 0; i < 4; i++) {
            #pragma unroll
            for (int j = 0; j < 4; j++) L[i][j] *= 0.125f;
            float mx = L[i][0];
            #pragma unroll
            for (int j = 1; j < 4; j++) mx = fmaxf(mx, L[i][j]);
            #pragma unroll
            for (int o = 1; o < 16; o <<= 1)
                mx = fmaxf(mx, __shfl_xor_sync(0xffffffffu, mx, o, 16));
            float s = 0.f;
            #pragma unroll
            for (int j = 0; j < 4; j++) { L[i][j] = __expf(L[i][j] - mx); s += L[i][j]; }
            #pragma unroll
            for (int o = 1; o < 16; o <<= 1)
                s += __shfl_xor_sync(0xffffffffu, s, o, 16);
            float inv = 1.0f / s;
            #pragma unroll
            for (int j = 0; j < 4; j++)
                A[ty + 16 * i][tx + 16 * j] = L[i][j] * inv;
        }
    }
    __syncthreads();

    #pragma unroll
    for (int e = 0; e < 16; e++) {
        int idx = tid + e * 256;
        int g = idx >> 6;
        Bm[g][idx & 63] = tok[(size_t)bh * 4096 + idx] / (norm[bh * 64 + g] + 1e-5f);
    }
    __syncthreads();

    {
        float av[4][4] = {};
        #pragma unroll
        for (int kk = 0; kk < 64; kk++) {
            float a[4];
            #pragma unroll
            for (int i = 0; i < 4; i++) a[i] = Bm[ty + 16 * i][kk];
            #pragma unroll
            for (int j = 0; j < 4; j++) {
                float wv = __ldg(&Wv[(tx + 16 * j) * 64 + kk]);
                #pragma unroll
                for (int i = 0; i < 4; i++) av[i][j] += a[i] * wv;
            }
        }
        __syncthreads();
        #pragma unroll
        for (int i = 0; i < 4; i++)
            #pragma unroll
            for (int j = 0; j < 4; j++)
                Cm[ty + 16 * i][tx + 16 * j] = av[i][j];
    }
    __syncthreads();

    {
        float ao[4][4] = {};
        #pragma unroll
        for (int kk = 0; kk < 64; kk++) {
            float a[4], bv[4];
            #pragma unroll
            for (int i = 0; i < 4; i++) a[i] = A[ty + 16 * i][kk];
            #pragma unroll
            for (int j = 0; j < 4; j++) bv[j] = Cm[kk][tx + 16 * j];
            #pragma unroll
            for (int i = 0; i < 4; i++)
                #pragma unroll
                for (int j = 0; j < 4; j++)
                    ao[i][j] += a[i] * bv[j];
        }
        __syncthreads();
        #pragma unroll
        for (int i = 0; i < 4; i++)
            #pragma unroll
            for (int j = 0; j < 4; j++)
                Bm[ty + 16 * i][tx + 16 * j] = ao[i][j];
    }
    __syncthreads();

    {
        float am[4][8] = {};
        #pragma unroll
        for (int kk = 0; kk < 64; kk++) {
            float a[4];
            #pragma unroll
            for (int i = 0; i < 4; i++) a[i] = Bm[ty + 16 * i][kk];
            #pragma unroll
            for (int j = 0; j < 8; j++) {
                float wv = __ldg(&Wout[(size_t)(tx + 16 * j) * INNER + h * DH + kk]);
                #pragma unroll
                for (int i = 0; i < 4; i++) am[i][j] += a[i] * wv;
            }
        }
        #pragma unroll
        for (int i = 0; i < 4; i++) {
            int g = ty + 16 * i;
            #pragma unroll
            for (int j = 0; j < 8; j++) {
                int o = tx + 16 * j;
                float v = am[i][j];
                __nv_bfloat16 hv = __float2bfloat16(v);
                float r = v - __bfloat162float(hv);
                size_t idx = ((size_t)b * CC + o) * INNER + h * DH + g;
                Mthi[idx] = hv;
                Mtlo[idx] = __float2bfloat16(r);
            }
        }
    }
}

// ---------------- K5: fused scatter + projection, kc=32, 4 warps, 2 CTAs/SM ----------------
// Chunk it in [0,16): h = it>>1, g0 = (it&1)*32.
// Stage (32KB): whi 8K | wlo 8K | Mthi 8K | Mtlo 8K. 3 stages = 96KB.
#define FSTAGE 32768
#define FNCHUNK 16

__device__ __forceinline__ void fin_load(
    uint32_t st,
    const __nv_bfloat16* __restrict__ Whi, const __nv_bfloat16* __restrict__ Wlo,
    const __nv_bfloat16* __restrict__ Mthi, const __nv_bfloat16* __restrict__ Mtlo,
    int it, int b, int n0, int tid)
{
    const int h  = it >> 1;
    const int g0 = (it & 1) * 32;

    // A: sw 2 arrays x 128 rows(n) x 4 granules = 1024 lines (8 per thread)
    #pragma unroll
    for (int j = 0; j < 8; j++) {
        int id  = tid + j * 128;
        int arr = id >> 9;              // 0:whi 1:wlo
        int l   = id & 511;
        int row = l >> 2;
        int gr  = l & 3;
        uint32_t saddr = st + arr * 8192 + sw32(row, gr);
        const __nv_bfloat16* g = (arr == 0 ? Whi : Wlo) +
            (((size_t)(b * HEADS + h) * NN) + n0 + row) * GG + g0 + gr * 8;
        cp16(saddr, g, true);
    }
    // B: Mt 2 arrays x 128 rows(o) x 4 granules = 1024 lines (8 per thread)
    #pragma unroll
    for (int j = 0; j < 8; j++) {
        int id  = tid + j * 128;
        int arr = id >> 9;              // 0:Mthi 1:Mtlo
        int l   = id & 511;
        int row = l >> 2;
        int gr  = l & 3;
        uint32_t saddr = st + 16384 + arr * 8192 + sw32(row, gr);
        const __nv_bfloat16* g = (arr == 0 ? Mthi : Mtlo) +
            ((size_t)b * CC + row) * INNER + h * DH + g0 + gr * 8;
        cp16(saddr, g, true);
    }
}

__global__ __launch_bounds__(128, 2)
void final_mma_kernel(const __nv_bfloat16* __restrict__ Whi,
                      const __nv_bfloat16* __restrict__ Wlo,
                      const __nv_bfloat16* __restrict__ Mthi,
                      const __nv_bfloat16* __restrict__ Mtlo,
                      const float* __restrict__ bout,
                      float* __restrict__ out)
{
    extern __shared__ char smem[];           // 3 stages x 32KB

    const int pt = blockIdx.x;
    const int b  = pt >> 9;
    const int n0 = (pt & 511) * 128;

    const int tid  = threadIdx.x;            // 0..127
    const int wid  = tid >> 5;
    const int lane = tid & 31;
    const int grp  = lane >> 2;
    const int tid4 = lane & 3;
    const int wm   = wid & 1;                // 2 row-groups of 64
    const int wn   = wid >> 1;               // 2 col-groups of 64

    const int t8   = lane >> 3;
    const int r8   = lane & 7;
    const int a_roff = ((t8 & 1) << 3) + r8;
    const int a_gsel = t8 >> 1;
    const int b_roff = ((t8 >> 1) << 3) + r8;
    const int b_gsel = t8 & 1;

    float acc[4][8][4];
    #pragma unroll
    for (int i = 0; i < 4; i++)
        #pragma unroll
        for (int j = 0; j < 8; j++)
            #pragma unroll
            for (int r = 0; r < 4; r++) acc[i][j][r] = 0.f;

    uint32_t sbase = (uint32_t)__cvta_generic_to_shared(smem);

    fin_load(sbase, Whi, Wlo, Mthi, Mtlo, 0, b, n0, tid);
    asm volatile("cp.async.commit_group;\n" ::: "memory");
    fin_load(sbase + FSTAGE, Whi, Wlo, Mthi, Mtlo, 1, b, n0, tid);
    asm volatile("cp.async.commit_group;\n" ::: "memory");

    for (int it = 0; it < FNCHUNK; ++it) {
        const int cur = it % 3;
        if (it + 2 < FNCHUNK)
            fin_load(sbase + (uint32_t)((it + 2) % 3) * FSTAGE,
                     Whi, Wlo, Mthi, Mtlo, it + 2, b, n0, tid);
        asm volatile("cp.async.commit_group;\n" ::: "memory");
        asm volatile("cp.async.wait_group 2;\n" ::: "memory");
        __syncthreads();

        const uint32_t stA = sbase + (uint32_t)cur * FSTAGE;
        const uint32_t stB = stA + 16384;

        #pragma unroll
        for (int s = 0; s < 2; s++) {
            uint32_t ah[4][4], al[4][4];
            #pragma unroll
            for (int mi = 0; mi < 4; mi++) {
                int row = wm * 64 + mi * 16 + a_roff;
                int g = 2 * s + a_gsel;
                uint32_t addr = stA + sw32(row, g);
                ldsm4(ah[mi], addr);
                ldsm4(al[mi], addr + 8192);
            }
            #pragma unroll
            for (int np = 0; np < 4; np++) {
                int row = wn * 64 + np * 16 + b_roff;
                int g = 2 * s + b_gsel;
                uint32_t addr = stB + sw32(row, g);
                uint32_t bh[4], bl[4];
                ldsm4(bh, addr);
                ldsm4(bl, addr + 8192);
                #pragma unroll
                for (int mi = 0; mi < 4; mi++) {
                    mma_bf16(acc[mi][2 * np],     ah[mi][0], ah[mi][1], ah[mi][2], ah[mi][3], bh[0], bh[1]);
                    mma_bf16(acc[mi][2 * np + 1], ah[mi][0], ah[mi][1], ah[mi][2], ah[mi][3], bh[2], bh[3]);
                }
                #pragma unroll
                for (int mi = 0; mi < 4; mi++) {
                    mma_bf16(acc[mi][2 * np],     ah[mi][0], ah[mi][1], ah[mi][2], ah[mi][3], bl[0], bl[1]);
                    mma_bf16(acc[mi][2 * np + 1], ah[mi][0], ah[mi][1], ah[mi][2], ah[mi][3], bl[2], bl[3]);
                }
                #pragma unroll
                for (int mi = 0; mi < 4; mi++) {
                    mma_bf16(acc[mi][2 * np],     al[mi][0], al[mi][1], al[mi][2], al[mi][3], bh[0], bh[1]);
                    mma_bf16(acc[mi][2 * np + 1], al[mi][0], al[mi][1], al[mi][2], al[mi][3], bh[2], bh[3]);
                }
            }
        }
        __syncthreads();
    }

    #pragma unroll
    for (int mi = 0; mi < 4; mi++) {
        int row = wm * 64 + mi * 16 + grp;
        int n  = n0 + row;
        #pragma unroll
        for (int ni = 0; ni < 8; ni++) {
            int oc = wn * 64 + ni * 8 + tid4 * 2;
            float b0v = bout[oc], b1v = bout[oc + 1];
            size_t base0 = ((size_t)b * NN + n) * CC + oc;
            out[base0]     = acc[mi][ni][0] + b0v;
            out[base0 + 1] = acc[mi][ni][1] + b1v;
            size_t base1 = ((size_t)b * NN + n + 8) * CC + oc;
            out[base1]     = acc[mi][ni][2] + b0v;
            out[base1 + 1] = acc[mi][ni][3] + b1v;
        }
    }
}

// ---------------- launch ----------------
extern "C" void kernel_launch(void* const* d_in, const int* in_sizes, int n_in,
                              void* d_out, int out_size) {
    const float* x     = (const float*)d_in[0];
    const float* Wfx   = (const float*)d_in[1];
    const float* bfx   = (const float*)d_in[2];
    const float* Wx    = (const float*)d_in[3];
    const float* bx    = (const float*)d_in[4];
    const float* Wsl   = (const float*)d_in[5];
    const float* bsl   = (const float*)d_in[6];
    const float* temp  = (const float*)d_in[7];
    const float* Wq    = (const float*)d_in[8];
    const float* Wk    = (const float*)d_in[9];
    const float* Wv    = (const float*)d_in[10];
    const float* Wout  = (const float*)d_in[11];
    const float* bout  = (const float*)d_in[12];
    float* out = (float*)d_out;

    float *p_tokp, *p_normp, *p_tok, *p_norm, *p_lb;
    __nv_bfloat16 *p_xhi, *p_xlo, *p_whi, *p_wlo;
    __nv_bfloat16 *p_fxhi;
    __nv_bfloat16 *p_swhi, *p_swlo, *p_Mthi, *p_Mtlo;
    cudaGetSymbolAddress((void**)&p_tokp, g_tokp);
    cudaGetSymbolAddress((void**)&p_normp, g_normp);
    cudaGetSymbolAddress((void**)&p_tok, g_tok);
    cudaGetSymbolAddress((void**)&p_norm, g_norm);
    cudaGetSymbolAddress((void**)&p_lb, g_lbias);
    cudaGetSymbolAddress((void**)&p_xhi, g_xhi);
    cudaGetSymbolAddress((void**)&p_xlo, g_xlo);
    cudaGetSymbolAddress((void**)&p_whi, g_whi);
    cudaGetSymbolAddress((void**)&p_wlo, g_wlo);
    cudaGetSymbolAddress((void**)&p_fxhi, g_fxhi);
    cudaGetSymbolAddress((void**)&p_swhi, g_swhi);
    cudaGetSymbolAddress((void**)&p_swlo, g_swlo);
    cudaGetSymbolAddress((void**)&p_Mthi, g_Mthi);
    cudaGetSymbolAddress((void**)&p_Mtlo, g_Mtlo);

    static bool attr_set = false;
    if (!attr_set) {
        cudaFuncSetAttribute(conv_mma_kernel,
                             cudaFuncAttributeMaxDynamicSharedMemorySize, 3 * CSTAGE);
        cudaFuncSetAttribute(final_mma_kernel,
                             cudaFuncAttributeMaxDynamicSharedMemorySize, 3 * FSTAGE);
        attr_set = true;
    }

    dim3 blk(16, 16);

    // 0. staging (3 launches; conv is launch #4 for ncu visibility)
    split_x_kernel<<<(BB * NN * CC) / 256, 256>>>(x, p_xhi, p_xlo);
    split_w_kernel<<<(512 * KTOT) / 256, 256>>>(Wfx, p_whi, p_wlo);
    combine_w_kernel<<<dim3(512, 10), 128>>>(Wx, Wsl, bx, bsl, temp, p_whi, p_wlo, p_lb);

    // 1. fused conv (launch #4): 128x128 tiles, 4 warps, 2 CTAs/SM, 3-stage
    conv_mma_kernel<<<dim3(8, 512, BB), 128, 3 * CSTAGE>>>(
        p_xhi, p_xlo, p_whi, p_wlo, bfx, p_lb, p_fxhi, p_swhi, p_swlo);

    // 2. slice token reduction on tensor cores + split reduce
    token_mma_kernel<<<dim3(SPLITS, BB * HEADS), 128>>>(
        p_swhi, p_swlo, p_fxhi, p_tokp, p_normp);
    split_reduce_kernel<<<260, 256>>>(p_tokp, p_normp, p_tok, p_norm);

    // 3. tiny attention + fused Wout fold -> Mt (bf16 hi/lo)
    attn_kernel<<<BB * HEADS, blk>>>(p_tok, p_norm, Wq, Wk, Wv, Wout, p_Mthi, p_Mtlo);

    // 4. fused scatter + projection: kc=32, 4 warps, 2 CTAs/SM, 3-stage
    final_mma_kernel<<<1024, 128, 3 * FSTAGE>>>(p_swhi, p_swlo, p_Mthi, p_Mtlo, bout, out);
}